// round 1
// baseline (speedup 1.0000x reference)
#include <cuda_runtime.h>
#include <cuda_bf16.h>
#include <cstdint>

// Problem: CausalSelfAttention. B=4, T=2048, C=1024, H=16, dk=64.
// Inputs (metadata order): x[4,2048,1024] f32, W_qkv[1024,3072] f32,
// b_qkv[3072] f32, W_proj[1024,1024] f32, b_proj[1024] f32.
// Output: [4,2048,1024] f32.

#define B_   4
#define T_   2048
#define C_   1024
#define H_   16
#define DK_  64
#define M_   (B_ * T_)        // 8192
#define N_QKV (3 * C_)        // 3072

// Scratch (static device memory — allocation is forbidden).
__device__ float g_Q[(size_t)B_ * H_ * T_ * DK_];   // 32 MB, [bh][t][d]
__device__ float g_K[(size_t)B_ * H_ * T_ * DK_];
__device__ float g_V[(size_t)B_ * H_ * T_ * DK_];
__device__ float g_att[(size_t)M_ * C_];            // 32 MB, [b*t][c]

// ---------------------------------------------------------------------------
// Tiled SGEMM: BM=64, BN=64, BK=16, 256 threads, 4x4 per thread.
// ---------------------------------------------------------------------------
#define BM 64
#define BN 64
#define BK 16

// QKV GEMM with fused epilogue scattering into head-major Q/K/V.
__global__ void __launch_bounds__(256, 2) gemm_qkv_kernel(
    const float* __restrict__ X,      // [8192,1024]
    const float* __restrict__ W,      // [1024,3072]
    const float* __restrict__ bias)   // [3072]
{
    __shared__ float As[BK][BM + 4];
    __shared__ float Bs[BK][BN];

    const int tid = threadIdx.x;
    const int tx = tid & 15, ty = tid >> 4;
    const int m0 = blockIdx.y * BM;
    const int n0 = blockIdx.x * BN;

    // Load mapping
    const int a_row = tid >> 2;         // 0..63
    const int a_col = (tid & 3) << 2;   // 0,4,8,12
    const int b_row = tid >> 4;         // 0..15
    const int b_col = (tid & 15) << 2;  // 0..60

    const float* Aptr = X + (m0 + a_row) * C_ + a_col;
    const float* Bptr = W + b_row * N_QKV + n0 + b_col;

    float acc[4][4] = {};

    for (int k0 = 0; k0 < C_; k0 += BK) {
        float4 a4 = *(const float4*)(Aptr + k0);
        float4 b4 = *(const float4*)(Bptr + k0 * N_QKV);
        As[a_col + 0][a_row] = a4.x;
        As[a_col + 1][a_row] = a4.y;
        As[a_col + 2][a_row] = a4.z;
        As[a_col + 3][a_row] = a4.w;
        *(float4*)&Bs[b_row][b_col] = b4;
        __syncthreads();
        #pragma unroll
        for (int kk = 0; kk < BK; kk++) {
            float4 av = *(const float4*)&As[kk][ty * 4];
            float4 bv = *(const float4*)&Bs[kk][tx * 4];
            float a[4] = {av.x, av.y, av.z, av.w};
            float b[4] = {bv.x, bv.y, bv.z, bv.w};
            #pragma unroll
            for (int i = 0; i < 4; i++)
                #pragma unroll
                for (int j = 0; j < 4; j++)
                    acc[i][j] += a[i] * b[j];
        }
        __syncthreads();
    }

    // Epilogue: n0 is a multiple of 64, so (which, head) constant per tile.
    const int which = n0 / C_;                 // 0=Q, 1=K, 2=V
    const int h = (n0 % C_) / DK_;
    float* dst = which == 0 ? g_Q : which == 1 ? g_K : g_V;

    #pragma unroll
    for (int i = 0; i < 4; i++) {
        int m = m0 + ty * 4 + i;
        int b = m >> 11;                       // m / 2048
        int t = m & (T_ - 1);
        float* row = dst + (((size_t)(b * H_ + h) * T_ + t) << 6);
        #pragma unroll
        for (int j = 0; j < 4; j++) {
            int d = tx * 4 + j;
            row[d] = acc[i][j] + bias[n0 + tx * 4 + j];
        }
    }
}

// Proj GEMM: g_att[8192,1024] @ W_proj[1024,1024] + b_proj -> d_out.
__global__ void __launch_bounds__(256, 2) gemm_proj_kernel(
    float* __restrict__ out,
    const float* __restrict__ W,      // [1024,1024]
    const float* __restrict__ bias)   // [1024]
{
    __shared__ float As[BK][BM + 4];
    __shared__ float Bs[BK][BN];

    const int tid = threadIdx.x;
    const int tx = tid & 15, ty = tid >> 4;
    const int m0 = blockIdx.y * BM;
    const int n0 = blockIdx.x * BN;

    const int a_row = tid >> 2;
    const int a_col = (tid & 3) << 2;
    const int b_row = tid >> 4;
    const int b_col = (tid & 15) << 2;

    const float* Aptr = g_att + (m0 + a_row) * C_ + a_col;
    const float* Bptr = W + b_row * C_ + n0 + b_col;

    float acc[4][4] = {};

    for (int k0 = 0; k0 < C_; k0 += BK) {
        float4 a4 = *(const float4*)(Aptr + k0);
        float4 b4 = *(const float4*)(Bptr + k0 * C_);
        As[a_col + 0][a_row] = a4.x;
        As[a_col + 1][a_row] = a4.y;
        As[a_col + 2][a_row] = a4.z;
        As[a_col + 3][a_row] = a4.w;
        *(float4*)&Bs[b_row][b_col] = b4;
        __syncthreads();
        #pragma unroll
        for (int kk = 0; kk < BK; kk++) {
            float4 av = *(const float4*)&As[kk][ty * 4];
            float4 bv = *(const float4*)&Bs[kk][tx * 4];
            float a[4] = {av.x, av.y, av.z, av.w};
            float b[4] = {bv.x, bv.y, bv.z, bv.w};
            #pragma unroll
            for (int i = 0; i < 4; i++)
                #pragma unroll
                for (int j = 0; j < 4; j++)
                    acc[i][j] += a[i] * b[j];
        }
        __syncthreads();
    }

    #pragma unroll
    for (int i = 0; i < 4; i++) {
        int m = m0 + ty * 4 + i;
        float* row = out + (size_t)m * C_ + n0;
        #pragma unroll
        for (int j = 0; j < 4; j++)
            row[tx * 4 + j] = acc[i][j] + bias[n0 + tx * 4 + j];
    }
}

// ---------------------------------------------------------------------------
// Flash attention (fp32): 1 thread = 1 query row; q/o register-resident;
// K/V tiles staged in smem, read via broadcast LDS.128.
// Grid: (T/128, B*H), block: 128 threads.
// ---------------------------------------------------------------------------
#define AQ 128
#define AK 64

__global__ void __launch_bounds__(128, 1) attn_kernel()
{
    const int bh = blockIdx.y;             // 0..63
    const int qt = blockIdx.x;             // 0..15
    const int tid = threadIdx.x;
    const int q = qt * AQ + tid;           // global query index within T

    __shared__ float4 Ks[AK][16];          // 16 KB
    __shared__ float4 Vs[AK][16];          // 16 KB

    const float4* Qg = (const float4*)(g_Q + ((size_t)bh * T_ + q) * DK_);
    float4 qv[16], ov[16];
    #pragma unroll
    for (int c = 0; c < 16; c++) {
        qv[c] = Qg[c];
        ov[c] = make_float4(0.f, 0.f, 0.f, 0.f);
    }

    float m = -1e30f, l = 0.f;
    const float scale = 0.125f;            // 1/sqrt(64)

    const int ktiles = (qt * AQ + AQ - 1) / AK + 1;   // tiles needed by block max q

    for (int kt = 0; kt < ktiles; kt++) {
        const int kb = kt * AK;
        const float4* Kg = (const float4*)(g_K + ((size_t)bh * T_ + kb) * DK_);
        const float4* Vg = (const float4*)(g_V + ((size_t)bh * T_ + kb) * DK_);
        #pragma unroll
        for (int i = 0; i < 8; i++) {
            int idx = tid + i * 128;       // 1024 float4 total
            ((float4*)Ks)[idx] = Kg[idx];
            ((float4*)Vs)[idx] = Vg[idx];
        }
        __syncthreads();

        const int jmax = min(AK, q - kb + 1);   // causal bound (may be <=0)
        for (int j = 0; j < jmax; j++) {
            // s = scale * dot(q, K[j]) with 4 independent accumulation chains
            float sx = 0.f, sy = 0.f, sz = 0.f, sw = 0.f;
            #pragma unroll
            for (int c = 0; c < 16; c++) {
                float4 k4 = Ks[j][c];
                sx += qv[c].x * k4.x;
                sy += qv[c].y * k4.y;
                sz += qv[c].z * k4.z;
                sw += qv[c].w * k4.w;
            }
            float s = ((sx + sy) + (sz + sw)) * scale;

            float p;
            if (s <= m) {
                p = __expf(s - m);
            } else {
                // Rare path: new running max -> rescale accumulators.
                float corr = __expf(m - s);
                m = s;
                l *= corr;
                #pragma unroll
                for (int c = 0; c < 16; c++) {
                    ov[c].x *= corr; ov[c].y *= corr;
                    ov[c].z *= corr; ov[c].w *= corr;
                }
                p = 1.f;
            }
            l += p;
            #pragma unroll
            for (int c = 0; c < 16; c++) {
                float4 v4 = Vs[j][c];
                ov[c].x += p * v4.x;
                ov[c].y += p * v4.y;
                ov[c].z += p * v4.z;
                ov[c].w += p * v4.w;
            }
        }
        __syncthreads();
    }

    // Write back to [b, t, h*64 + d] layout for the proj GEMM.
    const int b = bh >> 4, h = bh & 15;
    const float inv = 1.f / l;
    float4* out = (float4*)(g_att + ((size_t)(b * T_ + q)) * C_ + h * DK_);
    #pragma unroll
    for (int c = 0; c < 16; c++)
        out[c] = make_float4(ov[c].x * inv, ov[c].y * inv, ov[c].z * inv, ov[c].w * inv);
}

// ---------------------------------------------------------------------------
extern "C" void kernel_launch(void* const* d_in, const int* in_sizes, int n_in,
                              void* d_out, int out_size)
{
    const float* x      = (const float*)d_in[0];
    const float* W_qkv  = (const float*)d_in[1];
    const float* b_qkv  = (const float*)d_in[2];
    const float* W_proj = (const float*)d_in[3];
    const float* b_proj = (const float*)d_in[4];
    float* out = (float*)d_out;

    dim3 g1(N_QKV / BN, M_ / BM);     // (48, 128)
    gemm_qkv_kernel<<<g1, 256>>>(x, W_qkv, b_qkv);

    dim3 g2(T_ / AQ, B_ * H_);        // (16, 64)
    attn_kernel<<<g2, 128>>>();

    dim3 g3(C_ / BN, M_ / BM);        // (16, 128)
    gemm_proj_kernel<<<g3, 256>>>(out, W_proj, b_proj);
}

// round 3
// speedup vs baseline: 1.5201x; 1.5201x over previous
#include <cuda_runtime.h>
#include <cuda_bf16.h>
#include <cstdint>

// CausalSelfAttention: B=4, T=2048, C=1024, H=16, dk=64.
// R3: GEMMs via mma.sync bf16 (3-term hi/lo split), since sm_103a-only
// tcgen05 PTX is rejected by the harness's compute_103 PTX target.

#define B_   4
#define T_   2048
#define C_   1024
#define H_   16
#define DK_  64
#define M_   (B_ * T_)        // 8192
#define N_QKV (3 * C_)        // 3072

// Static scratch (allocation forbidden).
__device__ float g_Q[(size_t)B_ * H_ * T_ * DK_];
__device__ float g_K[(size_t)B_ * H_ * T_ * DK_];
__device__ float g_V[(size_t)B_ * H_ * T_ * DK_];
__device__ float g_att[(size_t)M_ * C_];
__device__ __nv_bfloat16 g_Ahi[(size_t)M_ * C_];          // activation hi/lo
__device__ __nv_bfloat16 g_Alo[(size_t)M_ * C_];
__device__ __nv_bfloat16 g_Whi[(size_t)(N_QKV + C_) * C_]; // W^T hi/lo, [n][k]
__device__ __nv_bfloat16 g_Wlo[(size_t)(N_QKV + C_) * C_];

// ---------------------------------------------------------------------------
// helpers
// ---------------------------------------------------------------------------
__device__ __forceinline__ uint32_t smem_u32(const void* p) {
    uint32_t a;
    asm("{ .reg .u64 t; cvta.to.shared.u64 t, %1; cvt.u32.u64 %0, t; }"
        : "=r"(a) : "l"(p));
    return a;
}
__device__ __forceinline__ void cp_async16(uint32_t dst, const void* src) {
    asm volatile("cp.async.ca.shared.global [%0], [%1], 16;"
                 :: "r"(dst), "l"(__cvta_generic_to_global(src)) : "memory");
}
__device__ __forceinline__ void ldsm_x4(uint32_t& r0, uint32_t& r1,
                                        uint32_t& r2, uint32_t& r3, uint32_t a) {
    asm volatile("ldmatrix.sync.aligned.m8n8.x4.shared.b16 {%0,%1,%2,%3}, [%4];"
                 : "=r"(r0), "=r"(r1), "=r"(r2), "=r"(r3) : "r"(a));
}
__device__ __forceinline__ void mma_bf16(float* c, const uint32_t* a,
                                         uint32_t b0, uint32_t b1) {
    asm volatile(
        "mma.sync.aligned.m16n8k16.row.col.f32.bf16.bf16.f32 "
        "{%0,%1,%2,%3}, {%4,%5,%6,%7}, {%8,%9}, {%0,%1,%2,%3};"
        : "+f"(c[0]), "+f"(c[1]), "+f"(c[2]), "+f"(c[3])
        : "r"(a[0]), "r"(a[1]), "r"(a[2]), "r"(a[3]), "r"(b0), "r"(b1));
}

// ---------------------------------------------------------------------------
// Split fp32 -> bf16 hi/lo (activations). 4 elems per thread.
// ---------------------------------------------------------------------------
__global__ void __launch_bounds__(256) split_act_kernel(const float* __restrict__ src)
{
    size_t i = ((size_t)blockIdx.x * 256 + threadIdx.x) * 4;
    float4 v = *(const float4*)(src + i);
    __nv_bfloat16 hx = __float2bfloat16_rn(v.x);
    __nv_bfloat16 hy = __float2bfloat16_rn(v.y);
    __nv_bfloat16 hz = __float2bfloat16_rn(v.z);
    __nv_bfloat16 hw = __float2bfloat16_rn(v.w);
    __nv_bfloat16 h2[4] = { hx, hy, hz, hw };
    *(uint2*)(g_Ahi + i) = *(uint2*)h2;
    __nv_bfloat16 l2[4] = {
        __float2bfloat16_rn(v.x - __bfloat162float(hx)),
        __float2bfloat16_rn(v.y - __bfloat162float(hy)),
        __float2bfloat16_rn(v.z - __bfloat162float(hz)),
        __float2bfloat16_rn(v.w - __bfloat162float(hw)) };
    *(uint2*)(g_Alo + i) = *(uint2*)l2;
}

// ---------------------------------------------------------------------------
// Transpose + split weights: W[k][N] -> Whi/Wlo[row_off + n][k]
// ---------------------------------------------------------------------------
__global__ void __launch_bounds__(256) split_w_kernel(
    const float* __restrict__ W, int Ncols, int row_off)
{
    __shared__ float tile[32][33];
    const int tx = threadIdx.x, ty = threadIdx.y;
    const int n0 = blockIdx.x * 32;
    const int k0 = blockIdx.y * 32;
    #pragma unroll
    for (int j = ty; j < 32; j += 8)
        tile[j][tx] = W[(size_t)(k0 + j) * Ncols + n0 + tx];
    __syncthreads();
    #pragma unroll
    for (int j = ty; j < 32; j += 8) {
        float v = tile[tx][j];                     // = W[k0+tx][n0+j]
        __nv_bfloat16 h = __float2bfloat16_rn(v);
        __nv_bfloat16 l = __float2bfloat16_rn(v - __bfloat162float(h));
        size_t o = (size_t)(row_off + n0 + j) * C_ + k0 + tx;
        g_Whi[o] = h;
        g_Wlo[o] = l;
    }
}

// ---------------------------------------------------------------------------
// mma.sync bf16 GEMM (3-term split): C[M,N] = A[M,K] * B^T[N,K] + bias
// Tile 128(M) x 256(N) x 32(K-chunk). 256 threads, 8 warps (2m x 4n),
// warp tile 64x64. cp.async double-buffered staging.
// mode 0: scatter into g_Q/g_K/g_V head-major.  mode 1: C -> out.
// ---------------------------------------------------------------------------
#define GM 128
#define GN 256
#define KC 32
#define NCHUNK (C_ / KC)          // 32
#define A_ST (GM * 80)            // 10240 (rows padded to 80 B)
#define B_ST (GN * 80)            // 20480
#define STAGE (2 * A_ST + 2 * B_ST) // 61440

extern __shared__ char gemm_smem[];

__global__ void __launch_bounds__(256, 1) gemm_bf16_kernel(
    const __nv_bfloat16* __restrict__ gBhi,
    const __nv_bfloat16* __restrict__ gBlo,
    const float* __restrict__ bias,
    float* __restrict__ Cout,
    int mode)
{
    const int tid = threadIdx.x;
    const int lane = tid & 31;
    const int wid = tid >> 5;
    const int wm = wid & 1;            // 0..1 -> 64 rows
    const int wn = wid >> 1;           // 0..3 -> 64 cols
    const int m0 = blockIdx.y * GM;
    const int n0 = blockIdx.x * GN;

    const uint32_t sbase = smem_u32(gemm_smem);

    float c[4][8][4];
    #pragma unroll
    for (int i = 0; i < 4; i++)
        #pragma unroll
        for (int j = 0; j < 8; j++)
            #pragma unroll
            for (int k = 0; k < 4; k++)
                c[i][j][k] = 0.f;

    // ---- staging: 12 cp.async/thread/chunk ----
    auto issue = [&](int ch, int buf) {
        const int k0 = ch * KC;
        const uint32_t sb = sbase + buf * STAGE;
        #pragma unroll
        for (int i = 0; i < 2; i++) {           // A hi/lo: 512 chunks each
            int idx = i * 256 + tid;
            int row = idx >> 2, cc = idx & 3;
            size_t go = ((size_t)(m0 + row) << 10) + k0 + cc * 8;
            uint32_t dof = row * 80 + cc * 16;
            cp_async16(sb + dof, g_Ahi + go);
            cp_async16(sb + A_ST + dof, g_Alo + go);
        }
        #pragma unroll
        for (int i = 0; i < 4; i++) {           // B hi/lo: 1024 chunks each
            int idx = i * 256 + tid;
            int row = idx >> 2, cc = idx & 3;
            size_t go = ((size_t)(n0 + row) << 10) + k0 + cc * 8;
            uint32_t dof = row * 80 + cc * 16;
            cp_async16(sb + 2 * A_ST + dof, gBhi + go);
            cp_async16(sb + 2 * A_ST + B_ST + dof, gBlo + go);
        }
    };

    issue(0, 0);
    asm volatile("cp.async.commit_group;" ::: "memory");

    const uint32_t a_lrow = (lane & 15);
    const uint32_t a_lk   = (lane >> 4) * 16;
    const uint32_t b_lrow = (lane & 7) | ((lane >> 1) & 8);
    const uint32_t b_lk   = ((lane >> 3) & 1) * 16;

    for (int ch = 0; ch < NCHUNK; ch++) {
        const int buf = ch & 1;
        if (ch + 1 < NCHUNK) {
            issue(ch + 1, buf ^ 1);
            asm volatile("cp.async.commit_group;" ::: "memory");
            asm volatile("cp.async.wait_group 1;" ::: "memory");
        } else {
            asm volatile("cp.async.wait_group 0;" ::: "memory");
        }
        __syncthreads();

        const uint32_t sA = sbase + buf * STAGE;
        const uint32_t sB = sA + 2 * A_ST;

        #pragma unroll
        for (int ks = 0; ks < 2; ks++) {
            const uint32_t kb = ks * 32;
            uint32_t ahi[4][4], bhi[4][4];
            #pragma unroll
            for (int mf = 0; mf < 4; mf++) {
                uint32_t ad = sA + (wm * 64 + mf * 16 + a_lrow) * 80 + kb + a_lk;
                ldsm_x4(ahi[mf][0], ahi[mf][1], ahi[mf][2], ahi[mf][3], ad);
            }
            #pragma unroll
            for (int np = 0; np < 4; np++) {
                uint32_t bd = sB + (wn * 64 + np * 16 + b_lrow) * 80 + kb + b_lk;
                ldsm_x4(bhi[np][0], bhi[np][1], bhi[np][2], bhi[np][3], bd);
            }
            #pragma unroll
            for (int mf = 0; mf < 4; mf++)
                #pragma unroll
                for (int np = 0; np < 4; np++) {
                    mma_bf16(c[mf][2 * np],     ahi[mf], bhi[np][0], bhi[np][1]);
                    mma_bf16(c[mf][2 * np + 1], ahi[mf], bhi[np][2], bhi[np][3]);
                }
            // lo(A) * hi(B)
            #pragma unroll
            for (int mf = 0; mf < 4; mf++) {
                uint32_t alo[4];
                uint32_t ad = sA + A_ST + (wm * 64 + mf * 16 + a_lrow) * 80 + kb + a_lk;
                ldsm_x4(alo[0], alo[1], alo[2], alo[3], ad);
                #pragma unroll
                for (int np = 0; np < 4; np++) {
                    mma_bf16(c[mf][2 * np],     alo, bhi[np][0], bhi[np][1]);
                    mma_bf16(c[mf][2 * np + 1], alo, bhi[np][2], bhi[np][3]);
                }
            }
            // hi(A) * lo(B)
            #pragma unroll
            for (int np = 0; np < 4; np++) {
                uint32_t blo[4];
                uint32_t bd = sB + B_ST + (wn * 64 + np * 16 + b_lrow) * 80 + kb + b_lk;
                ldsm_x4(blo[0], blo[1], blo[2], blo[3], bd);
                #pragma unroll
                for (int mf = 0; mf < 4; mf++) {
                    mma_bf16(c[mf][2 * np],     ahi[mf], blo[0], blo[1]);
                    mma_bf16(c[mf][2 * np + 1], ahi[mf], blo[2], blo[3]);
                }
            }
        }
        __syncthreads();
    }

    // ---- epilogue ----
    const int which = n0 >> 10;
    const int h = ((n0 + wn * 64) & (C_ - 1)) >> 6;
    float* qkv_dst = which == 0 ? g_Q : which == 1 ? g_K : g_V;

    #pragma unroll
    for (int mf = 0; mf < 4; mf++) {
        const int mrow = m0 + wm * 64 + mf * 16 + (lane >> 2);
        #pragma unroll
        for (int nf = 0; nf < 8; nf++) {
            const int n = n0 + wn * 64 + nf * 8 + (lane & 3) * 2;
            const float bx = bias[n], by = bias[n + 1];
            if (mode == 0) {
                const int b = mrow >> 11, t = mrow & (T_ - 1);
                float* p = qkv_dst
                    + (((size_t)(b * H_ + h) * T_ + t) << 6) + (n & 63);
                p[0] = c[mf][nf][0] + bx;
                p[1] = c[mf][nf][1] + by;
                p += (size_t)8 << 6;            // t+8, same b within tile
                p[0] = c[mf][nf][2] + bx;
                p[1] = c[mf][nf][3] + by;
            } else {
                float* p = Cout + (size_t)mrow * C_ + n;
                p[0] = c[mf][nf][0] + bx;
                p[1] = c[mf][nf][1] + by;
                p += (size_t)8 * C_;
                p[0] = c[mf][nf][2] + bx;
                p[1] = c[mf][nf][3] + by;
            }
        }
    }
}

// ---------------------------------------------------------------------------
// Flash attention (fp32), unchanged from R1.
// ---------------------------------------------------------------------------
#define AQ 128
#define AK 64

__global__ void __launch_bounds__(128, 1) attn_kernel()
{
    const int bh = blockIdx.y;
    const int qt = blockIdx.x;
    const int tid = threadIdx.x;
    const int q = qt * AQ + tid;

    __shared__ float4 Ks[AK][16];
    __shared__ float4 Vs[AK][16];

    const float4* Qg = (const float4*)(g_Q + ((size_t)bh * T_ + q) * DK_);
    float4 qv[16], ov[16];
    #pragma unroll
    for (int c = 0; c < 16; c++) {
        qv[c] = Qg[c];
        ov[c] = make_float4(0.f, 0.f, 0.f, 0.f);
    }

    float m = -1e30f, l = 0.f;
    const float scale = 0.125f;
    const int ktiles = (qt * AQ + AQ - 1) / AK + 1;

    for (int kt = 0; kt < ktiles; kt++) {
        const int kb = kt * AK;
        const float4* Kg = (const float4*)(g_K + ((size_t)bh * T_ + kb) * DK_);
        const float4* Vg = (const float4*)(g_V + ((size_t)bh * T_ + kb) * DK_);
        #pragma unroll
        for (int i = 0; i < 8; i++) {
            int idx = tid + i * 128;
            ((float4*)Ks)[idx] = Kg[idx];
            ((float4*)Vs)[idx] = Vg[idx];
        }
        __syncthreads();

        const int jmax = min(AK, q - kb + 1);
        for (int j = 0; j < jmax; j++) {
            float sx = 0.f, sy = 0.f, sz = 0.f, sw = 0.f;
            #pragma unroll
            for (int c = 0; c < 16; c++) {
                float4 k4 = Ks[j][c];
                sx += qv[c].x * k4.x;
                sy += qv[c].y * k4.y;
                sz += qv[c].z * k4.z;
                sw += qv[c].w * k4.w;
            }
            float s = ((sx + sy) + (sz + sw)) * scale;

            float p;
            if (s <= m) {
                p = __expf(s - m);
            } else {
                float corr = __expf(m - s);
                m = s;
                l *= corr;
                #pragma unroll
                for (int c = 0; c < 16; c++) {
                    ov[c].x *= corr; ov[c].y *= corr;
                    ov[c].z *= corr; ov[c].w *= corr;
                }
                p = 1.f;
            }
            l += p;
            #pragma unroll
            for (int c = 0; c < 16; c++) {
                float4 v4 = Vs[j][c];
                ov[c].x += p * v4.x;
                ov[c].y += p * v4.y;
                ov[c].z += p * v4.z;
                ov[c].w += p * v4.w;
            }
        }
        __syncthreads();
    }

    const int b = bh >> 4, h = bh & 15;
    const float inv = 1.f / l;
    float4* out = (float4*)(g_att + ((size_t)(b * T_ + q)) * C_ + h * DK_);
    #pragma unroll
    for (int c = 0; c < 16; c++)
        out[c] = make_float4(ov[c].x * inv, ov[c].y * inv, ov[c].z * inv, ov[c].w * inv);
}

// ---------------------------------------------------------------------------
extern "C" void kernel_launch(void* const* d_in, const int* in_sizes, int n_in,
                              void* d_out, int out_size)
{
    const float* x      = (const float*)d_in[0];
    const float* W_qkv  = (const float*)d_in[1];
    const float* b_qkv  = (const float*)d_in[2];
    const float* W_proj = (const float*)d_in[3];
    const float* b_proj = (const float*)d_in[4];
    float* out = (float*)d_out;

    static int smem_set = 0;
    if (!smem_set) {
        cudaFuncSetAttribute(gemm_bf16_kernel,
                             cudaFuncAttributeMaxDynamicSharedMemorySize,
                             2 * STAGE);
        smem_set = 1;
    }

    __nv_bfloat16 *Whi_d, *Wlo_d;
    cudaGetSymbolAddress((void**)&Whi_d, g_Whi);
    cudaGetSymbolAddress((void**)&Wlo_d, g_Wlo);

    dim3 tb(32, 8);
    split_w_kernel<<<dim3(N_QKV / 32, C_ / 32), tb>>>(W_qkv, N_QKV, 0);
    split_w_kernel<<<dim3(C_ / 32, C_ / 32), tb>>>(W_proj, C_, N_QKV);
    split_act_kernel<<<(M_ * C_) / (256 * 4), 256>>>(x);

    gemm_bf16_kernel<<<dim3(N_QKV / GN, M_ / GM), 256, 2 * STAGE>>>(
        Whi_d, Wlo_d, b_qkv, nullptr, 0);

    attn_kernel<<<dim3(T_ / AQ, B_ * H_), 128>>>();

    float* att_d;
    cudaGetSymbolAddress((void**)&att_d, g_att);
    split_act_kernel<<<(M_ * C_) / (256 * 4), 256>>>(att_d);

    gemm_bf16_kernel<<<dim3(C_ / GN, M_ / GM), 256, 2 * STAGE>>>(
        Whi_d + (size_t)N_QKV * C_, Wlo_d + (size_t)N_QKV * C_,
        b_proj, out, 1);
}

// round 4
// speedup vs baseline: 3.3460x; 2.2011x over previous
#include <cuda_runtime.h>
#include <cuda_bf16.h>
#include <cstdint>

// CausalSelfAttention: B=4, T=2048, C=1024, H=16, dk=64.
// R4: GEMMs via mma.sync bf16 3-term split (R3, validated) + flash attention
// also on mma.sync with bf16 hi/lo splits for Q,K,P,V. Q/K/V and the attention
// output are produced directly in bf16 hi/lo form (no fp32 round-trips).

#define B_   4
#define T_   2048
#define C_   1024
#define H_   16
#define DK_  64
#define M_   (B_ * T_)        // 8192
#define N_QKV (3 * C_)        // 3072

// Static scratch (allocation forbidden).
#define QKV_ELEMS ((size_t)B_ * H_ * T_ * DK_)
__device__ __align__(16) __nv_bfloat16 g_Qhi[QKV_ELEMS];   // scaled by 0.125
__device__ __align__(16) __nv_bfloat16 g_Qlo[QKV_ELEMS];
__device__ __align__(16) __nv_bfloat16 g_Khi[QKV_ELEMS];
__device__ __align__(16) __nv_bfloat16 g_Klo[QKV_ELEMS];
__device__ __align__(16) __nv_bfloat16 g_Vhi[QKV_ELEMS];
__device__ __align__(16) __nv_bfloat16 g_Vlo[QKV_ELEMS];
__device__ __align__(16) __nv_bfloat16 g_Ahi[(size_t)M_ * C_];   // GEMM A input
__device__ __align__(16) __nv_bfloat16 g_Alo[(size_t)M_ * C_];
__device__ __align__(16) __nv_bfloat16 g_Whi[(size_t)(N_QKV + C_) * C_];
__device__ __align__(16) __nv_bfloat16 g_Wlo[(size_t)(N_QKV + C_) * C_];

// ---------------------------------------------------------------------------
// helpers
// ---------------------------------------------------------------------------
__device__ __forceinline__ uint32_t smem_u32(const void* p) {
    uint32_t a;
    asm("{ .reg .u64 t; cvta.to.shared.u64 t, %1; cvt.u32.u64 %0, t; }"
        : "=r"(a) : "l"(p));
    return a;
}
__device__ __forceinline__ void cp_async16(uint32_t dst, const void* src) {
    asm volatile("cp.async.ca.shared.global [%0], [%1], 16;"
                 :: "r"(dst), "l"(__cvta_generic_to_global(src)) : "memory");
}
__device__ __forceinline__ void ldsm_x4(uint32_t& r0, uint32_t& r1,
                                        uint32_t& r2, uint32_t& r3, uint32_t a) {
    asm volatile("ldmatrix.sync.aligned.m8n8.x4.shared.b16 {%0,%1,%2,%3}, [%4];"
                 : "=r"(r0), "=r"(r1), "=r"(r2), "=r"(r3) : "r"(a));
}
__device__ __forceinline__ void ldsm_x4t(uint32_t& r0, uint32_t& r1,
                                         uint32_t& r2, uint32_t& r3, uint32_t a) {
    asm volatile("ldmatrix.sync.aligned.m8n8.x4.trans.shared.b16 {%0,%1,%2,%3}, [%4];"
                 : "=r"(r0), "=r"(r1), "=r"(r2), "=r"(r3) : "r"(a));
}
__device__ __forceinline__ void mma_bf16(float* c, const uint32_t* a,
                                         uint32_t b0, uint32_t b1) {
    asm volatile(
        "mma.sync.aligned.m16n8k16.row.col.f32.bf16.bf16.f32 "
        "{%0,%1,%2,%3}, {%4,%5,%6,%7}, {%8,%9}, {%0,%1,%2,%3};"
        : "+f"(c[0]), "+f"(c[1]), "+f"(c[2]), "+f"(c[3])
        : "r"(a[0]), "r"(a[1]), "r"(a[2]), "r"(a[3]), "r"(b0), "r"(b1));
}
// split-pack two fp32 into bf16x2 hi and bf16x2 lo registers
__device__ __forceinline__ void split_pack(float x, float y,
                                           uint32_t& hi, uint32_t& lo) {
    __nv_bfloat16 hx = __float2bfloat16_rn(x);
    __nv_bfloat16 hy = __float2bfloat16_rn(y);
    __nv_bfloat162 h; h.x = hx; h.y = hy;
    hi = *(uint32_t*)&h;
    __nv_bfloat162 l;
    l.x = __float2bfloat16_rn(x - __bfloat162float(hx));
    l.y = __float2bfloat16_rn(y - __bfloat162float(hy));
    lo = *(uint32_t*)&l;
}

// ---------------------------------------------------------------------------
// Split fp32 -> bf16 hi/lo (activations, x input only).
// ---------------------------------------------------------------------------
__global__ void __launch_bounds__(256) split_act_kernel(const float* __restrict__ src)
{
    size_t i = ((size_t)blockIdx.x * 256 + threadIdx.x) * 4;
    float4 v = *(const float4*)(src + i);
    __nv_bfloat16 hx = __float2bfloat16_rn(v.x);
    __nv_bfloat16 hy = __float2bfloat16_rn(v.y);
    __nv_bfloat16 hz = __float2bfloat16_rn(v.z);
    __nv_bfloat16 hw = __float2bfloat16_rn(v.w);
    __nv_bfloat16 h2[4] = { hx, hy, hz, hw };
    *(uint2*)(g_Ahi + i) = *(uint2*)h2;
    __nv_bfloat16 l2[4] = {
        __float2bfloat16_rn(v.x - __bfloat162float(hx)),
        __float2bfloat16_rn(v.y - __bfloat162float(hy)),
        __float2bfloat16_rn(v.z - __bfloat162float(hz)),
        __float2bfloat16_rn(v.w - __bfloat162float(hw)) };
    *(uint2*)(g_Alo + i) = *(uint2*)l2;
}

// ---------------------------------------------------------------------------
// Transpose + split weights: W[k][N] -> Whi/Wlo[row_off + n][k]
// ---------------------------------------------------------------------------
__global__ void __launch_bounds__(256) split_w_kernel(
    const float* __restrict__ W, int Ncols, int row_off)
{
    __shared__ float tile[32][33];
    const int tx = threadIdx.x, ty = threadIdx.y;
    const int n0 = blockIdx.x * 32;
    const int k0 = blockIdx.y * 32;
    #pragma unroll
    for (int j = ty; j < 32; j += 8)
        tile[j][tx] = W[(size_t)(k0 + j) * Ncols + n0 + tx];
    __syncthreads();
    #pragma unroll
    for (int j = ty; j < 32; j += 8) {
        float v = tile[tx][j];
        __nv_bfloat16 h = __float2bfloat16_rn(v);
        __nv_bfloat16 l = __float2bfloat16_rn(v - __bfloat162float(h));
        size_t o = (size_t)(row_off + n0 + j) * C_ + k0 + tx;
        g_Whi[o] = h;
        g_Wlo[o] = l;
    }
}

// ---------------------------------------------------------------------------
// mma.sync bf16 GEMM (3-term split). Tile 128x256x32, 8 warps (2m x 4n).
// mode 0: epilogue -> bf16 hi/lo Q/K/V head-major (Q scaled by 0.125)
// mode 1: epilogue -> fp32 out + bias
// ---------------------------------------------------------------------------
#define GM 128
#define GN 256
#define KC 32
#define NCHUNK (C_ / KC)
#define A_ST (GM * 80)
#define B_ST (GN * 80)
#define STAGE (2 * A_ST + 2 * B_ST)

extern __shared__ char gemm_smem[];

__global__ void __launch_bounds__(256, 1) gemm_bf16_kernel(
    const __nv_bfloat16* __restrict__ gBhi,
    const __nv_bfloat16* __restrict__ gBlo,
    const float* __restrict__ bias,
    float* __restrict__ Cout,
    int mode)
{
    const int tid = threadIdx.x;
    const int lane = tid & 31;
    const int wid = tid >> 5;
    const int wm = wid & 1;
    const int wn = wid >> 1;
    const int m0 = blockIdx.y * GM;
    const int n0 = blockIdx.x * GN;

    const uint32_t sbase = smem_u32(gemm_smem);

    float c[4][8][4];
    #pragma unroll
    for (int i = 0; i < 4; i++)
        #pragma unroll
        for (int j = 0; j < 8; j++)
            #pragma unroll
            for (int k = 0; k < 4; k++)
                c[i][j][k] = 0.f;

    auto issue = [&](int ch, int buf) {
        const int k0 = ch * KC;
        const uint32_t sb = sbase + buf * STAGE;
        #pragma unroll
        for (int i = 0; i < 2; i++) {
            int idx = i * 256 + tid;
            int row = idx >> 2, cc = idx & 3;
            size_t go = ((size_t)(m0 + row) << 10) + k0 + cc * 8;
            uint32_t dof = row * 80 + cc * 16;
            cp_async16(sb + dof, g_Ahi + go);
            cp_async16(sb + A_ST + dof, g_Alo + go);
        }
        #pragma unroll
        for (int i = 0; i < 4; i++) {
            int idx = i * 256 + tid;
            int row = idx >> 2, cc = idx & 3;
            size_t go = ((size_t)(n0 + row) << 10) + k0 + cc * 8;
            uint32_t dof = row * 80 + cc * 16;
            cp_async16(sb + 2 * A_ST + dof, gBhi + go);
            cp_async16(sb + 2 * A_ST + B_ST + dof, gBlo + go);
        }
    };

    issue(0, 0);
    asm volatile("cp.async.commit_group;" ::: "memory");

    const uint32_t a_lrow = (lane & 15);
    const uint32_t a_lk   = (lane >> 4) * 16;
    const uint32_t b_lrow = (lane & 7) | ((lane >> 1) & 8);
    const uint32_t b_lk   = ((lane >> 3) & 1) * 16;

    for (int ch = 0; ch < NCHUNK; ch++) {
        const int buf = ch & 1;
        if (ch + 1 < NCHUNK) {
            issue(ch + 1, buf ^ 1);
            asm volatile("cp.async.commit_group;" ::: "memory");
            asm volatile("cp.async.wait_group 1;" ::: "memory");
        } else {
            asm volatile("cp.async.wait_group 0;" ::: "memory");
        }
        __syncthreads();

        const uint32_t sA = sbase + buf * STAGE;
        const uint32_t sB = sA + 2 * A_ST;

        #pragma unroll
        for (int ks = 0; ks < 2; ks++) {
            const uint32_t kb = ks * 32;
            uint32_t ahi[4][4], bhi[4][4];
            #pragma unroll
            for (int mf = 0; mf < 4; mf++) {
                uint32_t ad = sA + (wm * 64 + mf * 16 + a_lrow) * 80 + kb + a_lk;
                ldsm_x4(ahi[mf][0], ahi[mf][1], ahi[mf][2], ahi[mf][3], ad);
            }
            #pragma unroll
            for (int np = 0; np < 4; np++) {
                uint32_t bd = sB + (wn * 64 + np * 16 + b_lrow) * 80 + kb + b_lk;
                ldsm_x4(bhi[np][0], bhi[np][1], bhi[np][2], bhi[np][3], bd);
            }
            #pragma unroll
            for (int mf = 0; mf < 4; mf++)
                #pragma unroll
                for (int np = 0; np < 4; np++) {
                    mma_bf16(c[mf][2 * np],     ahi[mf], bhi[np][0], bhi[np][1]);
                    mma_bf16(c[mf][2 * np + 1], ahi[mf], bhi[np][2], bhi[np][3]);
                }
            #pragma unroll
            for (int mf = 0; mf < 4; mf++) {
                uint32_t alo[4];
                uint32_t ad = sA + A_ST + (wm * 64 + mf * 16 + a_lrow) * 80 + kb + a_lk;
                ldsm_x4(alo[0], alo[1], alo[2], alo[3], ad);
                #pragma unroll
                for (int np = 0; np < 4; np++) {
                    mma_bf16(c[mf][2 * np],     alo, bhi[np][0], bhi[np][1]);
                    mma_bf16(c[mf][2 * np + 1], alo, bhi[np][2], bhi[np][3]);
                }
            }
            #pragma unroll
            for (int np = 0; np < 4; np++) {
                uint32_t blo[4];
                uint32_t bd = sB + B_ST + (wn * 64 + np * 16 + b_lrow) * 80 + kb + b_lk;
                ldsm_x4(blo[0], blo[1], blo[2], blo[3], bd);
                #pragma unroll
                for (int mf = 0; mf < 4; mf++) {
                    mma_bf16(c[mf][2 * np],     ahi[mf], blo[0], blo[1]);
                    mma_bf16(c[mf][2 * np + 1], ahi[mf], blo[2], blo[3]);
                }
            }
        }
        __syncthreads();
    }

    // ---- epilogue ----
    const int which = n0 >> 10;
    const int h = ((n0 + wn * 64) & (C_ - 1)) >> 6;
    __nv_bfloat16* dhi = which == 0 ? g_Qhi : which == 1 ? g_Khi : g_Vhi;
    __nv_bfloat16* dlo = which == 0 ? g_Qlo : which == 1 ? g_Klo : g_Vlo;
    const float sc = (which == 0) ? 0.125f : 1.0f;

    #pragma unroll
    for (int mf = 0; mf < 4; mf++) {
        const int mrow = m0 + wm * 64 + mf * 16 + (lane >> 2);
        #pragma unroll
        for (int nf = 0; nf < 8; nf++) {
            const int n = n0 + wn * 64 + nf * 8 + (lane & 3) * 2;
            const float bx = bias[n], by = bias[n + 1];
            if (mode == 0) {
                const int b = mrow >> 11, t = mrow & (T_ - 1);
                const int d = n & 63;
                size_t base = (((size_t)(b * H_ + h) * T_ + t) << 6) + d;
                uint32_t hi, lo;
                split_pack((c[mf][nf][0] + bx) * sc, (c[mf][nf][1] + by) * sc, hi, lo);
                *(uint32_t*)(dhi + base) = hi;
                *(uint32_t*)(dlo + base) = lo;
                split_pack((c[mf][nf][2] + bx) * sc, (c[mf][nf][3] + by) * sc, hi, lo);
                *(uint32_t*)(dhi + base + ((size_t)8 << 6)) = hi;
                *(uint32_t*)(dlo + base + ((size_t)8 << 6)) = lo;
            } else {
                float* p = Cout + (size_t)mrow * C_ + n;
                p[0] = c[mf][nf][0] + bx;
                p[1] = c[mf][nf][1] + by;
                p += (size_t)8 * C_;
                p[0] = c[mf][nf][2] + bx;
                p[1] = c[mf][nf][3] + by;
            }
        }
    }
}

// ---------------------------------------------------------------------------
// MMA flash attention. CTA: 128 q-rows (8 warps x m16), key tiles of 64.
// 3-stage cp.async ring. Output written as bf16 hi/lo into g_Ahi/g_Alo.
// ---------------------------------------------------------------------------
#define ROWB 144                  // 64 bf16 = 128 B + 16 pad
#define ATT_ARR (64 * ROWB)       // 9216
#define ATT_STAGE (4 * ATT_ARR)   // 36864
#define ATT_SMEM (3 * ATT_STAGE)  // 110592

extern __shared__ char att_smem[];

__global__ void __launch_bounds__(256, 1) attn_mma_kernel()
{
    const uint32_t sb = smem_u32(att_smem);
    const int tid = threadIdx.x, lane = tid & 31, wid = tid >> 5;
    const int bh = blockIdx.y;
    const int qt = (int)(gridDim.x - 1) - (int)blockIdx.x;   // heavy-first
    const int qb = qt * 128;
    const int ntiles = 2 * qt + 2;

    const size_t bhoff = (size_t)bh * T_ * DK_;
    const __nv_bfloat16* Khi = g_Khi + bhoff;
    const __nv_bfloat16* Klo = g_Klo + bhoff;
    const __nv_bfloat16* Vhi = g_Vhi + bhoff;
    const __nv_bfloat16* Vlo = g_Vlo + bhoff;

    // --- stage Q (hi+lo) through smem, ldmatrix into registers ---
    {
        const __nv_bfloat16* Qh = g_Qhi + bhoff + (size_t)qb * DK_;
        const __nv_bfloat16* Ql = g_Qlo + bhoff + (size_t)qb * DK_;
        #pragma unroll
        for (int i = 0; i < 4; i++) {
            int idx = i * 256 + tid;          // 0..1023
            int row = idx >> 3, ch = idx & 7;
            cp_async16(sb + row * ROWB + ch * 16, Qh + row * 64 + ch * 8);
            cp_async16(sb + 128 * ROWB + row * ROWB + ch * 16, Ql + row * 64 + ch * 8);
        }
        asm volatile("cp.async.commit_group;" ::: "memory");
        asm volatile("cp.async.wait_group 0;" ::: "memory");
        __syncthreads();
    }
    uint32_t qhi[4][4], qlo[4][4];
    {
        const uint32_t ar = wid * 16 + (lane & 15);
        const uint32_t ac = (lane >> 4) * 16;
        #pragma unroll
        for (int j = 0; j < 4; j++) {
            ldsm_x4(qhi[j][0], qhi[j][1], qhi[j][2], qhi[j][3],
                    sb + ar * ROWB + j * 32 + ac);
            ldsm_x4(qlo[j][0], qlo[j][1], qlo[j][2], qlo[j][3],
                    sb + 128 * ROWB + ar * ROWB + j * 32 + ac);
        }
    }
    __syncthreads();

    auto issue_tile = [&](int kt, int st) {
        const size_t goff = (size_t)kt * 64 * 64;
        const uint32_t s0 = sb + st * ATT_STAGE;
        const __nv_bfloat16* gs[4] = { Khi + goff, Klo + goff, Vhi + goff, Vlo + goff };
        #pragma unroll
        for (int a = 0; a < 4; a++) {
            #pragma unroll
            for (int i = 0; i < 2; i++) {
                int idx = i * 256 + tid;       // 0..511
                int row = idx >> 3, ch = idx & 7;
                cp_async16(s0 + a * ATT_ARR + row * ROWB + ch * 16,
                           gs[a] + row * 64 + ch * 8);
            }
        }
        asm volatile("cp.async.commit_group;" ::: "memory");
    };

    float O[8][4];
    #pragma unroll
    for (int f = 0; f < 8; f++)
        #pragma unroll
        for (int j = 0; j < 4; j++)
            O[f][j] = 0.f;
    float m0v = -1e30f, m1v = -1e30f, l0v = 0.f, l1v = 0.f;

    issue_tile(0, 0);
    if (ntiles > 1) issue_tile(1, 1);

    const uint32_t b_lrow = (lane & 7) | ((lane >> 1) & 8);
    const uint32_t b_lk   = ((lane >> 3) & 1) * 16;
    const uint32_t v_row  = lane & 15;
    const uint32_t v_cb   = (lane >> 4) * 16;
    const int q0 = qb + wid * 16 + (lane >> 2);
    const int q1 = q0 + 8;

    for (int kt = 0; kt < ntiles; kt++) {
        if (kt + 1 < ntiles)
            asm volatile("cp.async.wait_group 1;" ::: "memory");
        else
            asm volatile("cp.async.wait_group 0;" ::: "memory");
        __syncthreads();
        if (kt + 2 < ntiles) issue_tile(kt + 2, (kt + 2) % 3);

        const uint32_t sK  = sb + (kt % 3) * ATT_STAGE;
        const uint32_t sKl = sK + ATT_ARR;
        const uint32_t sV  = sK + 2 * ATT_ARR;
        const uint32_t sVl = sK + 3 * ATT_ARR;

        float c[8][4];
        #pragma unroll
        for (int f = 0; f < 8; f++)
            #pragma unroll
            for (int j = 0; j < 4; j++)
                c[f][j] = 0.f;

        // S = Qhi*Khi + Qlo*Khi + Qhi*Klo
        #pragma unroll
        for (int j = 0; j < 4; j++) {
            #pragma unroll
            for (int nb = 0; nb < 4; nb++) {
                uint32_t b0, b1, b2, b3;
                ldsm_x4(b0, b1, b2, b3,
                        sK + (nb * 16 + b_lrow) * ROWB + j * 32 + b_lk);
                mma_bf16(c[2 * nb],     qhi[j], b0, b1);
                mma_bf16(c[2 * nb + 1], qhi[j], b2, b3);
                mma_bf16(c[2 * nb],     qlo[j], b0, b1);
                mma_bf16(c[2 * nb + 1], qlo[j], b2, b3);
                ldsm_x4(b0, b1, b2, b3,
                        sKl + (nb * 16 + b_lrow) * ROWB + j * 32 + b_lk);
                mma_bf16(c[2 * nb],     qhi[j], b0, b1);
                mma_bf16(c[2 * nb + 1], qhi[j], b2, b3);
            }
        }

        // causal mask (only the last two tiles can touch the diagonal)
        if (kt >= 2 * qt) {
            const int kb = kt * 64;
            #pragma unroll
            for (int f = 0; f < 8; f++) {
                const int kc = kb + f * 8 + (lane & 3) * 2;
                if (kc     > q0) c[f][0] = -1e30f;
                if (kc + 1 > q0) c[f][1] = -1e30f;
                if (kc     > q1) c[f][2] = -1e30f;
                if (kc + 1 > q1) c[f][3] = -1e30f;
            }
        }

        // online softmax
        float tm0 = -1e30f, tm1 = -1e30f;
        #pragma unroll
        for (int f = 0; f < 8; f++) {
            tm0 = fmaxf(tm0, fmaxf(c[f][0], c[f][1]));
            tm1 = fmaxf(tm1, fmaxf(c[f][2], c[f][3]));
        }
        tm0 = fmaxf(tm0, __shfl_xor_sync(0xffffffffu, tm0, 1));
        tm0 = fmaxf(tm0, __shfl_xor_sync(0xffffffffu, tm0, 2));
        tm1 = fmaxf(tm1, __shfl_xor_sync(0xffffffffu, tm1, 1));
        tm1 = fmaxf(tm1, __shfl_xor_sync(0xffffffffu, tm1, 2));
        const float mn0 = fmaxf(m0v, tm0), mn1 = fmaxf(m1v, tm1);
        const float cor0 = __expf(m0v - mn0), cor1 = __expf(m1v - mn1);
        m0v = mn0; m1v = mn1;
        float rs0 = 0.f, rs1 = 0.f;
        #pragma unroll
        for (int f = 0; f < 8; f++) {
            c[f][0] = __expf(c[f][0] - mn0);
            c[f][1] = __expf(c[f][1] - mn0);
            c[f][2] = __expf(c[f][2] - mn1);
            c[f][3] = __expf(c[f][3] - mn1);
            rs0 += c[f][0] + c[f][1];
            rs1 += c[f][2] + c[f][3];
        }
        rs0 += __shfl_xor_sync(0xffffffffu, rs0, 1);
        rs0 += __shfl_xor_sync(0xffffffffu, rs0, 2);
        rs1 += __shfl_xor_sync(0xffffffffu, rs1, 1);
        rs1 += __shfl_xor_sync(0xffffffffu, rs1, 2);
        l0v = l0v * cor0 + rs0;
        l1v = l1v * cor1 + rs1;
        #pragma unroll
        for (int f = 0; f < 8; f++) {
            O[f][0] *= cor0; O[f][1] *= cor0;
            O[f][2] *= cor1; O[f][3] *= cor1;
        }

        // P -> bf16 hi/lo A-frags (C-frag pair == A-frag k16)
        uint32_t ph[4][4], pl[4][4];
        #pragma unroll
        for (int j = 0; j < 4; j++) {
            split_pack(c[2 * j][0],     c[2 * j][1],     ph[j][0], pl[j][0]);
            split_pack(c[2 * j][2],     c[2 * j][3],     ph[j][1], pl[j][1]);
            split_pack(c[2 * j + 1][0], c[2 * j + 1][1], ph[j][2], pl[j][2]);
            split_pack(c[2 * j + 1][2], c[2 * j + 1][3], ph[j][3], pl[j][3]);
        }

        // O += Phi*Vhi + Plo*Vhi + Phi*Vlo   (V B-frags via ldmatrix.trans)
        #pragma unroll
        for (int j = 0; j < 4; j++) {
            #pragma unroll
            for (int db = 0; db < 4; db++) {
                uint32_t b0, b1, b2, b3;
                ldsm_x4t(b0, b1, b2, b3,
                         sV + (j * 16 + v_row) * ROWB + db * 32 + v_cb);
                mma_bf16(O[2 * db],     ph[j], b0, b1);
                mma_bf16(O[2 * db + 1], ph[j], b2, b3);
                mma_bf16(O[2 * db],     pl[j], b0, b1);
                mma_bf16(O[2 * db + 1], pl[j], b2, b3);
                ldsm_x4t(b0, b1, b2, b3,
                         sVl + (j * 16 + v_row) * ROWB + db * 32 + v_cb);
                mma_bf16(O[2 * db],     ph[j], b0, b1);
                mma_bf16(O[2 * db + 1], ph[j], b2, b3);
            }
        }
    }

    // epilogue: normalize, split to bf16 hi/lo, write [b*T+t][h*64+d]
    const float inv0 = 1.f / l0v, inv1 = 1.f / l1v;
    const int b = bh >> 4, h = bh & 15;
    const int t0 = qb + wid * 16 + (lane >> 2);
    const size_t r0 = ((size_t)b * T_ + t0) * C_ + h * 64;
    const size_t r1 = r0 + (size_t)8 * C_;
    #pragma unroll
    for (int f = 0; f < 8; f++) {
        const int d = f * 8 + (lane & 3) * 2;
        uint32_t hi, lo;
        split_pack(O[f][0] * inv0, O[f][1] * inv0, hi, lo);
        *(uint32_t*)(g_Ahi + r0 + d) = hi;
        *(uint32_t*)(g_Alo + r0 + d) = lo;
        split_pack(O[f][2] * inv1, O[f][3] * inv1, hi, lo);
        *(uint32_t*)(g_Ahi + r1 + d) = hi;
        *(uint32_t*)(g_Alo + r1 + d) = lo;
    }
}

// ---------------------------------------------------------------------------
extern "C" void kernel_launch(void* const* d_in, const int* in_sizes, int n_in,
                              void* d_out, int out_size)
{
    const float* x      = (const float*)d_in[0];
    const float* W_qkv  = (const float*)d_in[1];
    const float* b_qkv  = (const float*)d_in[2];
    const float* W_proj = (const float*)d_in[3];
    const float* b_proj = (const float*)d_in[4];
    float* out = (float*)d_out;

    static int inited = 0;
    if (!inited) {
        cudaFuncSetAttribute(gemm_bf16_kernel,
                             cudaFuncAttributeMaxDynamicSharedMemorySize, 2 * STAGE);
        cudaFuncSetAttribute(attn_mma_kernel,
                             cudaFuncAttributeMaxDynamicSharedMemorySize, ATT_SMEM);
        inited = 1;
    }

    __nv_bfloat16 *Whi_d, *Wlo_d;
    cudaGetSymbolAddress((void**)&Whi_d, g_Whi);
    cudaGetSymbolAddress((void**)&Wlo_d, g_Wlo);

    dim3 tb(32, 8);
    split_w_kernel<<<dim3(N_QKV / 32, C_ / 32), tb>>>(W_qkv, N_QKV, 0);
    split_w_kernel<<<dim3(C_ / 32, C_ / 32), tb>>>(W_proj, C_, N_QKV);
    split_act_kernel<<<(M_ * C_) / (256 * 4), 256>>>(x);

    gemm_bf16_kernel<<<dim3(N_QKV / GN, M_ / GM), 256, 2 * STAGE>>>(
        Whi_d, Wlo_d, b_qkv, nullptr, 0);

    attn_mma_kernel<<<dim3(T_ / 128, B_ * H_), 256, ATT_SMEM>>>();

    gemm_bf16_kernel<<<dim3(C_ / GN, M_ / GM), 256, 2 * STAGE>>>(
        Whi_d + (size_t)N_QKV * C_, Wlo_d + (size_t)N_QKV * C_,
        b_proj, out, 1);
}

// round 5
// speedup vs baseline: 3.3538x; 1.0023x over previous
#include <cuda_runtime.h>
#include <cuda_bf16.h>
#include <cstdint>

// CausalSelfAttention: B=4, T=2048, C=1024, H=16, dk=64.
// R5: wave-quantization fix (qkv GN=192 -> 1024 CTAs = 6.92 waves) +
// 3-stage cp.async ring with single __syncthreads per chunk on both GEMMs.

#define B_   4
#define T_   2048
#define C_   1024
#define H_   16
#define DK_  64
#define M_   (B_ * T_)        // 8192
#define N_QKV (3 * C_)        // 3072

#define QKV_ELEMS ((size_t)B_ * H_ * T_ * DK_)
__device__ __align__(16) __nv_bfloat16 g_Qhi[QKV_ELEMS];   // scaled by 0.125
__device__ __align__(16) __nv_bfloat16 g_Qlo[QKV_ELEMS];
__device__ __align__(16) __nv_bfloat16 g_Khi[QKV_ELEMS];
__device__ __align__(16) __nv_bfloat16 g_Klo[QKV_ELEMS];
__device__ __align__(16) __nv_bfloat16 g_Vhi[QKV_ELEMS];
__device__ __align__(16) __nv_bfloat16 g_Vlo[QKV_ELEMS];
__device__ __align__(16) __nv_bfloat16 g_Ahi[(size_t)M_ * C_];
__device__ __align__(16) __nv_bfloat16 g_Alo[(size_t)M_ * C_];
__device__ __align__(16) __nv_bfloat16 g_Whi[(size_t)(N_QKV + C_) * C_];
__device__ __align__(16) __nv_bfloat16 g_Wlo[(size_t)(N_QKV + C_) * C_];

// ---------------------------------------------------------------------------
// helpers
// ---------------------------------------------------------------------------
__device__ __forceinline__ uint32_t smem_u32(const void* p) {
    uint32_t a;
    asm("{ .reg .u64 t; cvta.to.shared.u64 t, %1; cvt.u32.u64 %0, t; }"
        : "=r"(a) : "l"(p));
    return a;
}
__device__ __forceinline__ void cp_async16(uint32_t dst, const void* src) {
    asm volatile("cp.async.ca.shared.global [%0], [%1], 16;"
                 :: "r"(dst), "l"(__cvta_generic_to_global(src)) : "memory");
}
__device__ __forceinline__ void ldsm_x4(uint32_t& r0, uint32_t& r1,
                                        uint32_t& r2, uint32_t& r3, uint32_t a) {
    asm volatile("ldmatrix.sync.aligned.m8n8.x4.shared.b16 {%0,%1,%2,%3}, [%4];"
                 : "=r"(r0), "=r"(r1), "=r"(r2), "=r"(r3) : "r"(a));
}
__device__ __forceinline__ void ldsm_x4t(uint32_t& r0, uint32_t& r1,
                                         uint32_t& r2, uint32_t& r3, uint32_t a) {
    asm volatile("ldmatrix.sync.aligned.m8n8.x4.trans.shared.b16 {%0,%1,%2,%3}, [%4];"
                 : "=r"(r0), "=r"(r1), "=r"(r2), "=r"(r3) : "r"(a));
}
__device__ __forceinline__ void mma_bf16(float* c, const uint32_t* a,
                                         uint32_t b0, uint32_t b1) {
    asm volatile(
        "mma.sync.aligned.m16n8k16.row.col.f32.bf16.bf16.f32 "
        "{%0,%1,%2,%3}, {%4,%5,%6,%7}, {%8,%9}, {%0,%1,%2,%3};"
        : "+f"(c[0]), "+f"(c[1]), "+f"(c[2]), "+f"(c[3])
        : "r"(a[0]), "r"(a[1]), "r"(a[2]), "r"(a[3]), "r"(b0), "r"(b1));
}
__device__ __forceinline__ void split_pack(float x, float y,
                                           uint32_t& hi, uint32_t& lo) {
    __nv_bfloat16 hx = __float2bfloat16_rn(x);
    __nv_bfloat16 hy = __float2bfloat16_rn(y);
    __nv_bfloat162 h; h.x = hx; h.y = hy;
    hi = *(uint32_t*)&h;
    __nv_bfloat162 l;
    l.x = __float2bfloat16_rn(x - __bfloat162float(hx));
    l.y = __float2bfloat16_rn(y - __bfloat162float(hy));
    lo = *(uint32_t*)&l;
}

// ---------------------------------------------------------------------------
// Split fp32 -> bf16 hi/lo (x input only).
// ---------------------------------------------------------------------------
__global__ void __launch_bounds__(256) split_act_kernel(const float* __restrict__ src)
{
    size_t i = ((size_t)blockIdx.x * 256 + threadIdx.x) * 4;
    float4 v = *(const float4*)(src + i);
    __nv_bfloat16 hx = __float2bfloat16_rn(v.x);
    __nv_bfloat16 hy = __float2bfloat16_rn(v.y);
    __nv_bfloat16 hz = __float2bfloat16_rn(v.z);
    __nv_bfloat16 hw = __float2bfloat16_rn(v.w);
    __nv_bfloat16 h2[4] = { hx, hy, hz, hw };
    *(uint2*)(g_Ahi + i) = *(uint2*)h2;
    __nv_bfloat16 l2[4] = {
        __float2bfloat16_rn(v.x - __bfloat162float(hx)),
        __float2bfloat16_rn(v.y - __bfloat162float(hy)),
        __float2bfloat16_rn(v.z - __bfloat162float(hz)),
        __float2bfloat16_rn(v.w - __bfloat162float(hw)) };
    *(uint2*)(g_Alo + i) = *(uint2*)l2;
}

// ---------------------------------------------------------------------------
// Transpose + split weights: W[k][N] -> Whi/Wlo[row_off + n][k]
// ---------------------------------------------------------------------------
__global__ void __launch_bounds__(256) split_w_kernel(
    const float* __restrict__ W, int Ncols, int row_off)
{
    __shared__ float tile[32][33];
    const int tx = threadIdx.x, ty = threadIdx.y;
    const int n0 = blockIdx.x * 32;
    const int k0 = blockIdx.y * 32;
    #pragma unroll
    for (int j = ty; j < 32; j += 8)
        tile[j][tx] = W[(size_t)(k0 + j) * Ncols + n0 + tx];
    __syncthreads();
    #pragma unroll
    for (int j = ty; j < 32; j += 8) {
        float v = tile[tx][j];
        __nv_bfloat16 h = __float2bfloat16_rn(v);
        __nv_bfloat16 l = __float2bfloat16_rn(v - __bfloat162float(h));
        size_t o = (size_t)(row_off + n0 + j) * C_ + k0 + tx;
        g_Whi[o] = h;
        g_Wlo[o] = l;
    }
}

// ---------------------------------------------------------------------------
// mma.sync bf16 GEMM (3-term split), templated on NF = 8-col frags per warp.
// Tile 128 x (32*NF). 8 warps (2m x 4n), warp tile 64 x (8*NF).
// 3-stage cp.async ring, single __syncthreads per chunk, issue after sync.
// mode 0: epilogue -> bf16 hi/lo Q/K/V head-major (Q scaled 0.125), handles
//         tiles straddling the Q/K/V boundary (per-group which/h/d).
// mode 1: epilogue -> fp32 out + bias.
// ---------------------------------------------------------------------------
#define GM 128
#define KC 32
#define NCHUNK (C_ / KC)

extern __shared__ char gemm_smem[];

template<int NF>
__global__ void __launch_bounds__(256, 1) gemm_bf16_kernel(
    const __nv_bfloat16* __restrict__ gBhi,
    const __nv_bfloat16* __restrict__ gBlo,
    const float* __restrict__ bias,
    float* __restrict__ Cout,
    int mode)
{
    constexpr int GNt   = 32 * NF;
    constexpr int A_STb = GM * 80;
    constexpr int B_STb = GNt * 80;
    constexpr int STAGEb = 2 * A_STb + 2 * B_STb;
    constexpr int NP = NF / 2;

    const int tid = threadIdx.x;
    const int lane = tid & 31;
    const int wid = tid >> 5;
    const int wm = wid & 1;
    const int wn = wid >> 1;
    const int m0 = blockIdx.y * GM;
    const int n0 = blockIdx.x * GNt;

    const uint32_t sbase = smem_u32(gemm_smem);

    float c[4][NF][4];
    #pragma unroll
    for (int i = 0; i < 4; i++)
        #pragma unroll
        for (int j = 0; j < NF; j++)
            #pragma unroll
            for (int k = 0; k < 4; k++)
                c[i][j][k] = 0.f;

    auto issue = [&](int ch) {
        const int k0 = ch * KC;
        const uint32_t sb = sbase + (ch % 3) * STAGEb;
        #pragma unroll
        for (int i = 0; i < 2; i++) {
            int idx = i * 256 + tid;
            int row = idx >> 2, cc = idx & 3;
            size_t go = ((size_t)(m0 + row) << 10) + k0 + cc * 8;
            uint32_t dof = row * 80 + cc * 16;
            cp_async16(sb + dof, g_Ahi + go);
            cp_async16(sb + A_STb + dof, g_Alo + go);
        }
        #pragma unroll
        for (int i = 0; i < NP; i++) {
            int idx = i * 256 + tid;
            int row = idx >> 2, cc = idx & 3;
            size_t go = ((size_t)(n0 + row) << 10) + k0 + cc * 8;
            uint32_t dof = row * 80 + cc * 16;
            cp_async16(sb + 2 * A_STb + dof, gBhi + go);
            cp_async16(sb + 2 * A_STb + B_STb + dof, gBlo + go);
        }
        asm volatile("cp.async.commit_group;" ::: "memory");
    };

    issue(0);
    issue(1);

    const uint32_t a_lrow = (lane & 15);
    const uint32_t a_lk   = (lane >> 4) * 16;
    const uint32_t b_lrow = (lane & 7) | ((lane >> 1) & 8);
    const uint32_t b_lk   = ((lane >> 3) & 1) * 16;

    for (int ch = 0; ch < NCHUNK; ch++) {
        if (ch + 1 < NCHUNK)
            asm volatile("cp.async.wait_group 1;" ::: "memory");
        else
            asm volatile("cp.async.wait_group 0;" ::: "memory");
        __syncthreads();
        if (ch + 2 < NCHUNK) issue(ch + 2);

        const uint32_t sA = sbase + (ch % 3) * STAGEb;
        const uint32_t sB = sA + 2 * A_STb;

        #pragma unroll
        for (int ks = 0; ks < 2; ks++) {
            const uint32_t kb = ks * 32;
            uint32_t ahi[4][4], bhi[NP][4];
            #pragma unroll
            for (int mf = 0; mf < 4; mf++) {
                uint32_t ad = sA + (wm * 64 + mf * 16 + a_lrow) * 80 + kb + a_lk;
                ldsm_x4(ahi[mf][0], ahi[mf][1], ahi[mf][2], ahi[mf][3], ad);
            }
            #pragma unroll
            for (int np = 0; np < NP; np++) {
                uint32_t bd = sB + (wn * GNt / 4 + np * 16 + b_lrow) * 80 + kb + b_lk;
                ldsm_x4(bhi[np][0], bhi[np][1], bhi[np][2], bhi[np][3], bd);
            }
            #pragma unroll
            for (int mf = 0; mf < 4; mf++)
                #pragma unroll
                for (int np = 0; np < NP; np++) {
                    mma_bf16(c[mf][2 * np],     ahi[mf], bhi[np][0], bhi[np][1]);
                    mma_bf16(c[mf][2 * np + 1], ahi[mf], bhi[np][2], bhi[np][3]);
                }
            #pragma unroll
            for (int mf = 0; mf < 4; mf++) {
                uint32_t alo[4];
                uint32_t ad = sA + A_STb + (wm * 64 + mf * 16 + a_lrow) * 80 + kb + a_lk;
                ldsm_x4(alo[0], alo[1], alo[2], alo[3], ad);
                #pragma unroll
                for (int np = 0; np < NP; np++) {
                    mma_bf16(c[mf][2 * np],     alo, bhi[np][0], bhi[np][1]);
                    mma_bf16(c[mf][2 * np + 1], alo, bhi[np][2], bhi[np][3]);
                }
            }
            #pragma unroll
            for (int np = 0; np < NP; np++) {
                uint32_t blo[4];
                uint32_t bd = sB + B_STb + (wn * GNt / 4 + np * 16 + b_lrow) * 80 + kb + b_lk;
                ldsm_x4(blo[0], blo[1], blo[2], blo[3], bd);
                #pragma unroll
                for (int mf = 0; mf < 4; mf++) {
                    mma_bf16(c[mf][2 * np],     ahi[mf], blo[0], blo[1]);
                    mma_bf16(c[mf][2 * np + 1], ahi[mf], blo[2], blo[3]);
                }
            }
        }
        __syncthreads();   // protect buffer reuse for (ch%3) stage re-issue
    }

    // ---- epilogue ----
    __nv_bfloat16* Hs[3] = { g_Qhi, g_Khi, g_Vhi };
    __nv_bfloat16* Ls[3] = { g_Qlo, g_Klo, g_Vlo };

    #pragma unroll
    for (int mf = 0; mf < 4; mf++) {
        const int mrow = m0 + wm * 64 + mf * 16 + (lane >> 2);
        #pragma unroll
        for (int nf = 0; nf < NF; nf++) {
            const int n = n0 + wn * (NF * 8) + nf * 8 + (lane & 3) * 2;
            const float bx = bias[n], by = bias[n + 1];
            if (mode == 0) {
                const int which = n >> 10;
                const int h = (n >> 6) & 15;
                const int d = n & 63;
                const float sc = (which == 0) ? 0.125f : 1.0f;
                const int b = mrow >> 11, t = mrow & (T_ - 1);
                size_t base = (((size_t)(b * H_ + h) * T_ + t) << 6) + d;
                uint32_t hi, lo;
                split_pack((c[mf][nf][0] + bx) * sc, (c[mf][nf][1] + by) * sc, hi, lo);
                *(uint32_t*)(Hs[which] + base) = hi;
                *(uint32_t*)(Ls[which] + base) = lo;
                split_pack((c[mf][nf][2] + bx) * sc, (c[mf][nf][3] + by) * sc, hi, lo);
                *(uint32_t*)(Hs[which] + base + 512) = hi;   // (t+8) << 6
                *(uint32_t*)(Ls[which] + base + 512) = lo;
            } else {
                float* p = Cout + (size_t)mrow * C_ + n;
                p[0] = c[mf][nf][0] + bx;
                p[1] = c[mf][nf][1] + by;
                p += (size_t)8 * C_;
                p[0] = c[mf][nf][2] + bx;
                p[1] = c[mf][nf][3] + by;
            }
        }
    }
}

// ---------------------------------------------------------------------------
// MMA flash attention (R4, validated). 128 q-rows x 64-key tiles, 8 warps.
// ---------------------------------------------------------------------------
#define ROWB 144
#define ATT_ARR (64 * ROWB)
#define ATT_STAGE (4 * ATT_ARR)
#define ATT_SMEM (3 * ATT_STAGE)

extern __shared__ char att_smem[];

__global__ void __launch_bounds__(256, 1) attn_mma_kernel()
{
    const uint32_t sb = smem_u32(att_smem);
    const int tid = threadIdx.x, lane = tid & 31, wid = tid >> 5;
    const int bh = blockIdx.y;
    const int qt = (int)(gridDim.x - 1) - (int)blockIdx.x;   // heavy-first
    const int qb = qt * 128;
    const int ntiles = 2 * qt + 2;

    const size_t bhoff = (size_t)bh * T_ * DK_;
    const __nv_bfloat16* Khi = g_Khi + bhoff;
    const __nv_bfloat16* Klo = g_Klo + bhoff;
    const __nv_bfloat16* Vhi = g_Vhi + bhoff;
    const __nv_bfloat16* Vlo = g_Vlo + bhoff;

    {
        const __nv_bfloat16* Qh = g_Qhi + bhoff + (size_t)qb * DK_;
        const __nv_bfloat16* Ql = g_Qlo + bhoff + (size_t)qb * DK_;
        #pragma unroll
        for (int i = 0; i < 4; i++) {
            int idx = i * 256 + tid;
            int row = idx >> 3, ch = idx & 7;
            cp_async16(sb + row * ROWB + ch * 16, Qh + row * 64 + ch * 8);
            cp_async16(sb + 128 * ROWB + row * ROWB + ch * 16, Ql + row * 64 + ch * 8);
        }
        asm volatile("cp.async.commit_group;" ::: "memory");
        asm volatile("cp.async.wait_group 0;" ::: "memory");
        __syncthreads();
    }
    uint32_t qhi[4][4], qlo[4][4];
    {
        const uint32_t ar = wid * 16 + (lane & 15);
        const uint32_t ac = (lane >> 4) * 16;
        #pragma unroll
        for (int j = 0; j < 4; j++) {
            ldsm_x4(qhi[j][0], qhi[j][1], qhi[j][2], qhi[j][3],
                    sb + ar * ROWB + j * 32 + ac);
            ldsm_x4(qlo[j][0], qlo[j][1], qlo[j][2], qlo[j][3],
                    sb + 128 * ROWB + ar * ROWB + j * 32 + ac);
        }
    }
    __syncthreads();

    auto issue_tile = [&](int kt, int st) {
        const size_t goff = (size_t)kt * 64 * 64;
        const uint32_t s0 = sb + st * ATT_STAGE;
        const __nv_bfloat16* gs[4] = { Khi + goff, Klo + goff, Vhi + goff, Vlo + goff };
        #pragma unroll
        for (int a = 0; a < 4; a++) {
            #pragma unroll
            for (int i = 0; i < 2; i++) {
                int idx = i * 256 + tid;
                int row = idx >> 3, ch = idx & 7;
                cp_async16(s0 + a * ATT_ARR + row * ROWB + ch * 16,
                           gs[a] + row * 64 + ch * 8);
            }
        }
        asm volatile("cp.async.commit_group;" ::: "memory");
    };

    float O[8][4];
    #pragma unroll
    for (int f = 0; f < 8; f++)
        #pragma unroll
        for (int j = 0; j < 4; j++)
            O[f][j] = 0.f;
    float m0v = -1e30f, m1v = -1e30f, l0v = 0.f, l1v = 0.f;

    issue_tile(0, 0);
    if (ntiles > 1) issue_tile(1, 1);

    const uint32_t b_lrow = (lane & 7) | ((lane >> 1) & 8);
    const uint32_t b_lk   = ((lane >> 3) & 1) * 16;
    const uint32_t v_row  = lane & 15;
    const uint32_t v_cb   = (lane >> 4) * 16;
    const int q0 = qb + wid * 16 + (lane >> 2);
    const int q1 = q0 + 8;

    for (int kt = 0; kt < ntiles; kt++) {
        if (kt + 1 < ntiles)
            asm volatile("cp.async.wait_group 1;" ::: "memory");
        else
            asm volatile("cp.async.wait_group 0;" ::: "memory");
        __syncthreads();
        if (kt + 2 < ntiles) issue_tile(kt + 2, (kt + 2) % 3);

        const uint32_t sK  = sb + (kt % 3) * ATT_STAGE;
        const uint32_t sKl = sK + ATT_ARR;
        const uint32_t sV  = sK + 2 * ATT_ARR;
        const uint32_t sVl = sK + 3 * ATT_ARR;

        float c[8][4];
        #pragma unroll
        for (int f = 0; f < 8; f++)
            #pragma unroll
            for (int j = 0; j < 4; j++)
                c[f][j] = 0.f;

        #pragma unroll
        for (int j = 0; j < 4; j++) {
            #pragma unroll
            for (int nb = 0; nb < 4; nb++) {
                uint32_t b0, b1, b2, b3;
                ldsm_x4(b0, b1, b2, b3,
                        sK + (nb * 16 + b_lrow) * ROWB + j * 32 + b_lk);
                mma_bf16(c[2 * nb],     qhi[j], b0, b1);
                mma_bf16(c[2 * nb + 1], qhi[j], b2, b3);
                mma_bf16(c[2 * nb],     qlo[j], b0, b1);
                mma_bf16(c[2 * nb + 1], qlo[j], b2, b3);
                ldsm_x4(b0, b1, b2, b3,
                        sKl + (nb * 16 + b_lrow) * ROWB + j * 32 + b_lk);
                mma_bf16(c[2 * nb],     qhi[j], b0, b1);
                mma_bf16(c[2 * nb + 1], qhi[j], b2, b3);
            }
        }

        if (kt >= 2 * qt) {
            const int kb = kt * 64;
            #pragma unroll
            for (int f = 0; f < 8; f++) {
                const int kc = kb + f * 8 + (lane & 3) * 2;
                if (kc     > q0) c[f][0] = -1e30f;
                if (kc + 1 > q0) c[f][1] = -1e30f;
                if (kc     > q1) c[f][2] = -1e30f;
                if (kc + 1 > q1) c[f][3] = -1e30f;
            }
        }

        float tm0 = -1e30f, tm1 = -1e30f;
        #pragma unroll
        for (int f = 0; f < 8; f++) {
            tm0 = fmaxf(tm0, fmaxf(c[f][0], c[f][1]));
            tm1 = fmaxf(tm1, fmaxf(c[f][2], c[f][3]));
        }
        tm0 = fmaxf(tm0, __shfl_xor_sync(0xffffffffu, tm0, 1));
        tm0 = fmaxf(tm0, __shfl_xor_sync(0xffffffffu, tm0, 2));
        tm1 = fmaxf(tm1, __shfl_xor_sync(0xffffffffu, tm1, 1));
        tm1 = fmaxf(tm1, __shfl_xor_sync(0xffffffffu, tm1, 2));
        const float mn0 = fmaxf(m0v, tm0), mn1 = fmaxf(m1v, tm1);
        const float cor0 = __expf(m0v - mn0), cor1 = __expf(m1v - mn1);
        m0v = mn0; m1v = mn1;
        float rs0 = 0.f, rs1 = 0.f;
        #pragma unroll
        for (int f = 0; f < 8; f++) {
            c[f][0] = __expf(c[f][0] - mn0);
            c[f][1] = __expf(c[f][1] - mn0);
            c[f][2] = __expf(c[f][2] - mn1);
            c[f][3] = __expf(c[f][3] - mn1);
            rs0 += c[f][0] + c[f][1];
            rs1 += c[f][2] + c[f][3];
        }
        rs0 += __shfl_xor_sync(0xffffffffu, rs0, 1);
        rs0 += __shfl_xor_sync(0xffffffffu, rs0, 2);
        rs1 += __shfl_xor_sync(0xffffffffu, rs1, 1);
        rs1 += __shfl_xor_sync(0xffffffffu, rs1, 2);
        l0v = l0v * cor0 + rs0;
        l1v = l1v * cor1 + rs1;
        #pragma unroll
        for (int f = 0; f < 8; f++) {
            O[f][0] *= cor0; O[f][1] *= cor0;
            O[f][2] *= cor1; O[f][3] *= cor1;
        }

        uint32_t ph[4][4], pl[4][4];
        #pragma unroll
        for (int j = 0; j < 4; j++) {
            split_pack(c[2 * j][0],     c[2 * j][1],     ph[j][0], pl[j][0]);
            split_pack(c[2 * j][2],     c[2 * j][3],     ph[j][1], pl[j][1]);
            split_pack(c[2 * j + 1][0], c[2 * j + 1][1], ph[j][2], pl[j][2]);
            split_pack(c[2 * j + 1][2], c[2 * j + 1][3], ph[j][3], pl[j][3]);
        }

        #pragma unroll
        for (int j = 0; j < 4; j++) {
            #pragma unroll
            for (int db = 0; db < 4; db++) {
                uint32_t b0, b1, b2, b3;
                ldsm_x4t(b0, b1, b2, b3,
                         sV + (j * 16 + v_row) * ROWB + db * 32 + v_cb);
                mma_bf16(O[2 * db],     ph[j], b0, b1);
                mma_bf16(O[2 * db + 1], ph[j], b2, b3);
                mma_bf16(O[2 * db],     pl[j], b0, b1);
                mma_bf16(O[2 * db + 1], pl[j], b2, b3);
                ldsm_x4t(b0, b1, b2, b3,
                         sVl + (j * 16 + v_row) * ROWB + db * 32 + v_cb);
                mma_bf16(O[2 * db],     ph[j], b0, b1);
                mma_bf16(O[2 * db + 1], ph[j], b2, b3);
            }
        }
    }

    const float inv0 = 1.f / l0v, inv1 = 1.f / l1v;
    const int b = bh >> 4, h = bh & 15;
    const int t0 = qb + wid * 16 + (lane >> 2);
    const size_t r0 = ((size_t)b * T_ + t0) * C_ + h * 64;
    const size_t r1 = r0 + (size_t)8 * C_;
    #pragma unroll
    for (int f = 0; f < 8; f++) {
        const int d = f * 8 + (lane & 3) * 2;
        uint32_t hi, lo;
        split_pack(O[f][0] * inv0, O[f][1] * inv0, hi, lo);
        *(uint32_t*)(g_Ahi + r0 + d) = hi;
        *(uint32_t*)(g_Alo + r0 + d) = lo;
        split_pack(O[f][2] * inv1, O[f][3] * inv1, hi, lo);
        *(uint32_t*)(g_Ahi + r1 + d) = hi;
        *(uint32_t*)(g_Alo + r1 + d) = lo;
    }
}

// ---------------------------------------------------------------------------
#define STAGE6 (2 * (GM * 80) + 2 * (192 * 80))   // 51200
#define STAGE8 (2 * (GM * 80) + 2 * (256 * 80))   // 61440

extern "C" void kernel_launch(void* const* d_in, const int* in_sizes, int n_in,
                              void* d_out, int out_size)
{
    const float* x      = (const float*)d_in[0];
    const float* W_qkv  = (const float*)d_in[1];
    const float* b_qkv  = (const float*)d_in[2];
    const float* W_proj = (const float*)d_in[3];
    const float* b_proj = (const float*)d_in[4];
    float* out = (float*)d_out;

    static int inited = 0;
    if (!inited) {
        cudaFuncSetAttribute(gemm_bf16_kernel<6>,
                             cudaFuncAttributeMaxDynamicSharedMemorySize, 3 * STAGE6);
        cudaFuncSetAttribute(gemm_bf16_kernel<8>,
                             cudaFuncAttributeMaxDynamicSharedMemorySize, 3 * STAGE8);
        cudaFuncSetAttribute(attn_mma_kernel,
                             cudaFuncAttributeMaxDynamicSharedMemorySize, ATT_SMEM);
        inited = 1;
    }

    __nv_bfloat16 *Whi_d, *Wlo_d;
    cudaGetSymbolAddress((void**)&Whi_d, g_Whi);
    cudaGetSymbolAddress((void**)&Wlo_d, g_Wlo);

    dim3 tb(32, 8);
    split_w_kernel<<<dim3(N_QKV / 32, C_ / 32), tb>>>(W_qkv, N_QKV, 0);
    split_w_kernel<<<dim3(C_ / 32, C_ / 32), tb>>>(W_proj, C_, N_QKV);
    split_act_kernel<<<(M_ * C_) / (256 * 4), 256>>>(x);

    gemm_bf16_kernel<6><<<dim3(N_QKV / 192, M_ / GM), 256, 3 * STAGE6>>>(
        Whi_d, Wlo_d, b_qkv, nullptr, 0);

    attn_mma_kernel<<<dim3(T_ / 128, B_ * H_), 256, ATT_SMEM>>>();

    gemm_bf16_kernel<8><<<dim3(C_ / 256, M_ / GM), 256, 3 * STAGE8>>>(
        Whi_d + (size_t)N_QKV * C_, Wlo_d + (size_t)N_QKV * C_,
        b_proj, out, 1);
}

// round 6
// speedup vs baseline: 3.3745x; 1.0062x over previous
#include <cuda_runtime.h>
#include <cuda_bf16.h>
#include <cstdint>

// CausalSelfAttention: B=4, T=2048, C=1024, H=16, dk=64.
// R6: GEMM restructured to 128-thread CTAs (tile 128x96, 2 CTAs/SM) with a
// true single-barrier 3-stage cp.async ring. proj shares the kernel via
// bounds-checked N. Attention (R4 mma.sync flash, validated) unchanged.

#define B_   4
#define T_   2048
#define C_   1024
#define H_   16
#define DK_  64
#define M_   (B_ * T_)        // 8192
#define N_QKV (3 * C_)        // 3072

#define QKV_ELEMS ((size_t)B_ * H_ * T_ * DK_)
__device__ __align__(16) __nv_bfloat16 g_Qhi[QKV_ELEMS];   // scaled by 0.125
__device__ __align__(16) __nv_bfloat16 g_Qlo[QKV_ELEMS];
__device__ __align__(16) __nv_bfloat16 g_Khi[QKV_ELEMS];
__device__ __align__(16) __nv_bfloat16 g_Klo[QKV_ELEMS];
__device__ __align__(16) __nv_bfloat16 g_Vhi[QKV_ELEMS];
__device__ __align__(16) __nv_bfloat16 g_Vlo[QKV_ELEMS];
__device__ __align__(16) __nv_bfloat16 g_Ahi[(size_t)M_ * C_];
__device__ __align__(16) __nv_bfloat16 g_Alo[(size_t)M_ * C_];
// +128 pad rows so the proj GEMM's ragged last N-tile loads stay in-bounds.
__device__ __align__(16) __nv_bfloat16 g_Whi[(size_t)(N_QKV + C_ + 128) * C_];
__device__ __align__(16) __nv_bfloat16 g_Wlo[(size_t)(N_QKV + C_ + 128) * C_];

// ---------------------------------------------------------------------------
// helpers
// ---------------------------------------------------------------------------
__device__ __forceinline__ uint32_t smem_u32(const void* p) {
    uint32_t a;
    asm("{ .reg .u64 t; cvta.to.shared.u64 t, %1; cvt.u32.u64 %0, t; }"
        : "=r"(a) : "l"(p));
    return a;
}
__device__ __forceinline__ void cp_async16(uint32_t dst, const void* src) {
    asm volatile("cp.async.ca.shared.global [%0], [%1], 16;"
                 :: "r"(dst), "l"(__cvta_generic_to_global(src)) : "memory");
}
__device__ __forceinline__ void ldsm_x4(uint32_t& r0, uint32_t& r1,
                                        uint32_t& r2, uint32_t& r3, uint32_t a) {
    asm volatile("ldmatrix.sync.aligned.m8n8.x4.shared.b16 {%0,%1,%2,%3}, [%4];"
                 : "=r"(r0), "=r"(r1), "=r"(r2), "=r"(r3) : "r"(a));
}
__device__ __forceinline__ void ldsm_x4t(uint32_t& r0, uint32_t& r1,
                                         uint32_t& r2, uint32_t& r3, uint32_t a) {
    asm volatile("ldmatrix.sync.aligned.m8n8.x4.trans.shared.b16 {%0,%1,%2,%3}, [%4];"
                 : "=r"(r0), "=r"(r1), "=r"(r2), "=r"(r3) : "r"(a));
}
__device__ __forceinline__ void mma_bf16(float* c, const uint32_t* a,
                                         uint32_t b0, uint32_t b1) {
    asm volatile(
        "mma.sync.aligned.m16n8k16.row.col.f32.bf16.bf16.f32 "
        "{%0,%1,%2,%3}, {%4,%5,%6,%7}, {%8,%9}, {%0,%1,%2,%3};"
        : "+f"(c[0]), "+f"(c[1]), "+f"(c[2]), "+f"(c[3])
        : "r"(a[0]), "r"(a[1]), "r"(a[2]), "r"(a[3]), "r"(b0), "r"(b1));
}
__device__ __forceinline__ void split_pack(float x, float y,
                                           uint32_t& hi, uint32_t& lo) {
    __nv_bfloat16 hx = __float2bfloat16_rn(x);
    __nv_bfloat16 hy = __float2bfloat16_rn(y);
    __nv_bfloat162 h; h.x = hx; h.y = hy;
    hi = *(uint32_t*)&h;
    __nv_bfloat162 l;
    l.x = __float2bfloat16_rn(x - __bfloat162float(hx));
    l.y = __float2bfloat16_rn(y - __bfloat162float(hy));
    lo = *(uint32_t*)&l;
}

// ---------------------------------------------------------------------------
// Split fp32 -> bf16 hi/lo (x input only).
// ---------------------------------------------------------------------------
__global__ void __launch_bounds__(256) split_act_kernel(const float* __restrict__ src)
{
    size_t i = ((size_t)blockIdx.x * 256 + threadIdx.x) * 4;
    float4 v = *(const float4*)(src + i);
    __nv_bfloat16 hx = __float2bfloat16_rn(v.x);
    __nv_bfloat16 hy = __float2bfloat16_rn(v.y);
    __nv_bfloat16 hz = __float2bfloat16_rn(v.z);
    __nv_bfloat16 hw = __float2bfloat16_rn(v.w);
    __nv_bfloat16 h2[4] = { hx, hy, hz, hw };
    *(uint2*)(g_Ahi + i) = *(uint2*)h2;
    __nv_bfloat16 l2[4] = {
        __float2bfloat16_rn(v.x - __bfloat162float(hx)),
        __float2bfloat16_rn(v.y - __bfloat162float(hy)),
        __float2bfloat16_rn(v.z - __bfloat162float(hz)),
        __float2bfloat16_rn(v.w - __bfloat162float(hw)) };
    *(uint2*)(g_Alo + i) = *(uint2*)l2;
}

// ---------------------------------------------------------------------------
// Transpose + split weights: W[k][N] -> Whi/Wlo[row_off + n][k]
// ---------------------------------------------------------------------------
__global__ void __launch_bounds__(256) split_w_kernel(
    const float* __restrict__ W, int Ncols, int row_off)
{
    __shared__ float tile[32][33];
    const int tx = threadIdx.x, ty = threadIdx.y;
    const int n0 = blockIdx.x * 32;
    const int k0 = blockIdx.y * 32;
    #pragma unroll
    for (int j = ty; j < 32; j += 8)
        tile[j][tx] = W[(size_t)(k0 + j) * Ncols + n0 + tx];
    __syncthreads();
    #pragma unroll
    for (int j = ty; j < 32; j += 8) {
        float v = tile[tx][j];
        __nv_bfloat16 h = __float2bfloat16_rn(v);
        __nv_bfloat16 l = __float2bfloat16_rn(v - __bfloat162float(h));
        size_t o = (size_t)(row_off + n0 + j) * C_ + k0 + tx;
        g_Whi[o] = h;
        g_Wlo[o] = l;
    }
}

// ---------------------------------------------------------------------------
// mma.sync bf16 GEMM (3-term split). Tile 128(M) x 96(N) x 32(K-chunk).
// 128 threads = 4 warps (2m x 2n), warp tile 64x48 (NP=3 n-frags of 16).
// 3-stage cp.async ring, ONE __syncthreads per chunk. 2 CTAs/SM.
// mode 0: epilogue -> bf16 hi/lo Q/K/V head-major (Q scaled 0.125).
// mode 1: epilogue -> fp32 out + bias, columns guarded by n < Nlim.
// ---------------------------------------------------------------------------
#define GM 128
#define GN 96
#define KC 32
#define NCHUNK (C_ / KC)
#define A_ST (GM * 80)            // 10240
#define B_ST (GN * 80)            // 7680
#define STAGE (2 * A_ST + 2 * B_ST) // 35840
#define GEMM_SMEM (3 * STAGE)       // 107520

extern __shared__ char gemm_smem[];

__global__ void __launch_bounds__(128, 2) gemm_bf16_kernel(
    const __nv_bfloat16* __restrict__ gBhi,
    const __nv_bfloat16* __restrict__ gBlo,
    const float* __restrict__ bias,
    float* __restrict__ Cout,
    int mode, int Nlim)
{
    const int tid = threadIdx.x;
    const int lane = tid & 31;
    const int wid = tid >> 5;           // 0..3
    const int wm = wid & 1;             // m half
    const int wn = wid >> 1;            // n half
    const int m0 = blockIdx.y * GM;
    const int n0 = blockIdx.x * GN;

    const uint32_t sbase = smem_u32(gemm_smem);

    float c[4][6][4];
    #pragma unroll
    for (int i = 0; i < 4; i++)
        #pragma unroll
        for (int j = 0; j < 6; j++)
            #pragma unroll
            for (int k = 0; k < 4; k++)
                c[i][j][k] = 0.f;

    auto issue = [&](int ch) {
        const int k0 = ch * KC;
        const uint32_t sb = sbase + (ch % 3) * STAGE;
        #pragma unroll
        for (int i = 0; i < 4; i++) {          // A hi/lo: 512 16B units each
            int idx = i * 128 + tid;
            int row = idx >> 2, cc = idx & 3;
            size_t go = ((size_t)(m0 + row) << 10) + k0 + cc * 8;
            uint32_t dof = row * 80 + cc * 16;
            cp_async16(sb + dof, g_Ahi + go);
            cp_async16(sb + A_ST + dof, g_Alo + go);
        }
        #pragma unroll
        for (int i = 0; i < 3; i++) {          // B hi/lo: 384 16B units each
            int idx = i * 128 + tid;
            int row = idx >> 2, cc = idx & 3;
            size_t go = ((size_t)(n0 + row) << 10) + k0 + cc * 8;
            uint32_t dof = row * 80 + cc * 16;
            cp_async16(sb + 2 * A_ST + dof, gBhi + go);
            cp_async16(sb + 2 * A_ST + B_ST + dof, gBlo + go);
        }
        asm volatile("cp.async.commit_group;" ::: "memory");
    };

    issue(0);
    issue(1);

    const uint32_t a_lrow = (lane & 15);
    const uint32_t a_lk   = (lane >> 4) * 16;
    const uint32_t b_lrow = (lane & 7) | ((lane >> 1) & 8);
    const uint32_t b_lk   = ((lane >> 3) & 1) * 16;

    for (int ch = 0; ch < NCHUNK; ch++) {
        if (ch + 1 < NCHUNK)
            asm volatile("cp.async.wait_group 1;" ::: "memory");
        else
            asm volatile("cp.async.wait_group 0;" ::: "memory");
        __syncthreads();      // the ONLY barrier per chunk: makes stage ch
                              // visible to all warps AND proves iteration ch-1
                              // compute done before issue() reuses its stage.
        if (ch + 2 < NCHUNK) issue(ch + 2);

        const uint32_t sA = sbase + (ch % 3) * STAGE;
        const uint32_t sB = sA + 2 * A_ST;

        #pragma unroll
        for (int ks = 0; ks < 2; ks++) {
            const uint32_t kb = ks * 32;
            uint32_t ahi[4][4], bhi[3][4];
            #pragma unroll
            for (int mf = 0; mf < 4; mf++) {
                uint32_t ad = sA + (wm * 64 + mf * 16 + a_lrow) * 80 + kb + a_lk;
                ldsm_x4(ahi[mf][0], ahi[mf][1], ahi[mf][2], ahi[mf][3], ad);
            }
            #pragma unroll
            for (int np = 0; np < 3; np++) {
                uint32_t bd = sB + (wn * 48 + np * 16 + b_lrow) * 80 + kb + b_lk;
                ldsm_x4(bhi[np][0], bhi[np][1], bhi[np][2], bhi[np][3], bd);
            }
            #pragma unroll
            for (int mf = 0; mf < 4; mf++)
                #pragma unroll
                for (int np = 0; np < 3; np++) {
                    mma_bf16(c[mf][2 * np],     ahi[mf], bhi[np][0], bhi[np][1]);
                    mma_bf16(c[mf][2 * np + 1], ahi[mf], bhi[np][2], bhi[np][3]);
                }
            #pragma unroll
            for (int mf = 0; mf < 4; mf++) {
                uint32_t alo[4];
                uint32_t ad = sA + A_ST + (wm * 64 + mf * 16 + a_lrow) * 80 + kb + a_lk;
                ldsm_x4(alo[0], alo[1], alo[2], alo[3], ad);
                #pragma unroll
                for (int np = 0; np < 3; np++) {
                    mma_bf16(c[mf][2 * np],     alo, bhi[np][0], bhi[np][1]);
                    mma_bf16(c[mf][2 * np + 1], alo, bhi[np][2], bhi[np][3]);
                }
            }
            #pragma unroll
            for (int np = 0; np < 3; np++) {
                uint32_t blo[4];
                uint32_t bd = sB + B_ST + (wn * 48 + np * 16 + b_lrow) * 80 + kb + b_lk;
                ldsm_x4(blo[0], blo[1], blo[2], blo[3], bd);
                #pragma unroll
                for (int mf = 0; mf < 4; mf++) {
                    mma_bf16(c[mf][2 * np],     ahi[mf], blo[0], blo[1]);
                    mma_bf16(c[mf][2 * np + 1], ahi[mf], blo[2], blo[3]);
                }
            }
        }
        // no bottom barrier — top-of-loop barrier covers stage reuse.
    }

    // ---- epilogue ----
    __nv_bfloat16* Hs[3] = { g_Qhi, g_Khi, g_Vhi };
    __nv_bfloat16* Ls[3] = { g_Qlo, g_Klo, g_Vlo };

    #pragma unroll
    for (int mf = 0; mf < 4; mf++) {
        const int mrow = m0 + wm * 64 + mf * 16 + (lane >> 2);
        #pragma unroll
        for (int nf = 0; nf < 6; nf++) {
            const int n = n0 + wn * 48 + nf * 8 + (lane & 3) * 2;
            if (mode == 0) {
                const float bx = bias[n], by = bias[n + 1];
                const int which = n >> 10;
                const int h = (n >> 6) & 15;
                const int d = n & 63;
                const float sc = (which == 0) ? 0.125f : 1.0f;
                const int b = mrow >> 11, t = mrow & (T_ - 1);
                size_t base = (((size_t)(b * H_ + h) * T_ + t) << 6) + d;
                uint32_t hi, lo;
                split_pack((c[mf][nf][0] + bx) * sc, (c[mf][nf][1] + by) * sc, hi, lo);
                *(uint32_t*)(Hs[which] + base) = hi;
                *(uint32_t*)(Ls[which] + base) = lo;
                split_pack((c[mf][nf][2] + bx) * sc, (c[mf][nf][3] + by) * sc, hi, lo);
                *(uint32_t*)(Hs[which] + base + 512) = hi;   // (t+8) << 6
                *(uint32_t*)(Ls[which] + base + 512) = lo;
            } else if (n < Nlim) {
                const float bx = bias[n], by = bias[n + 1];
                float* p = Cout + (size_t)mrow * C_ + n;
                p[0] = c[mf][nf][0] + bx;
                p[1] = c[mf][nf][1] + by;
                p += (size_t)8 * C_;
                p[0] = c[mf][nf][2] + bx;
                p[1] = c[mf][nf][3] + by;
            }
        }
    }
}

// ---------------------------------------------------------------------------
// MMA flash attention (R4, validated). 128 q-rows x 64-key tiles, 8 warps.
// ---------------------------------------------------------------------------
#define ROWB 144
#define ATT_ARR (64 * ROWB)
#define ATT_STAGE (4 * ATT_ARR)
#define ATT_SMEM (3 * ATT_STAGE)

extern __shared__ char att_smem[];

__global__ void __launch_bounds__(256, 1) attn_mma_kernel()
{
    const uint32_t sb = smem_u32(att_smem);
    const int tid = threadIdx.x, lane = tid & 31, wid = tid >> 5;
    const int bh = blockIdx.y;
    const int qt = (int)(gridDim.x - 1) - (int)blockIdx.x;   // heavy-first
    const int qb = qt * 128;
    const int ntiles = 2 * qt + 2;

    const size_t bhoff = (size_t)bh * T_ * DK_;
    const __nv_bfloat16* Khi = g_Khi + bhoff;
    const __nv_bfloat16* Klo = g_Klo + bhoff;
    const __nv_bfloat16* Vhi = g_Vhi + bhoff;
    const __nv_bfloat16* Vlo = g_Vlo + bhoff;

    {
        const __nv_bfloat16* Qh = g_Qhi + bhoff + (size_t)qb * DK_;
        const __nv_bfloat16* Ql = g_Qlo + bhoff + (size_t)qb * DK_;
        #pragma unroll
        for (int i = 0; i < 4; i++) {
            int idx = i * 256 + tid;
            int row = idx >> 3, ch = idx & 7;
            cp_async16(sb + row * ROWB + ch * 16, Qh + row * 64 + ch * 8);
            cp_async16(sb + 128 * ROWB + row * ROWB + ch * 16, Ql + row * 64 + ch * 8);
        }
        asm volatile("cp.async.commit_group;" ::: "memory");
        asm volatile("cp.async.wait_group 0;" ::: "memory");
        __syncthreads();
    }
    uint32_t qhi[4][4], qlo[4][4];
    {
        const uint32_t ar = wid * 16 + (lane & 15);
        const uint32_t ac = (lane >> 4) * 16;
        #pragma unroll
        for (int j = 0; j < 4; j++) {
            ldsm_x4(qhi[j][0], qhi[j][1], qhi[j][2], qhi[j][3],
                    sb + ar * ROWB + j * 32 + ac);
            ldsm_x4(qlo[j][0], qlo[j][1], qlo[j][2], qlo[j][3],
                    sb + 128 * ROWB + ar * ROWB + j * 32 + ac);
        }
    }
    __syncthreads();

    auto issue_tile = [&](int kt, int st) {
        const size_t goff = (size_t)kt * 64 * 64;
        const uint32_t s0 = sb + st * ATT_STAGE;
        const __nv_bfloat16* gs[4] = { Khi + goff, Klo + goff, Vhi + goff, Vlo + goff };
        #pragma unroll
        for (int a = 0; a < 4; a++) {
            #pragma unroll
            for (int i = 0; i < 2; i++) {
                int idx = i * 256 + tid;
                int row = idx >> 3, ch = idx & 7;
                cp_async16(s0 + a * ATT_ARR + row * ROWB + ch * 16,
                           gs[a] + row * 64 + ch * 8);
            }
        }
        asm volatile("cp.async.commit_group;" ::: "memory");
    };

    float O[8][4];
    #pragma unroll
    for (int f = 0; f < 8; f++)
        #pragma unroll
        for (int j = 0; j < 4; j++)
            O[f][j] = 0.f;
    float m0v = -1e30f, m1v = -1e30f, l0v = 0.f, l1v = 0.f;

    issue_tile(0, 0);
    if (ntiles > 1) issue_tile(1, 1);

    const uint32_t b_lrow = (lane & 7) | ((lane >> 1) & 8);
    const uint32_t b_lk   = ((lane >> 3) & 1) * 16;
    const uint32_t v_row  = lane & 15;
    const uint32_t v_cb   = (lane >> 4) * 16;
    const int q0 = qb + wid * 16 + (lane >> 2);
    const int q1 = q0 + 8;

    for (int kt = 0; kt < ntiles; kt++) {
        if (kt + 1 < ntiles)
            asm volatile("cp.async.wait_group 1;" ::: "memory");
        else
            asm volatile("cp.async.wait_group 0;" ::: "memory");
        __syncthreads();
        if (kt + 2 < ntiles) issue_tile(kt + 2, (kt + 2) % 3);

        const uint32_t sK  = sb + (kt % 3) * ATT_STAGE;
        const uint32_t sKl = sK + ATT_ARR;
        const uint32_t sV  = sK + 2 * ATT_ARR;
        const uint32_t sVl = sK + 3 * ATT_ARR;

        float c[8][4];
        #pragma unroll
        for (int f = 0; f < 8; f++)
            #pragma unroll
            for (int j = 0; j < 4; j++)
                c[f][j] = 0.f;

        #pragma unroll
        for (int j = 0; j < 4; j++) {
            #pragma unroll
            for (int nb = 0; nb < 4; nb++) {
                uint32_t b0, b1, b2, b3;
                ldsm_x4(b0, b1, b2, b3,
                        sK + (nb * 16 + b_lrow) * ROWB + j * 32 + b_lk);
                mma_bf16(c[2 * nb],     qhi[j], b0, b1);
                mma_bf16(c[2 * nb + 1], qhi[j], b2, b3);
                mma_bf16(c[2 * nb],     qlo[j], b0, b1);
                mma_bf16(c[2 * nb + 1], qlo[j], b2, b3);
                ldsm_x4(b0, b1, b2, b3,
                        sKl + (nb * 16 + b_lrow) * ROWB + j * 32 + b_lk);
                mma_bf16(c[2 * nb],     qhi[j], b0, b1);
                mma_bf16(c[2 * nb + 1], qhi[j], b2, b3);
            }
        }

        if (kt >= 2 * qt) {
            const int kb = kt * 64;
            #pragma unroll
            for (int f = 0; f < 8; f++) {
                const int kc = kb + f * 8 + (lane & 3) * 2;
                if (kc     > q0) c[f][0] = -1e30f;
                if (kc + 1 > q0) c[f][1] = -1e30f;
                if (kc     > q1) c[f][2] = -1e30f;
                if (kc + 1 > q1) c[f][3] = -1e30f;
            }
        }

        float tm0 = -1e30f, tm1 = -1e30f;
        #pragma unroll
        for (int f = 0; f < 8; f++) {
            tm0 = fmaxf(tm0, fmaxf(c[f][0], c[f][1]));
            tm1 = fmaxf(tm1, fmaxf(c[f][2], c[f][3]));
        }
        tm0 = fmaxf(tm0, __shfl_xor_sync(0xffffffffu, tm0, 1));
        tm0 = fmaxf(tm0, __shfl_xor_sync(0xffffffffu, tm0, 2));
        tm1 = fmaxf(tm1, __shfl_xor_sync(0xffffffffu, tm1, 1));
        tm1 = fmaxf(tm1, __shfl_xor_sync(0xffffffffu, tm1, 2));
        const float mn0 = fmaxf(m0v, tm0), mn1 = fmaxf(m1v, tm1);
        const float cor0 = __expf(m0v - mn0), cor1 = __expf(m1v - mn1);
        m0v = mn0; m1v = mn1;
        float rs0 = 0.f, rs1 = 0.f;
        #pragma unroll
        for (int f = 0; f < 8; f++) {
            c[f][0] = __expf(c[f][0] - mn0);
            c[f][1] = __expf(c[f][1] - mn0);
            c[f][2] = __expf(c[f][2] - mn1);
            c[f][3] = __expf(c[f][3] - mn1);
            rs0 += c[f][0] + c[f][1];
            rs1 += c[f][2] + c[f][3];
        }
        rs0 += __shfl_xor_sync(0xffffffffu, rs0, 1);
        rs0 += __shfl_xor_sync(0xffffffffu, rs0, 2);
        rs1 += __shfl_xor_sync(0xffffffffu, rs1, 1);
        rs1 += __shfl_xor_sync(0xffffffffu, rs1, 2);
        l0v = l0v * cor0 + rs0;
        l1v = l1v * cor1 + rs1;
        #pragma unroll
        for (int f = 0; f < 8; f++) {
            O[f][0] *= cor0; O[f][1] *= cor0;
            O[f][2] *= cor1; O[f][3] *= cor1;
        }

        uint32_t ph[4][4], pl[4][4];
        #pragma unroll
        for (int j = 0; j < 4; j++) {
            split_pack(c[2 * j][0],     c[2 * j][1],     ph[j][0], pl[j][0]);
            split_pack(c[2 * j][2],     c[2 * j][3],     ph[j][1], pl[j][1]);
            split_pack(c[2 * j + 1][0], c[2 * j + 1][1], ph[j][2], pl[j][2]);
            split_pack(c[2 * j + 1][2], c[2 * j + 1][3], ph[j][3], pl[j][3]);
        }

        #pragma unroll
        for (int j = 0; j < 4; j++) {
            #pragma unroll
            for (int db = 0; db < 4; db++) {
                uint32_t b0, b1, b2, b3;
                ldsm_x4t(b0, b1, b2, b3,
                         sV + (j * 16 + v_row) * ROWB + db * 32 + v_cb);
                mma_bf16(O[2 * db],     ph[j], b0, b1);
                mma_bf16(O[2 * db + 1], ph[j], b2, b3);
                mma_bf16(O[2 * db],     pl[j], b0, b1);
                mma_bf16(O[2 * db + 1], pl[j], b2, b3);
                ldsm_x4t(b0, b1, b2, b3,
                         sVl + (j * 16 + v_row) * ROWB + db * 32 + v_cb);
                mma_bf16(O[2 * db],     ph[j], b0, b1);
                mma_bf16(O[2 * db + 1], ph[j], b2, b3);
            }
        }
    }

    const float inv0 = 1.f / l0v, inv1 = 1.f / l1v;
    const int b = bh >> 4, h = bh & 15;
    const int t0 = qb + wid * 16 + (lane >> 2);
    const size_t r0 = ((size_t)b * T_ + t0) * C_ + h * 64;
    const size_t r1 = r0 + (size_t)8 * C_;
    #pragma unroll
    for (int f = 0; f < 8; f++) {
        const int d = f * 8 + (lane & 3) * 2;
        uint32_t hi, lo;
        split_pack(O[f][0] * inv0, O[f][1] * inv0, hi, lo);
        *(uint32_t*)(g_Ahi + r0 + d) = hi;
        *(uint32_t*)(g_Alo + r0 + d) = lo;
        split_pack(O[f][2] * inv1, O[f][3] * inv1, hi, lo);
        *(uint32_t*)(g_Ahi + r1 + d) = hi;
        *(uint32_t*)(g_Alo + r1 + d) = lo;
    }
}

// ---------------------------------------------------------------------------
extern "C" void kernel_launch(void* const* d_in, const int* in_sizes, int n_in,
                              void* d_out, int out_size)
{
    const float* x      = (const float*)d_in[0];
    const float* W_qkv  = (const float*)d_in[1];
    const float* b_qkv  = (const float*)d_in[2];
    const float* W_proj = (const float*)d_in[3];
    const float* b_proj = (const float*)d_in[4];
    float* out = (float*)d_out;

    static int inited = 0;
    if (!inited) {
        cudaFuncSetAttribute(gemm_bf16_kernel,
                             cudaFuncAttributeMaxDynamicSharedMemorySize, GEMM_SMEM);
        cudaFuncSetAttribute(attn_mma_kernel,
                             cudaFuncAttributeMaxDynamicSharedMemorySize, ATT_SMEM);
        inited = 1;
    }

    __nv_bfloat16 *Whi_d, *Wlo_d;
    cudaGetSymbolAddress((void**)&Whi_d, g_Whi);
    cudaGetSymbolAddress((void**)&Wlo_d, g_Wlo);

    dim3 tb(32, 8);
    split_w_kernel<<<dim3(N_QKV / 32, C_ / 32), tb>>>(W_qkv, N_QKV, 0);
    split_w_kernel<<<dim3(C_ / 32, C_ / 32), tb>>>(W_proj, C_, N_QKV);
    split_act_kernel<<<(M_ * C_) / (256 * 4), 256>>>(x);

    // qkv: 3072/96 = 32 n-tiles x 64 m-tiles = 2048 CTAs (6.92 waves @2/SM)
    gemm_bf16_kernel<<<dim3(N_QKV / GN, M_ / GM), 128, GEMM_SMEM>>>(
        Whi_d, Wlo_d, b_qkv, nullptr, 0, N_QKV);

    attn_mma_kernel<<<dim3(T_ / 128, B_ * H_), 256, ATT_SMEM>>>();

    // proj: ceil(1024/96) = 11 n-tiles x 64 = 704 CTAs; ragged tile guarded.
    gemm_bf16_kernel<<<dim3((C_ + GN - 1) / GN, M_ / GM), 128, GEMM_SMEM>>>(
        Whi_d + (size_t)N_QKV * C_, Wlo_d + (size_t)N_QKV * C_,
        b_proj, out, 1, C_);
}

// round 7
// speedup vs baseline: 4.7192x; 1.3985x over previous
#include <cuda_runtime.h>
#include <cuda_fp16.h>
#include <cstdint>

// CausalSelfAttention: B=4, T=2048, C=1024, H=16, dk=64.
// R7: fp16 asymmetric 2-term split. A-side (x, Q, P, attn-out) split into
// fp16 hi+lo; B-side (W, K, V) single fp16. 2 MMAs per logical matmul
// instead of 3; K/V staging traffic halved. Error ~2^-12 (~2.4e-4) per
// matmul, dominated by the unsplit B rounding.

#define B_   4
#define T_   2048
#define C_   1024
#define H_   16
#define DK_  64
#define M_   (B_ * T_)        // 8192
#define N_QKV (3 * C_)        // 3072

#define QKV_ELEMS ((size_t)B_ * H_ * T_ * DK_)
__device__ __align__(16) __half g_Qhi[QKV_ELEMS];   // scaled by 0.125
__device__ __align__(16) __half g_Qlo[QKV_ELEMS];
__device__ __align__(16) __half g_K[QKV_ELEMS];     // single fp16
__device__ __align__(16) __half g_V[QKV_ELEMS];     // single fp16
__device__ __align__(16) __half g_Ahi[(size_t)M_ * C_];   // GEMM A input hi
__device__ __align__(16) __half g_Alo[(size_t)M_ * C_];   // GEMM A input lo
// +128 pad rows so the proj GEMM's ragged last N-tile loads stay in-bounds.
__device__ __align__(16) __half g_Wh[(size_t)(N_QKV + C_ + 128) * C_];

// ---------------------------------------------------------------------------
// helpers
// ---------------------------------------------------------------------------
__device__ __forceinline__ uint32_t smem_u32(const void* p) {
    uint32_t a;
    asm("{ .reg .u64 t; cvta.to.shared.u64 t, %1; cvt.u32.u64 %0, t; }"
        : "=r"(a) : "l"(p));
    return a;
}
__device__ __forceinline__ void cp_async16(uint32_t dst, const void* src) {
    asm volatile("cp.async.ca.shared.global [%0], [%1], 16;"
                 :: "r"(dst), "l"(__cvta_generic_to_global(src)) : "memory");
}
__device__ __forceinline__ void ldsm_x4(uint32_t& r0, uint32_t& r1,
                                        uint32_t& r2, uint32_t& r3, uint32_t a) {
    asm volatile("ldmatrix.sync.aligned.m8n8.x4.shared.b16 {%0,%1,%2,%3}, [%4];"
                 : "=r"(r0), "=r"(r1), "=r"(r2), "=r"(r3) : "r"(a));
}
__device__ __forceinline__ void ldsm_x4t(uint32_t& r0, uint32_t& r1,
                                         uint32_t& r2, uint32_t& r3, uint32_t a) {
    asm volatile("ldmatrix.sync.aligned.m8n8.x4.trans.shared.b16 {%0,%1,%2,%3}, [%4];"
                 : "=r"(r0), "=r"(r1), "=r"(r2), "=r"(r3) : "r"(a));
}
__device__ __forceinline__ void mma_f16(float* c, const uint32_t* a,
                                        uint32_t b0, uint32_t b1) {
    asm volatile(
        "mma.sync.aligned.m16n8k16.row.col.f32.f16.f16.f32 "
        "{%0,%1,%2,%3}, {%4,%5,%6,%7}, {%8,%9}, {%0,%1,%2,%3};"
        : "+f"(c[0]), "+f"(c[1]), "+f"(c[2]), "+f"(c[3])
        : "r"(a[0]), "r"(a[1]), "r"(a[2]), "r"(a[3]), "r"(b0), "r"(b1));
}
// split two fp32 into packed fp16x2 hi and fp16x2 lo
__device__ __forceinline__ void split_pack(float x, float y,
                                           uint32_t& hi, uint32_t& lo) {
    __half hx = __float2half_rn(x);
    __half hy = __float2half_rn(y);
    __half2 h; h.x = hx; h.y = hy;
    hi = *(uint32_t*)&h;
    __half2 l;
    l.x = __float2half_rn(x - __half2float(hx));
    l.y = __float2half_rn(y - __half2float(hy));
    lo = *(uint32_t*)&l;
}
__device__ __forceinline__ uint32_t pack_h2(float x, float y) {
    __half2 h; h.x = __float2half_rn(x); h.y = __float2half_rn(y);
    return *(uint32_t*)&h;
}

// ---------------------------------------------------------------------------
// Split fp32 -> fp16 hi/lo (x input only).
// ---------------------------------------------------------------------------
__global__ void __launch_bounds__(256) split_act_kernel(const float* __restrict__ src)
{
    size_t i = ((size_t)blockIdx.x * 256 + threadIdx.x) * 4;
    float4 v = *(const float4*)(src + i);
    __half hx = __float2half_rn(v.x);
    __half hy = __float2half_rn(v.y);
    __half hz = __float2half_rn(v.z);
    __half hw = __float2half_rn(v.w);
    __half h2[4] = { hx, hy, hz, hw };
    *(uint2*)(g_Ahi + i) = *(uint2*)h2;
    __half l2[4] = {
        __float2half_rn(v.x - __half2float(hx)),
        __float2half_rn(v.y - __half2float(hy)),
        __float2half_rn(v.z - __half2float(hz)),
        __float2half_rn(v.w - __half2float(hw)) };
    *(uint2*)(g_Alo + i) = *(uint2*)l2;
}

// ---------------------------------------------------------------------------
// Transpose weights: W[k][N] -> Wh[row_off + n][k], single fp16
// ---------------------------------------------------------------------------
__global__ void __launch_bounds__(256) split_w_kernel(
    const float* __restrict__ W, int Ncols, int row_off)
{
    __shared__ float tile[32][33];
    const int tx = threadIdx.x, ty = threadIdx.y;
    const int n0 = blockIdx.x * 32;
    const int k0 = blockIdx.y * 32;
    #pragma unroll
    for (int j = ty; j < 32; j += 8)
        tile[j][tx] = W[(size_t)(k0 + j) * Ncols + n0 + tx];
    __syncthreads();
    #pragma unroll
    for (int j = ty; j < 32; j += 8) {
        size_t o = (size_t)(row_off + n0 + j) * C_ + k0 + tx;
        g_Wh[o] = __float2half_rn(tile[tx][j]);
    }
}

// ---------------------------------------------------------------------------
// mma.sync fp16 GEMM (asymmetric 2-term). Tile 128(M) x 96(N) x 32(K-chunk).
// 128 threads = 4 warps (2m x 2n), warp tile 64x48. 3-stage cp.async ring,
// one __syncthreads per chunk.
// mode 0: epilogue -> Q split hi/lo (scaled 0.125), K/V single fp16.
// mode 1: epilogue -> fp32 out + bias, columns guarded by n < Nlim.
// ---------------------------------------------------------------------------
#define GM 128
#define GN 96
#define KC 32
#define NCHUNK (C_ / KC)
#define A_ST (GM * 80)              // 10240
#define B_ST (GN * 80)              // 7680
#define STAGE (2 * A_ST + B_ST)     // 28160
#define GEMM_SMEM (3 * STAGE)       // 84480

extern __shared__ char gemm_smem[];

__global__ void __launch_bounds__(128, 2) gemm_f16_kernel(
    const __half* __restrict__ gB,
    const float* __restrict__ bias,
    float* __restrict__ Cout,
    int mode, int Nlim)
{
    const int tid = threadIdx.x;
    const int lane = tid & 31;
    const int wid = tid >> 5;
    const int wm = wid & 1;
    const int wn = wid >> 1;
    const int m0 = blockIdx.y * GM;
    const int n0 = blockIdx.x * GN;

    const uint32_t sbase = smem_u32(gemm_smem);

    float c[4][6][4];
    #pragma unroll
    for (int i = 0; i < 4; i++)
        #pragma unroll
        for (int j = 0; j < 6; j++)
            #pragma unroll
            for (int k = 0; k < 4; k++)
                c[i][j][k] = 0.f;

    auto issue = [&](int ch) {
        const int k0 = ch * KC;
        const uint32_t sb = sbase + (ch % 3) * STAGE;
        #pragma unroll
        for (int i = 0; i < 4; i++) {          // A hi/lo: 512 16B units each
            int idx = i * 128 + tid;
            int row = idx >> 2, cc = idx & 3;
            size_t go = ((size_t)(m0 + row) << 10) + k0 + cc * 8;
            uint32_t dof = row * 80 + cc * 16;
            cp_async16(sb + dof, g_Ahi + go);
            cp_async16(sb + A_ST + dof, g_Alo + go);
        }
        #pragma unroll
        for (int i = 0; i < 3; i++) {          // B: 384 16B units
            int idx = i * 128 + tid;
            int row = idx >> 2, cc = idx & 3;
            size_t go = ((size_t)(n0 + row) << 10) + k0 + cc * 8;
            uint32_t dof = row * 80 + cc * 16;
            cp_async16(sb + 2 * A_ST + dof, gB + go);
        }
        asm volatile("cp.async.commit_group;" ::: "memory");
    };

    issue(0);
    issue(1);

    const uint32_t a_lrow = (lane & 15);
    const uint32_t a_lk   = (lane >> 4) * 16;
    const uint32_t b_lrow = (lane & 7) | ((lane >> 1) & 8);
    const uint32_t b_lk   = ((lane >> 3) & 1) * 16;

    for (int ch = 0; ch < NCHUNK; ch++) {
        if (ch + 1 < NCHUNK)
            asm volatile("cp.async.wait_group 1;" ::: "memory");
        else
            asm volatile("cp.async.wait_group 0;" ::: "memory");
        __syncthreads();      // single barrier: stage ch visible + stage
                              // (ch-1) compute provably done before reuse
        if (ch + 2 < NCHUNK) issue(ch + 2);

        const uint32_t sA = sbase + (ch % 3) * STAGE;
        const uint32_t sB = sA + 2 * A_ST;

        #pragma unroll
        for (int ks = 0; ks < 2; ks++) {
            const uint32_t kb = ks * 32;
            uint32_t ahi[4][4], bb[3][4];
            #pragma unroll
            for (int mf = 0; mf < 4; mf++) {
                uint32_t ad = sA + (wm * 64 + mf * 16 + a_lrow) * 80 + kb + a_lk;
                ldsm_x4(ahi[mf][0], ahi[mf][1], ahi[mf][2], ahi[mf][3], ad);
            }
            #pragma unroll
            for (int np = 0; np < 3; np++) {
                uint32_t bd = sB + (wn * 48 + np * 16 + b_lrow) * 80 + kb + b_lk;
                ldsm_x4(bb[np][0], bb[np][1], bb[np][2], bb[np][3], bd);
            }
            #pragma unroll
            for (int mf = 0; mf < 4; mf++)
                #pragma unroll
                for (int np = 0; np < 3; np++) {
                    mma_f16(c[mf][2 * np],     ahi[mf], bb[np][0], bb[np][1]);
                    mma_f16(c[mf][2 * np + 1], ahi[mf], bb[np][2], bb[np][3]);
                }
            #pragma unroll
            for (int mf = 0; mf < 4; mf++) {
                uint32_t alo[4];
                uint32_t ad = sA + A_ST + (wm * 64 + mf * 16 + a_lrow) * 80 + kb + a_lk;
                ldsm_x4(alo[0], alo[1], alo[2], alo[3], ad);
                #pragma unroll
                for (int np = 0; np < 3; np++) {
                    mma_f16(c[mf][2 * np],     alo, bb[np][0], bb[np][1]);
                    mma_f16(c[mf][2 * np + 1], alo, bb[np][2], bb[np][3]);
                }
            }
        }
    }

    // ---- epilogue ----
    #pragma unroll
    for (int mf = 0; mf < 4; mf++) {
        const int mrow = m0 + wm * 64 + mf * 16 + (lane >> 2);
        #pragma unroll
        for (int nf = 0; nf < 6; nf++) {
            const int n = n0 + wn * 48 + nf * 8 + (lane & 3) * 2;
            if (mode == 0) {
                const float bx = bias[n], by = bias[n + 1];
                const int which = n >> 10;                 // 0=Q,1=K,2=V
                const int h = (n >> 6) & 15;
                const int d = n & 63;
                const int b = mrow >> 11, t = mrow & (T_ - 1);
                size_t base = (((size_t)(b * H_ + h) * T_ + t) << 6) + d;
                float v0 = c[mf][nf][0] + bx, v1 = c[mf][nf][1] + by;
                float v2 = c[mf][nf][2] + bx, v3 = c[mf][nf][3] + by;
                if (which == 0) {
                    uint32_t hi, lo;
                    split_pack(v0 * 0.125f, v1 * 0.125f, hi, lo);
                    *(uint32_t*)(g_Qhi + base) = hi;
                    *(uint32_t*)(g_Qlo + base) = lo;
                    split_pack(v2 * 0.125f, v3 * 0.125f, hi, lo);
                    *(uint32_t*)(g_Qhi + base + 512) = hi;   // (t+8) << 6
                    *(uint32_t*)(g_Qlo + base + 512) = lo;
                } else {
                    __half* dst = (which == 1) ? g_K : g_V;
                    *(uint32_t*)(dst + base)       = pack_h2(v0, v1);
                    *(uint32_t*)(dst + base + 512) = pack_h2(v2, v3);
                }
            } else if (n < Nlim) {
                const float bx = bias[n], by = bias[n + 1];
                float* p = Cout + (size_t)mrow * C_ + n;
                p[0] = c[mf][nf][0] + bx;
                p[1] = c[mf][nf][1] + by;
                p += (size_t)8 * C_;
                p[0] = c[mf][nf][2] + bx;
                p[1] = c[mf][nf][3] + by;
            }
        }
    }
}

// ---------------------------------------------------------------------------
// MMA flash attention, fp16 asymmetric 2-term. 128 q-rows x 64-key tiles,
// 8 warps, 3-stage cp.async ring (K and V single arrays per stage).
// ---------------------------------------------------------------------------
#define ROWB 144
#define ATT_ARR (64 * ROWB)          // 9216
#define ATT_STAGE (2 * ATT_ARR)      // 18432 (K + V)
#define ATT_SMEM (3 * ATT_STAGE)     // 55296

extern __shared__ char att_smem[];

__global__ void __launch_bounds__(256, 1) attn_mma_kernel()
{
    const uint32_t sb = smem_u32(att_smem);
    const int tid = threadIdx.x, lane = tid & 31, wid = tid >> 5;
    const int bh = blockIdx.y;
    const int qt = (int)(gridDim.x - 1) - (int)blockIdx.x;   // heavy-first
    const int qb = qt * 128;
    const int ntiles = 2 * qt + 2;

    const size_t bhoff = (size_t)bh * T_ * DK_;
    const __half* Kg = g_K + bhoff;
    const __half* Vg = g_V + bhoff;

    // stage Q hi/lo through smem -> registers
    {
        const __half* Qh = g_Qhi + bhoff + (size_t)qb * DK_;
        const __half* Ql = g_Qlo + bhoff + (size_t)qb * DK_;
        #pragma unroll
        for (int i = 0; i < 4; i++) {
            int idx = i * 256 + tid;          // 0..1023
            int row = idx >> 3, ch = idx & 7;
            cp_async16(sb + row * ROWB + ch * 16, Qh + row * 64 + ch * 8);
            cp_async16(sb + 128 * ROWB + row * ROWB + ch * 16, Ql + row * 64 + ch * 8);
        }
        asm volatile("cp.async.commit_group;" ::: "memory");
        asm volatile("cp.async.wait_group 0;" ::: "memory");
        __syncthreads();
    }
    uint32_t qhi[4][4], qlo[4][4];
    {
        const uint32_t ar = wid * 16 + (lane & 15);
        const uint32_t ac = (lane >> 4) * 16;
        #pragma unroll
        for (int j = 0; j < 4; j++) {
            ldsm_x4(qhi[j][0], qhi[j][1], qhi[j][2], qhi[j][3],
                    sb + ar * ROWB + j * 32 + ac);
            ldsm_x4(qlo[j][0], qlo[j][1], qlo[j][2], qlo[j][3],
                    sb + 128 * ROWB + ar * ROWB + j * 32 + ac);
        }
    }
    __syncthreads();

    auto issue_tile = [&](int kt, int st) {
        const size_t goff = (size_t)kt * 64 * 64;
        const uint32_t s0 = sb + st * ATT_STAGE;
        #pragma unroll
        for (int i = 0; i < 2; i++) {
            int idx = i * 256 + tid;           // 0..511
            int row = idx >> 3, ch = idx & 7;
            cp_async16(s0 + row * ROWB + ch * 16, Kg + goff + row * 64 + ch * 8);
            cp_async16(s0 + ATT_ARR + row * ROWB + ch * 16,
                       Vg + goff + row * 64 + ch * 8);
        }
        asm volatile("cp.async.commit_group;" ::: "memory");
    };

    float O[8][4];
    #pragma unroll
    for (int f = 0; f < 8; f++)
        #pragma unroll
        for (int j = 0; j < 4; j++)
            O[f][j] = 0.f;
    float m0v = -1e30f, m1v = -1e30f, l0v = 0.f, l1v = 0.f;

    issue_tile(0, 0);
    if (ntiles > 1) issue_tile(1, 1);

    const uint32_t b_lrow = (lane & 7) | ((lane >> 1) & 8);
    const uint32_t b_lk   = ((lane >> 3) & 1) * 16;
    const uint32_t v_row  = lane & 15;
    const uint32_t v_cb   = (lane >> 4) * 16;
    const int q0 = qb + wid * 16 + (lane >> 2);
    const int q1 = q0 + 8;

    for (int kt = 0; kt < ntiles; kt++) {
        if (kt + 1 < ntiles)
            asm volatile("cp.async.wait_group 1;" ::: "memory");
        else
            asm volatile("cp.async.wait_group 0;" ::: "memory");
        __syncthreads();
        if (kt + 2 < ntiles) issue_tile(kt + 2, (kt + 2) % 3);

        const uint32_t sK = sb + (kt % 3) * ATT_STAGE;
        const uint32_t sV = sK + ATT_ARR;

        float c[8][4];
        #pragma unroll
        for (int f = 0; f < 8; f++)
            #pragma unroll
            for (int j = 0; j < 4; j++)
                c[f][j] = 0.f;

        // S = Qhi*K + Qlo*K
        #pragma unroll
        for (int j = 0; j < 4; j++) {
            #pragma unroll
            for (int nb = 0; nb < 4; nb++) {
                uint32_t b0, b1, b2, b3;
                ldsm_x4(b0, b1, b2, b3,
                        sK + (nb * 16 + b_lrow) * ROWB + j * 32 + b_lk);
                mma_f16(c[2 * nb],     qhi[j], b0, b1);
                mma_f16(c[2 * nb + 1], qhi[j], b2, b3);
                mma_f16(c[2 * nb],     qlo[j], b0, b1);
                mma_f16(c[2 * nb + 1], qlo[j], b2, b3);
            }
        }

        if (kt >= 2 * qt) {
            const int kb = kt * 64;
            #pragma unroll
            for (int f = 0; f < 8; f++) {
                const int kc = kb + f * 8 + (lane & 3) * 2;
                if (kc     > q0) c[f][0] = -1e30f;
                if (kc + 1 > q0) c[f][1] = -1e30f;
                if (kc     > q1) c[f][2] = -1e30f;
                if (kc + 1 > q1) c[f][3] = -1e30f;
            }
        }

        float tm0 = -1e30f, tm1 = -1e30f;
        #pragma unroll
        for (int f = 0; f < 8; f++) {
            tm0 = fmaxf(tm0, fmaxf(c[f][0], c[f][1]));
            tm1 = fmaxf(tm1, fmaxf(c[f][2], c[f][3]));
        }
        tm0 = fmaxf(tm0, __shfl_xor_sync(0xffffffffu, tm0, 1));
        tm0 = fmaxf(tm0, __shfl_xor_sync(0xffffffffu, tm0, 2));
        tm1 = fmaxf(tm1, __shfl_xor_sync(0xffffffffu, tm1, 1));
        tm1 = fmaxf(tm1, __shfl_xor_sync(0xffffffffu, tm1, 2));
        const float mn0 = fmaxf(m0v, tm0), mn1 = fmaxf(m1v, tm1);
        const float cor0 = __expf(m0v - mn0), cor1 = __expf(m1v - mn1);
        m0v = mn0; m1v = mn1;
        float rs0 = 0.f, rs1 = 0.f;
        #pragma unroll
        for (int f = 0; f < 8; f++) {
            c[f][0] = __expf(c[f][0] - mn0);
            c[f][1] = __expf(c[f][1] - mn0);
            c[f][2] = __expf(c[f][2] - mn1);
            c[f][3] = __expf(c[f][3] - mn1);
            rs0 += c[f][0] + c[f][1];
            rs1 += c[f][2] + c[f][3];
        }
        rs0 += __shfl_xor_sync(0xffffffffu, rs0, 1);
        rs0 += __shfl_xor_sync(0xffffffffu, rs0, 2);
        rs1 += __shfl_xor_sync(0xffffffffu, rs1, 1);
        rs1 += __shfl_xor_sync(0xffffffffu, rs1, 2);
        l0v = l0v * cor0 + rs0;
        l1v = l1v * cor1 + rs1;
        #pragma unroll
        for (int f = 0; f < 8; f++) {
            O[f][0] *= cor0; O[f][1] *= cor0;
            O[f][2] *= cor1; O[f][3] *= cor1;
        }

        // P -> fp16 hi/lo A-frags
        uint32_t ph[4][4], pl[4][4];
        #pragma unroll
        for (int j = 0; j < 4; j++) {
            split_pack(c[2 * j][0],     c[2 * j][1],     ph[j][0], pl[j][0]);
            split_pack(c[2 * j][2],     c[2 * j][3],     ph[j][1], pl[j][1]);
            split_pack(c[2 * j + 1][0], c[2 * j + 1][1], ph[j][2], pl[j][2]);
            split_pack(c[2 * j + 1][2], c[2 * j + 1][3], ph[j][3], pl[j][3]);
        }

        // O += Phi*V + Plo*V   (V B-frags via ldmatrix.trans)
        #pragma unroll
        for (int j = 0; j < 4; j++) {
            #pragma unroll
            for (int db = 0; db < 4; db++) {
                uint32_t b0, b1, b2, b3;
                ldsm_x4t(b0, b1, b2, b3,
                         sV + (j * 16 + v_row) * ROWB + db * 32 + v_cb);
                mma_f16(O[2 * db],     ph[j], b0, b1);
                mma_f16(O[2 * db + 1], ph[j], b2, b3);
                mma_f16(O[2 * db],     pl[j], b0, b1);
                mma_f16(O[2 * db + 1], pl[j], b2, b3);
            }
        }
    }

    // epilogue: normalize, split fp16 hi/lo, write [b*T+t][h*64+d]
    const float inv0 = 1.f / l0v, inv1 = 1.f / l1v;
    const int b = bh >> 4, h = bh & 15;
    const int t0 = qb + wid * 16 + (lane >> 2);
    const size_t r0 = ((size_t)b * T_ + t0) * C_ + h * 64;
    const size_t r1 = r0 + (size_t)8 * C_;
    #pragma unroll
    for (int f = 0; f < 8; f++) {
        const int d = f * 8 + (lane & 3) * 2;
        uint32_t hi, lo;
        split_pack(O[f][0] * inv0, O[f][1] * inv0, hi, lo);
        *(uint32_t*)(g_Ahi + r0 + d) = hi;
        *(uint32_t*)(g_Alo + r0 + d) = lo;
        split_pack(O[f][2] * inv1, O[f][3] * inv1, hi, lo);
        *(uint32_t*)(g_Ahi + r1 + d) = hi;
        *(uint32_t*)(g_Alo + r1 + d) = lo;
    }
}

// ---------------------------------------------------------------------------
extern "C" void kernel_launch(void* const* d_in, const int* in_sizes, int n_in,
                              void* d_out, int out_size)
{
    const float* x      = (const float*)d_in[0];
    const float* W_qkv  = (const float*)d_in[1];
    const float* b_qkv  = (const float*)d_in[2];
    const float* W_proj = (const float*)d_in[3];
    const float* b_proj = (const float*)d_in[4];
    float* out = (float*)d_out;

    static int inited = 0;
    if (!inited) {
        cudaFuncSetAttribute(gemm_f16_kernel,
                             cudaFuncAttributeMaxDynamicSharedMemorySize, GEMM_SMEM);
        cudaFuncSetAttribute(attn_mma_kernel,
                             cudaFuncAttributeMaxDynamicSharedMemorySize, ATT_SMEM);
        inited = 1;
    }

    __half* Wh_d;
    cudaGetSymbolAddress((void**)&Wh_d, g_Wh);

    dim3 tb(32, 8);
    split_w_kernel<<<dim3(N_QKV / 32, C_ / 32), tb>>>(W_qkv, N_QKV, 0);
    split_w_kernel<<<dim3(C_ / 32, C_ / 32), tb>>>(W_proj, C_, N_QKV);
    split_act_kernel<<<(M_ * C_) / (256 * 4), 256>>>(x);

    // qkv: 32 n-tiles x 64 m-tiles = 2048 CTAs
    gemm_f16_kernel<<<dim3(N_QKV / GN, M_ / GM), 128, GEMM_SMEM>>>(
        Wh_d, b_qkv, nullptr, 0, N_QKV);

    attn_mma_kernel<<<dim3(T_ / 128, B_ * H_), 256, ATT_SMEM>>>();

    // proj: ceil(1024/96) = 11 n-tiles x 64 = 704 CTAs; ragged tile guarded.
    gemm_f16_kernel<<<dim3((C_ + GN - 1) / GN, M_ / GM), 128, GEMM_SMEM>>>(
        Wh_d + (size_t)N_QKV * C_, b_proj, out, 1, C_);
}

// round 8
// speedup vs baseline: 5.2207x; 1.1063x over previous
#include <cuda_runtime.h>
#include <cuda_fp16.h>
#include <cstdint>

// CausalSelfAttention: B=4, T=2048, C=1024, H=16, dk=64.
// R8: GEMM at 3 CTAs/SM (12 warps/SM): 2-stage cp.async ring (smem 56.3KB/CTA),
// __launch_bounds__(128,3). fp16 asymmetric 2-term split (R7, validated).

#define B_   4
#define T_   2048
#define C_   1024
#define H_   16
#define DK_  64
#define M_   (B_ * T_)        // 8192
#define N_QKV (3 * C_)        // 3072

#define QKV_ELEMS ((size_t)B_ * H_ * T_ * DK_)
__device__ __align__(16) __half g_Qhi[QKV_ELEMS];   // scaled by 0.125
__device__ __align__(16) __half g_Qlo[QKV_ELEMS];
__device__ __align__(16) __half g_K[QKV_ELEMS];     // single fp16
__device__ __align__(16) __half g_V[QKV_ELEMS];     // single fp16
__device__ __align__(16) __half g_Ahi[(size_t)M_ * C_];
__device__ __align__(16) __half g_Alo[(size_t)M_ * C_];
// +128 pad rows so the proj GEMM's ragged last N-tile loads stay in-bounds.
__device__ __align__(16) __half g_Wh[(size_t)(N_QKV + C_ + 128) * C_];

// ---------------------------------------------------------------------------
// helpers
// ---------------------------------------------------------------------------
__device__ __forceinline__ uint32_t smem_u32(const void* p) {
    uint32_t a;
    asm("{ .reg .u64 t; cvta.to.shared.u64 t, %1; cvt.u32.u64 %0, t; }"
        : "=r"(a) : "l"(p));
    return a;
}
__device__ __forceinline__ void cp_async16(uint32_t dst, const void* src) {
    asm volatile("cp.async.ca.shared.global [%0], [%1], 16;"
                 :: "r"(dst), "l"(__cvta_generic_to_global(src)) : "memory");
}
__device__ __forceinline__ void ldsm_x4(uint32_t& r0, uint32_t& r1,
                                        uint32_t& r2, uint32_t& r3, uint32_t a) {
    asm volatile("ldmatrix.sync.aligned.m8n8.x4.shared.b16 {%0,%1,%2,%3}, [%4];"
                 : "=r"(r0), "=r"(r1), "=r"(r2), "=r"(r3) : "r"(a));
}
__device__ __forceinline__ void ldsm_x4t(uint32_t& r0, uint32_t& r1,
                                         uint32_t& r2, uint32_t& r3, uint32_t a) {
    asm volatile("ldmatrix.sync.aligned.m8n8.x4.trans.shared.b16 {%0,%1,%2,%3}, [%4];"
                 : "=r"(r0), "=r"(r1), "=r"(r2), "=r"(r3) : "r"(a));
}
__device__ __forceinline__ void mma_f16(float* c, const uint32_t* a,
                                        uint32_t b0, uint32_t b1) {
    asm volatile(
        "mma.sync.aligned.m16n8k16.row.col.f32.f16.f16.f32 "
        "{%0,%1,%2,%3}, {%4,%5,%6,%7}, {%8,%9}, {%0,%1,%2,%3};"
        : "+f"(c[0]), "+f"(c[1]), "+f"(c[2]), "+f"(c[3])
        : "r"(a[0]), "r"(a[1]), "r"(a[2]), "r"(a[3]), "r"(b0), "r"(b1));
}
__device__ __forceinline__ void split_pack(float x, float y,
                                           uint32_t& hi, uint32_t& lo) {
    __half hx = __float2half_rn(x);
    __half hy = __float2half_rn(y);
    __half2 h; h.x = hx; h.y = hy;
    hi = *(uint32_t*)&h;
    __half2 l;
    l.x = __float2half_rn(x - __half2float(hx));
    l.y = __float2half_rn(y - __half2float(hy));
    lo = *(uint32_t*)&l;
}
__device__ __forceinline__ uint32_t pack_h2(float x, float y) {
    __half2 h; h.x = __float2half_rn(x); h.y = __float2half_rn(y);
    return *(uint32_t*)&h;
}

// ---------------------------------------------------------------------------
// Split fp32 -> fp16 hi/lo (x input only).
// ---------------------------------------------------------------------------
__global__ void __launch_bounds__(256) split_act_kernel(const float* __restrict__ src)
{
    size_t i = ((size_t)blockIdx.x * 256 + threadIdx.x) * 4;
    float4 v = *(const float4*)(src + i);
    __half hx = __float2half_rn(v.x);
    __half hy = __float2half_rn(v.y);
    __half hz = __float2half_rn(v.z);
    __half hw = __float2half_rn(v.w);
    __half h2[4] = { hx, hy, hz, hw };
    *(uint2*)(g_Ahi + i) = *(uint2*)h2;
    __half l2[4] = {
        __float2half_rn(v.x - __half2float(hx)),
        __float2half_rn(v.y - __half2float(hy)),
        __float2half_rn(v.z - __half2float(hz)),
        __float2half_rn(v.w - __half2float(hw)) };
    *(uint2*)(g_Alo + i) = *(uint2*)l2;
}

// ---------------------------------------------------------------------------
// Transpose weights: W[k][N] -> Wh[row_off + n][k], single fp16
// ---------------------------------------------------------------------------
__global__ void __launch_bounds__(256) split_w_kernel(
    const float* __restrict__ W, int Ncols, int row_off)
{
    __shared__ float tile[32][33];
    const int tx = threadIdx.x, ty = threadIdx.y;
    const int n0 = blockIdx.x * 32;
    const int k0 = blockIdx.y * 32;
    #pragma unroll
    for (int j = ty; j < 32; j += 8)
        tile[j][tx] = W[(size_t)(k0 + j) * Ncols + n0 + tx];
    __syncthreads();
    #pragma unroll
    for (int j = ty; j < 32; j += 8) {
        size_t o = (size_t)(row_off + n0 + j) * C_ + k0 + tx;
        g_Wh[o] = __float2half_rn(tile[tx][j]);
    }
}

// ---------------------------------------------------------------------------
// mma.sync fp16 GEMM (asymmetric 2-term). Tile 128(M) x 96(N) x 32(K-chunk).
// 128 threads = 4 warps (2m x 2n), warp tile 64x48.
// 2-stage cp.async ring, ONE __syncthreads per chunk, 3 CTAs/SM.
// ---------------------------------------------------------------------------
#define GM 128
#define GN 96
#define KC 32
#define NCHUNK (C_ / KC)
#define A_ST (GM * 80)              // 10240
#define B_ST (GN * 80)              // 7680
#define STAGE (2 * A_ST + B_ST)     // 28160
#define GEMM_SMEM (2 * STAGE)       // 56320

extern __shared__ char gemm_smem[];

__global__ void __launch_bounds__(128, 3) gemm_f16_kernel(
    const __half* __restrict__ gB,
    const float* __restrict__ bias,
    float* __restrict__ Cout,
    int mode, int Nlim)
{
    const int tid = threadIdx.x;
    const int lane = tid & 31;
    const int wid = tid >> 5;
    const int wm = wid & 1;
    const int wn = wid >> 1;
    const int m0 = blockIdx.y * GM;
    const int n0 = blockIdx.x * GN;

    const uint32_t sbase = smem_u32(gemm_smem);

    float c[4][6][4];
    #pragma unroll
    for (int i = 0; i < 4; i++)
        #pragma unroll
        for (int j = 0; j < 6; j++)
            #pragma unroll
            for (int k = 0; k < 4; k++)
                c[i][j][k] = 0.f;

    auto issue = [&](int ch) {
        const int k0 = ch * KC;
        const uint32_t sb = sbase + (ch & 1) * STAGE;
        #pragma unroll
        for (int i = 0; i < 4; i++) {          // A hi/lo
            int idx = i * 128 + tid;
            int row = idx >> 2, cc = idx & 3;
            size_t go = ((size_t)(m0 + row) << 10) + k0 + cc * 8;
            uint32_t dof = row * 80 + cc * 16;
            cp_async16(sb + dof, g_Ahi + go);
            cp_async16(sb + A_ST + dof, g_Alo + go);
        }
        #pragma unroll
        for (int i = 0; i < 3; i++) {          // B single fp16
            int idx = i * 128 + tid;
            int row = idx >> 2, cc = idx & 3;
            size_t go = ((size_t)(n0 + row) << 10) + k0 + cc * 8;
            uint32_t dof = row * 80 + cc * 16;
            cp_async16(sb + 2 * A_ST + dof, gB + go);
        }
        asm volatile("cp.async.commit_group;" ::: "memory");
    };

    issue(0);

    const uint32_t a_lrow = (lane & 15);
    const uint32_t a_lk   = (lane >> 4) * 16;
    const uint32_t b_lrow = (lane & 7) | ((lane >> 1) & 8);
    const uint32_t b_lk   = ((lane >> 3) & 1) * 16;

    for (int ch = 0; ch < NCHUNK; ch++) {
        asm volatile("cp.async.wait_group 0;" ::: "memory");
        __syncthreads();   // stage ch visible to all; stage ch-1 compute done
                           // by all warps -> its buffer ((ch+1)&1) is free.
        if (ch + 1 < NCHUNK) issue(ch + 1);

        const uint32_t sA = sbase + (ch & 1) * STAGE;
        const uint32_t sB = sA + 2 * A_ST;

        #pragma unroll
        for (int ks = 0; ks < 2; ks++) {
            const uint32_t kb = ks * 32;
            uint32_t ahi[4][4], bb[3][4];
            #pragma unroll
            for (int mf = 0; mf < 4; mf++) {
                uint32_t ad = sA + (wm * 64 + mf * 16 + a_lrow) * 80 + kb + a_lk;
                ldsm_x4(ahi[mf][0], ahi[mf][1], ahi[mf][2], ahi[mf][3], ad);
            }
            #pragma unroll
            for (int np = 0; np < 3; np++) {
                uint32_t bd = sB + (wn * 48 + np * 16 + b_lrow) * 80 + kb + b_lk;
                ldsm_x4(bb[np][0], bb[np][1], bb[np][2], bb[np][3], bd);
            }
            #pragma unroll
            for (int mf = 0; mf < 4; mf++)
                #pragma unroll
                for (int np = 0; np < 3; np++) {
                    mma_f16(c[mf][2 * np],     ahi[mf], bb[np][0], bb[np][1]);
                    mma_f16(c[mf][2 * np + 1], ahi[mf], bb[np][2], bb[np][3]);
                }
            #pragma unroll
            for (int mf = 0; mf < 4; mf++) {
                uint32_t alo[4];
                uint32_t ad = sA + A_ST + (wm * 64 + mf * 16 + a_lrow) * 80 + kb + a_lk;
                ldsm_x4(alo[0], alo[1], alo[2], alo[3], ad);
                #pragma unroll
                for (int np = 0; np < 3; np++) {
                    mma_f16(c[mf][2 * np],     alo, bb[np][0], bb[np][1]);
                    mma_f16(c[mf][2 * np + 1], alo, bb[np][2], bb[np][3]);
                }
            }
        }
    }

    // ---- epilogue ----
    #pragma unroll
    for (int mf = 0; mf < 4; mf++) {
        const int mrow = m0 + wm * 64 + mf * 16 + (lane >> 2);
        #pragma unroll
        for (int nf = 0; nf < 6; nf++) {
            const int n = n0 + wn * 48 + nf * 8 + (lane & 3) * 2;
            if (mode == 0) {
                const float bx = bias[n], by = bias[n + 1];
                const int which = n >> 10;                 // 0=Q,1=K,2=V
                const int h = (n >> 6) & 15;
                const int d = n & 63;
                const int b = mrow >> 11, t = mrow & (T_ - 1);
                size_t base = (((size_t)(b * H_ + h) * T_ + t) << 6) + d;
                float v0 = c[mf][nf][0] + bx, v1 = c[mf][nf][1] + by;
                float v2 = c[mf][nf][2] + bx, v3 = c[mf][nf][3] + by;
                if (which == 0) {
                    uint32_t hi, lo;
                    split_pack(v0 * 0.125f, v1 * 0.125f, hi, lo);
                    *(uint32_t*)(g_Qhi + base) = hi;
                    *(uint32_t*)(g_Qlo + base) = lo;
                    split_pack(v2 * 0.125f, v3 * 0.125f, hi, lo);
                    *(uint32_t*)(g_Qhi + base + 512) = hi;   // (t+8) << 6
                    *(uint32_t*)(g_Qlo + base + 512) = lo;
                } else {
                    __half* dst = (which == 1) ? g_K : g_V;
                    *(uint32_t*)(dst + base)       = pack_h2(v0, v1);
                    *(uint32_t*)(dst + base + 512) = pack_h2(v2, v3);
                }
            } else if (n < Nlim) {
                const float bx = bias[n], by = bias[n + 1];
                float* p = Cout + (size_t)mrow * C_ + n;
                p[0] = c[mf][nf][0] + bx;
                p[1] = c[mf][nf][1] + by;
                p += (size_t)8 * C_;
                p[0] = c[mf][nf][2] + bx;
                p[1] = c[mf][nf][3] + by;
            }
        }
    }
}

// ---------------------------------------------------------------------------
// MMA flash attention, fp16 asymmetric 2-term (R7, validated).
// ---------------------------------------------------------------------------
#define ROWB 144
#define ATT_ARR (64 * ROWB)          // 9216
#define ATT_STAGE (2 * ATT_ARR)      // 18432 (K + V)
#define ATT_SMEM (3 * ATT_STAGE)     // 55296

extern __shared__ char att_smem[];

__global__ void __launch_bounds__(256, 1) attn_mma_kernel()
{
    const uint32_t sb = smem_u32(att_smem);
    const int tid = threadIdx.x, lane = tid & 31, wid = tid >> 5;
    const int bh = blockIdx.y;
    const int qt = (int)(gridDim.x - 1) - (int)blockIdx.x;   // heavy-first
    const int qb = qt * 128;
    const int ntiles = 2 * qt + 2;

    const size_t bhoff = (size_t)bh * T_ * DK_;
    const __half* Kg = g_K + bhoff;
    const __half* Vg = g_V + bhoff;

    {
        const __half* Qh = g_Qhi + bhoff + (size_t)qb * DK_;
        const __half* Ql = g_Qlo + bhoff + (size_t)qb * DK_;
        #pragma unroll
        for (int i = 0; i < 4; i++) {
            int idx = i * 256 + tid;
            int row = idx >> 3, ch = idx & 7;
            cp_async16(sb + row * ROWB + ch * 16, Qh + row * 64 + ch * 8);
            cp_async16(sb + 128 * ROWB + row * ROWB + ch * 16, Ql + row * 64 + ch * 8);
        }
        asm volatile("cp.async.commit_group;" ::: "memory");
        asm volatile("cp.async.wait_group 0;" ::: "memory");
        __syncthreads();
    }
    uint32_t qhi[4][4], qlo[4][4];
    {
        const uint32_t ar = wid * 16 + (lane & 15);
        const uint32_t ac = (lane >> 4) * 16;
        #pragma unroll
        for (int j = 0; j < 4; j++) {
            ldsm_x4(qhi[j][0], qhi[j][1], qhi[j][2], qhi[j][3],
                    sb + ar * ROWB + j * 32 + ac);
            ldsm_x4(qlo[j][0], qlo[j][1], qlo[j][2], qlo[j][3],
                    sb + 128 * ROWB + ar * ROWB + j * 32 + ac);
        }
    }
    __syncthreads();

    auto issue_tile = [&](int kt, int st) {
        const size_t goff = (size_t)kt * 64 * 64;
        const uint32_t s0 = sb + st * ATT_STAGE;
        #pragma unroll
        for (int i = 0; i < 2; i++) {
            int idx = i * 256 + tid;
            int row = idx >> 3, ch = idx & 7;
            cp_async16(s0 + row * ROWB + ch * 16, Kg + goff + row * 64 + ch * 8);
            cp_async16(s0 + ATT_ARR + row * ROWB + ch * 16,
                       Vg + goff + row * 64 + ch * 8);
        }
        asm volatile("cp.async.commit_group;" ::: "memory");
    };

    float O[8][4];
    #pragma unroll
    for (int f = 0; f < 8; f++)
        #pragma unroll
        for (int j = 0; j < 4; j++)
            O[f][j] = 0.f;
    float m0v = -1e30f, m1v = -1e30f, l0v = 0.f, l1v = 0.f;

    issue_tile(0, 0);
    if (ntiles > 1) issue_tile(1, 1);

    const uint32_t b_lrow = (lane & 7) | ((lane >> 1) & 8);
    const uint32_t b_lk   = ((lane >> 3) & 1) * 16;
    const uint32_t v_row  = lane & 15;
    const uint32_t v_cb   = (lane >> 4) * 16;
    const int q0 = qb + wid * 16 + (lane >> 2);
    const int q1 = q0 + 8;

    for (int kt = 0; kt < ntiles; kt++) {
        if (kt + 1 < ntiles)
            asm volatile("cp.async.wait_group 1;" ::: "memory");
        else
            asm volatile("cp.async.wait_group 0;" ::: "memory");
        __syncthreads();
        if (kt + 2 < ntiles) issue_tile(kt + 2, (kt + 2) % 3);

        const uint32_t sK = sb + (kt % 3) * ATT_STAGE;
        const uint32_t sV = sK + ATT_ARR;

        float c[8][4];
        #pragma unroll
        for (int f = 0; f < 8; f++)
            #pragma unroll
            for (int j = 0; j < 4; j++)
                c[f][j] = 0.f;

        #pragma unroll
        for (int j = 0; j < 4; j++) {
            #pragma unroll
            for (int nb = 0; nb < 4; nb++) {
                uint32_t b0, b1, b2, b3;
                ldsm_x4(b0, b1, b2, b3,
                        sK + (nb * 16 + b_lrow) * ROWB + j * 32 + b_lk);
                mma_f16(c[2 * nb],     qhi[j], b0, b1);
                mma_f16(c[2 * nb + 1], qhi[j], b2, b3);
                mma_f16(c[2 * nb],     qlo[j], b0, b1);
                mma_f16(c[2 * nb + 1], qlo[j], b2, b3);
            }
        }

        if (kt >= 2 * qt) {
            const int kb = kt * 64;
            #pragma unroll
            for (int f = 0; f < 8; f++) {
                const int kc = kb + f * 8 + (lane & 3) * 2;
                if (kc     > q0) c[f][0] = -1e30f;
                if (kc + 1 > q0) c[f][1] = -1e30f;
                if (kc     > q1) c[f][2] = -1e30f;
                if (kc + 1 > q1) c[f][3] = -1e30f;
            }
        }

        float tm0 = -1e30f, tm1 = -1e30f;
        #pragma unroll
        for (int f = 0; f < 8; f++) {
            tm0 = fmaxf(tm0, fmaxf(c[f][0], c[f][1]));
            tm1 = fmaxf(tm1, fmaxf(c[f][2], c[f][3]));
        }
        tm0 = fmaxf(tm0, __shfl_xor_sync(0xffffffffu, tm0, 1));
        tm0 = fmaxf(tm0, __shfl_xor_sync(0xffffffffu, tm0, 2));
        tm1 = fmaxf(tm1, __shfl_xor_sync(0xffffffffu, tm1, 1));
        tm1 = fmaxf(tm1, __shfl_xor_sync(0xffffffffu, tm1, 2));
        const float mn0 = fmaxf(m0v, tm0), mn1 = fmaxf(m1v, tm1);
        const float cor0 = __expf(m0v - mn0), cor1 = __expf(m1v - mn1);
        m0v = mn0; m1v = mn1;
        float rs0 = 0.f, rs1 = 0.f;
        #pragma unroll
        for (int f = 0; f < 8; f++) {
            c[f][0] = __expf(c[f][0] - mn0);
            c[f][1] = __expf(c[f][1] - mn0);
            c[f][2] = __expf(c[f][2] - mn1);
            c[f][3] = __expf(c[f][3] - mn1);
            rs0 += c[f][0] + c[f][1];
            rs1 += c[f][2] + c[f][3];
        }
        rs0 += __shfl_xor_sync(0xffffffffu, rs0, 1);
        rs0 += __shfl_xor_sync(0xffffffffu, rs0, 2);
        rs1 += __shfl_xor_sync(0xffffffffu, rs1, 1);
        rs1 += __shfl_xor_sync(0xffffffffu, rs1, 2);
        l0v = l0v * cor0 + rs0;
        l1v = l1v * cor1 + rs1;
        #pragma unroll
        for (int f = 0; f < 8; f++) {
            O[f][0] *= cor0; O[f][1] *= cor0;
            O[f][2] *= cor1; O[f][3] *= cor1;
        }

        uint32_t ph[4][4], pl[4][4];
        #pragma unroll
        for (int j = 0; j < 4; j++) {
            split_pack(c[2 * j][0],     c[2 * j][1],     ph[j][0], pl[j][0]);
            split_pack(c[2 * j][2],     c[2 * j][3],     ph[j][1], pl[j][1]);
            split_pack(c[2 * j + 1][0], c[2 * j + 1][1], ph[j][2], pl[j][2]);
            split_pack(c[2 * j + 1][2], c[2 * j + 1][3], ph[j][3], pl[j][3]);
        }

        #pragma unroll
        for (int j = 0; j < 4; j++) {
            #pragma unroll
            for (int db = 0; db < 4; db++) {
                uint32_t b0, b1, b2, b3;
                ldsm_x4t(b0, b1, b2, b3,
                         sV + (j * 16 + v_row) * ROWB + db * 32 + v_cb);
                mma_f16(O[2 * db],     ph[j], b0, b1);
                mma_f16(O[2 * db + 1], ph[j], b2, b3);
                mma_f16(O[2 * db],     pl[j], b0, b1);
                mma_f16(O[2 * db + 1], pl[j], b2, b3);
            }
        }
    }

    const float inv0 = 1.f / l0v, inv1 = 1.f / l1v;
    const int b = bh >> 4, h = bh & 15;
    const int t0 = qb + wid * 16 + (lane >> 2);
    const size_t r0 = ((size_t)b * T_ + t0) * C_ + h * 64;
    const size_t r1 = r0 + (size_t)8 * C_;
    #pragma unroll
    for (int f = 0; f < 8; f++) {
        const int d = f * 8 + (lane & 3) * 2;
        uint32_t hi, lo;
        split_pack(O[f][0] * inv0, O[f][1] * inv0, hi, lo);
        *(uint32_t*)(g_Ahi + r0 + d) = hi;
        *(uint32_t*)(g_Alo + r0 + d) = lo;
        split_pack(O[f][2] * inv1, O[f][3] * inv1, hi, lo);
        *(uint32_t*)(g_Ahi + r1 + d) = hi;
        *(uint32_t*)(g_Alo + r1 + d) = lo;
    }
}

// ---------------------------------------------------------------------------
extern "C" void kernel_launch(void* const* d_in, const int* in_sizes, int n_in,
                              void* d_out, int out_size)
{
    const float* x      = (const float*)d_in[0];
    const float* W_qkv  = (const float*)d_in[1];
    const float* b_qkv  = (const float*)d_in[2];
    const float* W_proj = (const float*)d_in[3];
    const float* b_proj = (const float*)d_in[4];
    float* out = (float*)d_out;

    static int inited = 0;
    if (!inited) {
        cudaFuncSetAttribute(gemm_f16_kernel,
                             cudaFuncAttributeMaxDynamicSharedMemorySize, GEMM_SMEM);
        cudaFuncSetAttribute(attn_mma_kernel,
                             cudaFuncAttributeMaxDynamicSharedMemorySize, ATT_SMEM);
        inited = 1;
    }

    __half* Wh_d;
    cudaGetSymbolAddress((void**)&Wh_d, g_Wh);

    dim3 tb(32, 8);
    split_w_kernel<<<dim3(N_QKV / 32, C_ / 32), tb>>>(W_qkv, N_QKV, 0);
    split_w_kernel<<<dim3(C_ / 32, C_ / 32), tb>>>(W_proj, C_, N_QKV);
    split_act_kernel<<<(M_ * C_) / (256 * 4), 256>>>(x);

    gemm_f16_kernel<<<dim3(N_QKV / GN, M_ / GM), 128, GEMM_SMEM>>>(
        Wh_d, b_qkv, nullptr, 0, N_QKV);

    attn_mma_kernel<<<dim3(T_ / 128, B_ * H_), 256, ATT_SMEM>>>();

    gemm_f16_kernel<<<dim3((C_ + GN - 1) / GN, M_ / GM), 128, GEMM_SMEM>>>(
        Wh_d + (size_t)N_QKV * C_, b_proj, out, 1, C_);
}

// round 9
// speedup vs baseline: 5.4079x; 1.0359x over previous
#include <cuda_runtime.h>
#include <cuda_fp16.h>
#include <cstdint>

// CausalSelfAttention: B=4, T=2048, C=1024, H=16, dk=64.
// R9: attention re-tiled to 128-thread CTAs (64 q-rows), 3 CTAs/SM (the R8
// occupancy lever, proven on the GEMM). GEMMs unchanged from R8.

#define B_   4
#define T_   2048
#define C_   1024
#define H_   16
#define DK_  64
#define M_   (B_ * T_)        // 8192
#define N_QKV (3 * C_)        // 3072

#define QKV_ELEMS ((size_t)B_ * H_ * T_ * DK_)
__device__ __align__(16) __half g_Qhi[QKV_ELEMS];   // scaled by 0.125
__device__ __align__(16) __half g_Qlo[QKV_ELEMS];
__device__ __align__(16) __half g_K[QKV_ELEMS];     // single fp16
__device__ __align__(16) __half g_V[QKV_ELEMS];     // single fp16
__device__ __align__(16) __half g_Ahi[(size_t)M_ * C_];
__device__ __align__(16) __half g_Alo[(size_t)M_ * C_];
// +128 pad rows so the proj GEMM's ragged last N-tile loads stay in-bounds.
__device__ __align__(16) __half g_Wh[(size_t)(N_QKV + C_ + 128) * C_];

// ---------------------------------------------------------------------------
// helpers
// ---------------------------------------------------------------------------
__device__ __forceinline__ uint32_t smem_u32(const void* p) {
    uint32_t a;
    asm("{ .reg .u64 t; cvta.to.shared.u64 t, %1; cvt.u32.u64 %0, t; }"
        : "=r"(a) : "l"(p));
    return a;
}
__device__ __forceinline__ void cp_async16(uint32_t dst, const void* src) {
    asm volatile("cp.async.ca.shared.global [%0], [%1], 16;"
                 :: "r"(dst), "l"(__cvta_generic_to_global(src)) : "memory");
}
__device__ __forceinline__ void ldsm_x4(uint32_t& r0, uint32_t& r1,
                                        uint32_t& r2, uint32_t& r3, uint32_t a) {
    asm volatile("ldmatrix.sync.aligned.m8n8.x4.shared.b16 {%0,%1,%2,%3}, [%4];"
                 : "=r"(r0), "=r"(r1), "=r"(r2), "=r"(r3) : "r"(a));
}
__device__ __forceinline__ void ldsm_x4t(uint32_t& r0, uint32_t& r1,
                                         uint32_t& r2, uint32_t& r3, uint32_t a) {
    asm volatile("ldmatrix.sync.aligned.m8n8.x4.trans.shared.b16 {%0,%1,%2,%3}, [%4];"
                 : "=r"(r0), "=r"(r1), "=r"(r2), "=r"(r3) : "r"(a));
}
__device__ __forceinline__ void mma_f16(float* c, const uint32_t* a,
                                        uint32_t b0, uint32_t b1) {
    asm volatile(
        "mma.sync.aligned.m16n8k16.row.col.f32.f16.f16.f32 "
        "{%0,%1,%2,%3}, {%4,%5,%6,%7}, {%8,%9}, {%0,%1,%2,%3};"
        : "+f"(c[0]), "+f"(c[1]), "+f"(c[2]), "+f"(c[3])
        : "r"(a[0]), "r"(a[1]), "r"(a[2]), "r"(a[3]), "r"(b0), "r"(b1));
}
__device__ __forceinline__ void split_pack(float x, float y,
                                           uint32_t& hi, uint32_t& lo) {
    __half hx = __float2half_rn(x);
    __half hy = __float2half_rn(y);
    __half2 h; h.x = hx; h.y = hy;
    hi = *(uint32_t*)&h;
    __half2 l;
    l.x = __float2half_rn(x - __half2float(hx));
    l.y = __float2half_rn(y - __half2float(hy));
    lo = *(uint32_t*)&l;
}
__device__ __forceinline__ uint32_t pack_h2(float x, float y) {
    __half2 h; h.x = __float2half_rn(x); h.y = __float2half_rn(y);
    return *(uint32_t*)&h;
}

// ---------------------------------------------------------------------------
// Split fp32 -> fp16 hi/lo (x input only).
// ---------------------------------------------------------------------------
__global__ void __launch_bounds__(256) split_act_kernel(const float* __restrict__ src)
{
    size_t i = ((size_t)blockIdx.x * 256 + threadIdx.x) * 4;
    float4 v = *(const float4*)(src + i);
    __half hx = __float2half_rn(v.x);
    __half hy = __float2half_rn(v.y);
    __half hz = __float2half_rn(v.z);
    __half hw = __float2half_rn(v.w);
    __half h2[4] = { hx, hy, hz, hw };
    *(uint2*)(g_Ahi + i) = *(uint2*)h2;
    __half l2[4] = {
        __float2half_rn(v.x - __half2float(hx)),
        __float2half_rn(v.y - __half2float(hy)),
        __float2half_rn(v.z - __half2float(hz)),
        __float2half_rn(v.w - __half2float(hw)) };
    *(uint2*)(g_Alo + i) = *(uint2*)l2;
}

// ---------------------------------------------------------------------------
// Transpose weights: W[k][N] -> Wh[row_off + n][k], single fp16
// ---------------------------------------------------------------------------
__global__ void __launch_bounds__(256) split_w_kernel(
    const float* __restrict__ W, int Ncols, int row_off)
{
    __shared__ float tile[32][33];
    const int tx = threadIdx.x, ty = threadIdx.y;
    const int n0 = blockIdx.x * 32;
    const int k0 = blockIdx.y * 32;
    #pragma unroll
    for (int j = ty; j < 32; j += 8)
        tile[j][tx] = W[(size_t)(k0 + j) * Ncols + n0 + tx];
    __syncthreads();
    #pragma unroll
    for (int j = ty; j < 32; j += 8) {
        size_t o = (size_t)(row_off + n0 + j) * C_ + k0 + tx;
        g_Wh[o] = __float2half_rn(tile[tx][j]);
    }
}

// ---------------------------------------------------------------------------
// mma.sync fp16 GEMM (asymmetric 2-term), R8 config: tile 128x96x32,
// 4 warps, 2-stage ring, one barrier per chunk, 3 CTAs/SM.
// ---------------------------------------------------------------------------
#define GM 128
#define GN 96
#define KC 32
#define NCHUNK (C_ / KC)
#define A_ST (GM * 80)              // 10240
#define B_ST (GN * 80)              // 7680
#define STAGE (2 * A_ST + B_ST)     // 28160
#define GEMM_SMEM (2 * STAGE)       // 56320

extern __shared__ char gemm_smem[];

__global__ void __launch_bounds__(128, 3) gemm_f16_kernel(
    const __half* __restrict__ gB,
    const float* __restrict__ bias,
    float* __restrict__ Cout,
    int mode, int Nlim)
{
    const int tid = threadIdx.x;
    const int lane = tid & 31;
    const int wid = tid >> 5;
    const int wm = wid & 1;
    const int wn = wid >> 1;
    const int m0 = blockIdx.y * GM;
    const int n0 = blockIdx.x * GN;

    const uint32_t sbase = smem_u32(gemm_smem);

    float c[4][6][4];
    #pragma unroll
    for (int i = 0; i < 4; i++)
        #pragma unroll
        for (int j = 0; j < 6; j++)
            #pragma unroll
            for (int k = 0; k < 4; k++)
                c[i][j][k] = 0.f;

    auto issue = [&](int ch) {
        const int k0 = ch * KC;
        const uint32_t sb = sbase + (ch & 1) * STAGE;
        #pragma unroll
        for (int i = 0; i < 4; i++) {          // A hi/lo
            int idx = i * 128 + tid;
            int row = idx >> 2, cc = idx & 3;
            size_t go = ((size_t)(m0 + row) << 10) + k0 + cc * 8;
            uint32_t dof = row * 80 + cc * 16;
            cp_async16(sb + dof, g_Ahi + go);
            cp_async16(sb + A_ST + dof, g_Alo + go);
        }
        #pragma unroll
        for (int i = 0; i < 3; i++) {          // B single fp16
            int idx = i * 128 + tid;
            int row = idx >> 2, cc = idx & 3;
            size_t go = ((size_t)(n0 + row) << 10) + k0 + cc * 8;
            uint32_t dof = row * 80 + cc * 16;
            cp_async16(sb + 2 * A_ST + dof, gB + go);
        }
        asm volatile("cp.async.commit_group;" ::: "memory");
    };

    issue(0);

    const uint32_t a_lrow = (lane & 15);
    const uint32_t a_lk   = (lane >> 4) * 16;
    const uint32_t b_lrow = (lane & 7) | ((lane >> 1) & 8);
    const uint32_t b_lk   = ((lane >> 3) & 1) * 16;

    for (int ch = 0; ch < NCHUNK; ch++) {
        asm volatile("cp.async.wait_group 0;" ::: "memory");
        __syncthreads();
        if (ch + 1 < NCHUNK) issue(ch + 1);

        const uint32_t sA = sbase + (ch & 1) * STAGE;
        const uint32_t sB = sA + 2 * A_ST;

        #pragma unroll
        for (int ks = 0; ks < 2; ks++) {
            const uint32_t kb = ks * 32;
            uint32_t ahi[4][4], bb[3][4];
            #pragma unroll
            for (int mf = 0; mf < 4; mf++) {
                uint32_t ad = sA + (wm * 64 + mf * 16 + a_lrow) * 80 + kb + a_lk;
                ldsm_x4(ahi[mf][0], ahi[mf][1], ahi[mf][2], ahi[mf][3], ad);
            }
            #pragma unroll
            for (int np = 0; np < 3; np++) {
                uint32_t bd = sB + (wn * 48 + np * 16 + b_lrow) * 80 + kb + b_lk;
                ldsm_x4(bb[np][0], bb[np][1], bb[np][2], bb[np][3], bd);
            }
            #pragma unroll
            for (int mf = 0; mf < 4; mf++)
                #pragma unroll
                for (int np = 0; np < 3; np++) {
                    mma_f16(c[mf][2 * np],     ahi[mf], bb[np][0], bb[np][1]);
                    mma_f16(c[mf][2 * np + 1], ahi[mf], bb[np][2], bb[np][3]);
                }
            #pragma unroll
            for (int mf = 0; mf < 4; mf++) {
                uint32_t alo[4];
                uint32_t ad = sA + A_ST + (wm * 64 + mf * 16 + a_lrow) * 80 + kb + a_lk;
                ldsm_x4(alo[0], alo[1], alo[2], alo[3], ad);
                #pragma unroll
                for (int np = 0; np < 3; np++) {
                    mma_f16(c[mf][2 * np],     alo, bb[np][0], bb[np][1]);
                    mma_f16(c[mf][2 * np + 1], alo, bb[np][2], bb[np][3]);
                }
            }
        }
    }

    // ---- epilogue ----
    #pragma unroll
    for (int mf = 0; mf < 4; mf++) {
        const int mrow = m0 + wm * 64 + mf * 16 + (lane >> 2);
        #pragma unroll
        for (int nf = 0; nf < 6; nf++) {
            const int n = n0 + wn * 48 + nf * 8 + (lane & 3) * 2;
            if (mode == 0) {
                const float bx = bias[n], by = bias[n + 1];
                const int which = n >> 10;                 // 0=Q,1=K,2=V
                const int h = (n >> 6) & 15;
                const int d = n & 63;
                const int b = mrow >> 11, t = mrow & (T_ - 1);
                size_t base = (((size_t)(b * H_ + h) * T_ + t) << 6) + d;
                float v0 = c[mf][nf][0] + bx, v1 = c[mf][nf][1] + by;
                float v2 = c[mf][nf][2] + bx, v3 = c[mf][nf][3] + by;
                if (which == 0) {
                    uint32_t hi, lo;
                    split_pack(v0 * 0.125f, v1 * 0.125f, hi, lo);
                    *(uint32_t*)(g_Qhi + base) = hi;
                    *(uint32_t*)(g_Qlo + base) = lo;
                    split_pack(v2 * 0.125f, v3 * 0.125f, hi, lo);
                    *(uint32_t*)(g_Qhi + base + 512) = hi;   // (t+8) << 6
                    *(uint32_t*)(g_Qlo + base + 512) = lo;
                } else {
                    __half* dst = (which == 1) ? g_K : g_V;
                    *(uint32_t*)(dst + base)       = pack_h2(v0, v1);
                    *(uint32_t*)(dst + base + 512) = pack_h2(v2, v3);
                }
            } else if (n < Nlim) {
                const float bx = bias[n], by = bias[n + 1];
                float* p = Cout + (size_t)mrow * C_ + n;
                p[0] = c[mf][nf][0] + bx;
                p[1] = c[mf][nf][1] + by;
                p += (size_t)8 * C_;
                p[0] = c[mf][nf][2] + bx;
                p[1] = c[mf][nf][3] + by;
            }
        }
    }
}

// ---------------------------------------------------------------------------
// MMA flash attention, fp16 asymmetric 2-term. R9: 64 q-rows per CTA,
// 128 threads (4 warps x m16), 3 CTAs/SM, 3-stage K/V ring.
// ---------------------------------------------------------------------------
#define ROWB 144
#define ATT_ARR (64 * ROWB)          // 9216
#define ATT_STAGE (2 * ATT_ARR)      // 18432 (K + V)
#define ATT_SMEM (3 * ATT_STAGE)     // 55296

extern __shared__ char att_smem[];

__global__ void __launch_bounds__(128, 3) attn_mma_kernel()
{
    const uint32_t sb = smem_u32(att_smem);
    const int tid = threadIdx.x, lane = tid & 31, wid = tid >> 5;   // 4 warps
    const int bh = blockIdx.y;
    const int qt = (int)(gridDim.x - 1) - (int)blockIdx.x;   // heavy-first
    const int qb = qt * 64;
    const int ntiles = qt + 1;

    const size_t bhoff = (size_t)bh * T_ * DK_;
    const __half* Kg = g_K + bhoff;
    const __half* Vg = g_V + bhoff;

    // stage Q hi/lo (64 rows) through smem -> registers
    {
        const __half* Qh = g_Qhi + bhoff + (size_t)qb * DK_;
        const __half* Ql = g_Qlo + bhoff + (size_t)qb * DK_;
        #pragma unroll
        for (int i = 0; i < 4; i++) {
            int idx = i * 128 + tid;          // 0..511
            int row = idx >> 3, ch = idx & 7;
            cp_async16(sb + row * ROWB + ch * 16, Qh + row * 64 + ch * 8);
            cp_async16(sb + 64 * ROWB + row * ROWB + ch * 16, Ql + row * 64 + ch * 8);
        }
        asm volatile("cp.async.commit_group;" ::: "memory");
        asm volatile("cp.async.wait_group 0;" ::: "memory");
        __syncthreads();
    }
    uint32_t qhi[4][4], qlo[4][4];
    {
        const uint32_t ar = wid * 16 + (lane & 15);          // 0..63
        const uint32_t ac = (lane >> 4) * 16;
        #pragma unroll
        for (int j = 0; j < 4; j++) {
            ldsm_x4(qhi[j][0], qhi[j][1], qhi[j][2], qhi[j][3],
                    sb + ar * ROWB + j * 32 + ac);
            ldsm_x4(qlo[j][0], qlo[j][1], qlo[j][2], qlo[j][3],
                    sb + 64 * ROWB + ar * ROWB + j * 32 + ac);
        }
    }
    __syncthreads();

    auto issue_tile = [&](int kt, int st) {
        const size_t goff = (size_t)kt * 64 * 64;
        const uint32_t s0 = sb + st * ATT_STAGE;
        #pragma unroll
        for (int i = 0; i < 4; i++) {
            int idx = i * 128 + tid;           // 0..511
            int row = idx >> 3, ch = idx & 7;
            cp_async16(s0 + row * ROWB + ch * 16, Kg + goff + row * 64 + ch * 8);
            cp_async16(s0 + ATT_ARR + row * ROWB + ch * 16,
                       Vg + goff + row * 64 + ch * 8);
        }
        asm volatile("cp.async.commit_group;" ::: "memory");
    };

    float O[8][4];
    #pragma unroll
    for (int f = 0; f < 8; f++)
        #pragma unroll
        for (int j = 0; j < 4; j++)
            O[f][j] = 0.f;
    float m0v = -1e30f, m1v = -1e30f, l0v = 0.f, l1v = 0.f;

    issue_tile(0, 0);
    if (ntiles > 1) issue_tile(1, 1);

    const uint32_t b_lrow = (lane & 7) | ((lane >> 1) & 8);
    const uint32_t b_lk   = ((lane >> 3) & 1) * 16;
    const uint32_t v_row  = lane & 15;
    const uint32_t v_cb   = (lane >> 4) * 16;
    const int q0 = qb + wid * 16 + (lane >> 2);
    const int q1 = q0 + 8;

    for (int kt = 0; kt < ntiles; kt++) {
        if (kt + 1 < ntiles)
            asm volatile("cp.async.wait_group 1;" ::: "memory");
        else
            asm volatile("cp.async.wait_group 0;" ::: "memory");
        __syncthreads();
        if (kt + 2 < ntiles) issue_tile(kt + 2, (kt + 2) % 3);

        const uint32_t sK = sb + (kt % 3) * ATT_STAGE;
        const uint32_t sV = sK + ATT_ARR;

        float c[8][4];
        #pragma unroll
        for (int f = 0; f < 8; f++)
            #pragma unroll
            for (int j = 0; j < 4; j++)
                c[f][j] = 0.f;

        // S = Qhi*K + Qlo*K
        #pragma unroll
        for (int j = 0; j < 4; j++) {
            #pragma unroll
            for (int nb = 0; nb < 4; nb++) {
                uint32_t b0, b1, b2, b3;
                ldsm_x4(b0, b1, b2, b3,
                        sK + (nb * 16 + b_lrow) * ROWB + j * 32 + b_lk);
                mma_f16(c[2 * nb],     qhi[j], b0, b1);
                mma_f16(c[2 * nb + 1], qhi[j], b2, b3);
                mma_f16(c[2 * nb],     qlo[j], b0, b1);
                mma_f16(c[2 * nb + 1], qlo[j], b2, b3);
            }
        }

        // diagonal mask: only the last tile (kt == qt) crosses the diagonal
        if (kt == qt) {
            const int kb = kt * 64;
            #pragma unroll
            for (int f = 0; f < 8; f++) {
                const int kc = kb + f * 8 + (lane & 3) * 2;
                if (kc     > q0) c[f][0] = -1e30f;
                if (kc + 1 > q0) c[f][1] = -1e30f;
                if (kc     > q1) c[f][2] = -1e30f;
                if (kc + 1 > q1) c[f][3] = -1e30f;
            }
        }

        float tm0 = -1e30f, tm1 = -1e30f;
        #pragma unroll
        for (int f = 0; f < 8; f++) {
            tm0 = fmaxf(tm0, fmaxf(c[f][0], c[f][1]));
            tm1 = fmaxf(tm1, fmaxf(c[f][2], c[f][3]));
        }
        tm0 = fmaxf(tm0, __shfl_xor_sync(0xffffffffu, tm0, 1));
        tm0 = fmaxf(tm0, __shfl_xor_sync(0xffffffffu, tm0, 2));
        tm1 = fmaxf(tm1, __shfl_xor_sync(0xffffffffu, tm1, 1));
        tm1 = fmaxf(tm1, __shfl_xor_sync(0xffffffffu, tm1, 2));
        const float mn0 = fmaxf(m0v, tm0), mn1 = fmaxf(m1v, tm1);
        const float cor0 = __expf(m0v - mn0), cor1 = __expf(m1v - mn1);
        m0v = mn0; m1v = mn1;
        float rs0 = 0.f, rs1 = 0.f;
        #pragma unroll
        for (int f = 0; f < 8; f++) {
            c[f][0] = __expf(c[f][0] - mn0);
            c[f][1] = __expf(c[f][1] - mn0);
            c[f][2] = __expf(c[f][2] - mn1);
            c[f][3] = __expf(c[f][3] - mn1);
            rs0 += c[f][0] + c[f][1];
            rs1 += c[f][2] + c[f][3];
        }
        rs0 += __shfl_xor_sync(0xffffffffu, rs0, 1);
        rs0 += __shfl_xor_sync(0xffffffffu, rs0, 2);
        rs1 += __shfl_xor_sync(0xffffffffu, rs1, 1);
        rs1 += __shfl_xor_sync(0xffffffffu, rs1, 2);
        l0v = l0v * cor0 + rs0;
        l1v = l1v * cor1 + rs1;
        #pragma unroll
        for (int f = 0; f < 8; f++) {
            O[f][0] *= cor0; O[f][1] *= cor0;
            O[f][2] *= cor1; O[f][3] *= cor1;
        }

        // P -> fp16 hi/lo A-frags
        uint32_t ph[4][4], pl[4][4];
        #pragma unroll
        for (int j = 0; j < 4; j++) {
            split_pack(c[2 * j][0],     c[2 * j][1],     ph[j][0], pl[j][0]);
            split_pack(c[2 * j][2],     c[2 * j][3],     ph[j][1], pl[j][1]);
            split_pack(c[2 * j + 1][0], c[2 * j + 1][1], ph[j][2], pl[j][2]);
            split_pack(c[2 * j + 1][2], c[2 * j + 1][3], ph[j][3], pl[j][3]);
        }

        // O += Phi*V + Plo*V
        #pragma unroll
        for (int j = 0; j < 4; j++) {
            #pragma unroll
            for (int db = 0; db < 4; db++) {
                uint32_t b0, b1, b2, b3;
                ldsm_x4t(b0, b1, b2, b3,
                         sV + (j * 16 + v_row) * ROWB + db * 32 + v_cb);
                mma_f16(O[2 * db],     ph[j], b0, b1);
                mma_f16(O[2 * db + 1], ph[j], b2, b3);
                mma_f16(O[2 * db],     pl[j], b0, b1);
                mma_f16(O[2 * db + 1], pl[j], b2, b3);
            }
        }
    }

    // epilogue: normalize, split fp16 hi/lo, write [b*T+t][h*64+d]
    const float inv0 = 1.f / l0v, inv1 = 1.f / l1v;
    const int b = bh >> 4, h = bh & 15;
    const int t0 = qb + wid * 16 + (lane >> 2);
    const size_t r0 = ((size_t)b * T_ + t0) * C_ + h * 64;
    const size_t r1 = r0 + (size_t)8 * C_;
    #pragma unroll
    for (int f = 0; f < 8; f++) {
        const int d = f * 8 + (lane & 3) * 2;
        uint32_t hi, lo;
        split_pack(O[f][0] * inv0, O[f][1] * inv0, hi, lo);
        *(uint32_t*)(g_Ahi + r0 + d) = hi;
        *(uint32_t*)(g_Alo + r0 + d) = lo;
        split_pack(O[f][2] * inv1, O[f][3] * inv1, hi, lo);
        *(uint32_t*)(g_Ahi + r1 + d) = hi;
        *(uint32_t*)(g_Alo + r1 + d) = lo;
    }
}

// ---------------------------------------------------------------------------
extern "C" void kernel_launch(void* const* d_in, const int* in_sizes, int n_in,
                              void* d_out, int out_size)
{
    const float* x      = (const float*)d_in[0];
    const float* W_qkv  = (const float*)d_in[1];
    const float* b_qkv  = (const float*)d_in[2];
    const float* W_proj = (const float*)d_in[3];
    const float* b_proj = (const float*)d_in[4];
    float* out = (float*)d_out;

    static int inited = 0;
    if (!inited) {
        cudaFuncSetAttribute(gemm_f16_kernel,
                             cudaFuncAttributeMaxDynamicSharedMemorySize, GEMM_SMEM);
        cudaFuncSetAttribute(attn_mma_kernel,
                             cudaFuncAttributeMaxDynamicSharedMemorySize, ATT_SMEM);
        inited = 1;
    }

    __half* Wh_d;
    cudaGetSymbolAddress((void**)&Wh_d, g_Wh);

    dim3 tb(32, 8);
    split_w_kernel<<<dim3(N_QKV / 32, C_ / 32), tb>>>(W_qkv, N_QKV, 0);
    split_w_kernel<<<dim3(C_ / 32, C_ / 32), tb>>>(W_proj, C_, N_QKV);
    split_act_kernel<<<(M_ * C_) / (256 * 4), 256>>>(x);

    gemm_f16_kernel<<<dim3(N_QKV / GN, M_ / GM), 128, GEMM_SMEM>>>(
        Wh_d, b_qkv, nullptr, 0, N_QKV);

    // 32 q-tiles x 64 bh = 2048 CTAs, 128 threads, 3 CTAs/SM
    attn_mma_kernel<<<dim3(T_ / 64, B_ * H_), 128, ATT_SMEM>>>();

    gemm_f16_kernel<<<dim3((C_ + GN - 1) / GN, M_ / GM), 128, GEMM_SMEM>>>(
        Wh_d + (size_t)N_QKV * C_, b_proj, out, 1, C_);
}

// round 10
// speedup vs baseline: 5.9891x; 1.1075x over previous
#include <cuda_runtime.h>
#include <cuda_fp16.h>
#include <cstdint>

// CausalSelfAttention: B=4, T=2048, C=1024, H=16, dk=64.
// R10: softmax restructure in attention — log2-domain scores (log2e folded
// into Q scale), P computed via cvt.rn.f16x2 + ex2.approx.f16x2 (half the
// SFU ops, zero repack), PV lo-term dropped (l normalizes with the same
// fp16 P weights), row-sum l via constant all-ones MMA (no sum shfls).

#define B_   4
#define T_   2048
#define C_   1024
#define H_   16
#define DK_  64
#define M_   (B_ * T_)        // 8192
#define N_QKV (3 * C_)        // 3072

#define QKV_ELEMS ((size_t)B_ * H_ * T_ * DK_)
__device__ __align__(16) __half g_Qhi[QKV_ELEMS];   // scaled by 0.125*log2e
__device__ __align__(16) __half g_Qlo[QKV_ELEMS];
__device__ __align__(16) __half g_K[QKV_ELEMS];     // single fp16
__device__ __align__(16) __half g_V[QKV_ELEMS];     // single fp16
__device__ __align__(16) __half g_Ahi[(size_t)M_ * C_];
__device__ __align__(16) __half g_Alo[(size_t)M_ * C_];
// +128 pad rows so the proj GEMM's ragged last N-tile loads stay in-bounds.
__device__ __align__(16) __half g_Wh[(size_t)(N_QKV + C_ + 128) * C_];

// ---------------------------------------------------------------------------
// helpers
// ---------------------------------------------------------------------------
__device__ __forceinline__ uint32_t smem_u32(const void* p) {
    uint32_t a;
    asm("{ .reg .u64 t; cvta.to.shared.u64 t, %1; cvt.u32.u64 %0, t; }"
        : "=r"(a) : "l"(p));
    return a;
}
__device__ __forceinline__ void cp_async16(uint32_t dst, const void* src) {
    asm volatile("cp.async.ca.shared.global [%0], [%1], 16;"
                 :: "r"(dst), "l"(__cvta_generic_to_global(src)) : "memory");
}
__device__ __forceinline__ void ldsm_x4(uint32_t& r0, uint32_t& r1,
                                        uint32_t& r2, uint32_t& r3, uint32_t a) {
    asm volatile("ldmatrix.sync.aligned.m8n8.x4.shared.b16 {%0,%1,%2,%3}, [%4];"
                 : "=r"(r0), "=r"(r1), "=r"(r2), "=r"(r3) : "r"(a));
}
__device__ __forceinline__ void ldsm_x4t(uint32_t& r0, uint32_t& r1,
                                         uint32_t& r2, uint32_t& r3, uint32_t a) {
    asm volatile("ldmatrix.sync.aligned.m8n8.x4.trans.shared.b16 {%0,%1,%2,%3}, [%4];"
                 : "=r"(r0), "=r"(r1), "=r"(r2), "=r"(r3) : "r"(a));
}
__device__ __forceinline__ void mma_f16(float* c, const uint32_t* a,
                                        uint32_t b0, uint32_t b1) {
    asm volatile(
        "mma.sync.aligned.m16n8k16.row.col.f32.f16.f16.f32 "
        "{%0,%1,%2,%3}, {%4,%5,%6,%7}, {%8,%9}, {%0,%1,%2,%3};"
        : "+f"(c[0]), "+f"(c[1]), "+f"(c[2]), "+f"(c[3])
        : "r"(a[0]), "r"(a[1]), "r"(a[2]), "r"(a[3]), "r"(b0), "r"(b1));
}
__device__ __forceinline__ void split_pack(float x, float y,
                                           uint32_t& hi, uint32_t& lo) {
    __half hx = __float2half_rn(x);
    __half hy = __float2half_rn(y);
    __half2 h; h.x = hx; h.y = hy;
    hi = *(uint32_t*)&h;
    __half2 l;
    l.x = __float2half_rn(x - __half2float(hx));
    l.y = __float2half_rn(y - __half2float(hy));
    lo = *(uint32_t*)&l;
}
__device__ __forceinline__ uint32_t pack_h2(float x, float y) {
    __half2 h; h.x = __float2half_rn(x); h.y = __float2half_rn(y);
    return *(uint32_t*)&h;
}
// p = 2^x, 2^y packed to fp16x2 (x -> element 0).
__device__ __forceinline__ uint32_t ex2_f16x2(float x, float y) {
    uint32_t d;
    asm("{ .reg .b32 t;\n\t"
        "cvt.rn.f16x2.f32 t, %2, %1;\n\t"      // t = {hi=y, lo=x}
        "ex2.approx.f16x2 %0, t; }"
        : "=r"(d) : "f"(x), "f"(y));
    return d;
}
__device__ __forceinline__ float ex2_f32(float x) {
    float d;
    asm("ex2.approx.f32 %0, %1;" : "=f"(d) : "f"(x));
    return d;
}

// ---------------------------------------------------------------------------
// Split fp32 -> fp16 hi/lo (x input only).
// ---------------------------------------------------------------------------
__global__ void __launch_bounds__(256) split_act_kernel(const float* __restrict__ src)
{
    size_t i = ((size_t)blockIdx.x * 256 + threadIdx.x) * 4;
    float4 v = *(const float4*)(src + i);
    __half hx = __float2half_rn(v.x);
    __half hy = __float2half_rn(v.y);
    __half hz = __float2half_rn(v.z);
    __half hw = __float2half_rn(v.w);
    __half h2[4] = { hx, hy, hz, hw };
    *(uint2*)(g_Ahi + i) = *(uint2*)h2;
    __half l2[4] = {
        __float2half_rn(v.x - __half2float(hx)),
        __float2half_rn(v.y - __half2float(hy)),
        __float2half_rn(v.z - __half2float(hz)),
        __float2half_rn(v.w - __half2float(hw)) };
    *(uint2*)(g_Alo + i) = *(uint2*)l2;
}

// ---------------------------------------------------------------------------
// Transpose weights: W[k][N] -> Wh[row_off + n][k], single fp16
// ---------------------------------------------------------------------------
__global__ void __launch_bounds__(256) split_w_kernel(
    const float* __restrict__ W, int Ncols, int row_off)
{
    __shared__ float tile[32][33];
    const int tx = threadIdx.x, ty = threadIdx.y;
    const int n0 = blockIdx.x * 32;
    const int k0 = blockIdx.y * 32;
    #pragma unroll
    for (int j = ty; j < 32; j += 8)
        tile[j][tx] = W[(size_t)(k0 + j) * Ncols + n0 + tx];
    __syncthreads();
    #pragma unroll
    for (int j = ty; j < 32; j += 8) {
        size_t o = (size_t)(row_off + n0 + j) * C_ + k0 + tx;
        g_Wh[o] = __float2half_rn(tile[tx][j]);
    }
}

// ---------------------------------------------------------------------------
// mma.sync fp16 GEMM (asymmetric 2-term), R8 config: tile 128x96x32,
// 4 warps, 2-stage ring, one barrier per chunk, 3 CTAs/SM.
// ---------------------------------------------------------------------------
#define GM 128
#define GN 96
#define KC 32
#define NCHUNK (C_ / KC)
#define A_ST (GM * 80)              // 10240
#define B_ST (GN * 80)              // 7680
#define STAGE (2 * A_ST + B_ST)     // 28160
#define GEMM_SMEM (2 * STAGE)       // 56320

// Q pre-scale: 1/sqrt(64) * log2(e)  -> scores arrive in log2 domain
#define QSCALE 0.18033688011112042f

extern __shared__ char gemm_smem[];

__global__ void __launch_bounds__(128, 3) gemm_f16_kernel(
    const __half* __restrict__ gB,
    const float* __restrict__ bias,
    float* __restrict__ Cout,
    int mode, int Nlim)
{
    const int tid = threadIdx.x;
    const int lane = tid & 31;
    const int wid = tid >> 5;
    const int wm = wid & 1;
    const int wn = wid >> 1;
    const int m0 = blockIdx.y * GM;
    const int n0 = blockIdx.x * GN;

    const uint32_t sbase = smem_u32(gemm_smem);

    float c[4][6][4];
    #pragma unroll
    for (int i = 0; i < 4; i++)
        #pragma unroll
        for (int j = 0; j < 6; j++)
            #pragma unroll
            for (int k = 0; k < 4; k++)
                c[i][j][k] = 0.f;

    auto issue = [&](int ch) {
        const int k0 = ch * KC;
        const uint32_t sb = sbase + (ch & 1) * STAGE;
        #pragma unroll
        for (int i = 0; i < 4; i++) {          // A hi/lo
            int idx = i * 128 + tid;
            int row = idx >> 2, cc = idx & 3;
            size_t go = ((size_t)(m0 + row) << 10) + k0 + cc * 8;
            uint32_t dof = row * 80 + cc * 16;
            cp_async16(sb + dof, g_Ahi + go);
            cp_async16(sb + A_ST + dof, g_Alo + go);
        }
        #pragma unroll
        for (int i = 0; i < 3; i++) {          // B single fp16
            int idx = i * 128 + tid;
            int row = idx >> 2, cc = idx & 3;
            size_t go = ((size_t)(n0 + row) << 10) + k0 + cc * 8;
            uint32_t dof = row * 80 + cc * 16;
            cp_async16(sb + 2 * A_ST + dof, gB + go);
        }
        asm volatile("cp.async.commit_group;" ::: "memory");
    };

    issue(0);

    const uint32_t a_lrow = (lane & 15);
    const uint32_t a_lk   = (lane >> 4) * 16;
    const uint32_t b_lrow = (lane & 7) | ((lane >> 1) & 8);
    const uint32_t b_lk   = ((lane >> 3) & 1) * 16;

    for (int ch = 0; ch < NCHUNK; ch++) {
        asm volatile("cp.async.wait_group 0;" ::: "memory");
        __syncthreads();
        if (ch + 1 < NCHUNK) issue(ch + 1);

        const uint32_t sA = sbase + (ch & 1) * STAGE;
        const uint32_t sB = sA + 2 * A_ST;

        #pragma unroll
        for (int ks = 0; ks < 2; ks++) {
            const uint32_t kb = ks * 32;
            uint32_t ahi[4][4], bb[3][4];
            #pragma unroll
            for (int mf = 0; mf < 4; mf++) {
                uint32_t ad = sA + (wm * 64 + mf * 16 + a_lrow) * 80 + kb + a_lk;
                ldsm_x4(ahi[mf][0], ahi[mf][1], ahi[mf][2], ahi[mf][3], ad);
            }
            #pragma unroll
            for (int np = 0; np < 3; np++) {
                uint32_t bd = sB + (wn * 48 + np * 16 + b_lrow) * 80 + kb + b_lk;
                ldsm_x4(bb[np][0], bb[np][1], bb[np][2], bb[np][3], bd);
            }
            #pragma unroll
            for (int mf = 0; mf < 4; mf++)
                #pragma unroll
                for (int np = 0; np < 3; np++) {
                    mma_f16(c[mf][2 * np],     ahi[mf], bb[np][0], bb[np][1]);
                    mma_f16(c[mf][2 * np + 1], ahi[mf], bb[np][2], bb[np][3]);
                }
            #pragma unroll
            for (int mf = 0; mf < 4; mf++) {
                uint32_t alo[4];
                uint32_t ad = sA + A_ST + (wm * 64 + mf * 16 + a_lrow) * 80 + kb + a_lk;
                ldsm_x4(alo[0], alo[1], alo[2], alo[3], ad);
                #pragma unroll
                for (int np = 0; np < 3; np++) {
                    mma_f16(c[mf][2 * np],     alo, bb[np][0], bb[np][1]);
                    mma_f16(c[mf][2 * np + 1], alo, bb[np][2], bb[np][3]);
                }
            }
        }
    }

    // ---- epilogue ----
    #pragma unroll
    for (int mf = 0; mf < 4; mf++) {
        const int mrow = m0 + wm * 64 + mf * 16 + (lane >> 2);
        #pragma unroll
        for (int nf = 0; nf < 6; nf++) {
            const int n = n0 + wn * 48 + nf * 8 + (lane & 3) * 2;
            if (mode == 0) {
                const float bx = bias[n], by = bias[n + 1];
                const int which = n >> 10;                 // 0=Q,1=K,2=V
                const int h = (n >> 6) & 15;
                const int d = n & 63;
                const int b = mrow >> 11, t = mrow & (T_ - 1);
                size_t base = (((size_t)(b * H_ + h) * T_ + t) << 6) + d;
                float v0 = c[mf][nf][0] + bx, v1 = c[mf][nf][1] + by;
                float v2 = c[mf][nf][2] + bx, v3 = c[mf][nf][3] + by;
                if (which == 0) {
                    uint32_t hi, lo;
                    split_pack(v0 * QSCALE, v1 * QSCALE, hi, lo);
                    *(uint32_t*)(g_Qhi + base) = hi;
                    *(uint32_t*)(g_Qlo + base) = lo;
                    split_pack(v2 * QSCALE, v3 * QSCALE, hi, lo);
                    *(uint32_t*)(g_Qhi + base + 512) = hi;   // (t+8) << 6
                    *(uint32_t*)(g_Qlo + base + 512) = lo;
                } else {
                    __half* dst = (which == 1) ? g_K : g_V;
                    *(uint32_t*)(dst + base)       = pack_h2(v0, v1);
                    *(uint32_t*)(dst + base + 512) = pack_h2(v2, v3);
                }
            } else if (n < Nlim) {
                const float bx = bias[n], by = bias[n + 1];
                float* p = Cout + (size_t)mrow * C_ + n;
                p[0] = c[mf][nf][0] + bx;
                p[1] = c[mf][nf][1] + by;
                p += (size_t)8 * C_;
                p[0] = c[mf][nf][2] + bx;
                p[1] = c[mf][nf][3] + by;
            }
        }
    }
}

// ---------------------------------------------------------------------------
// MMA flash attention (fp16), log2-domain softmax, ex2.f16x2 P, ones-MMA l.
// 64 q-rows per CTA, 128 threads (4 warps), 3 CTAs/SM, 3-stage K/V ring.
// ---------------------------------------------------------------------------
#define ROWB 144
#define ATT_ARR (64 * ROWB)          // 9216
#define ATT_STAGE (2 * ATT_ARR)      // 18432 (K + V)
#define ATT_SMEM (3 * ATT_STAGE)     // 55296
#define ONES2 0x3C003C00u            // fp16x2 {1.0, 1.0}

extern __shared__ char att_smem[];

__global__ void __launch_bounds__(128, 3) attn_mma_kernel()
{
    const uint32_t sb = smem_u32(att_smem);
    const int tid = threadIdx.x, lane = tid & 31, wid = tid >> 5;   // 4 warps
    const int bh = blockIdx.y;
    const int qt = (int)(gridDim.x - 1) - (int)blockIdx.x;   // heavy-first
    const int qb = qt * 64;
    const int ntiles = qt + 1;

    const size_t bhoff = (size_t)bh * T_ * DK_;
    const __half* Kg = g_K + bhoff;
    const __half* Vg = g_V + bhoff;

    // stage Q hi/lo (64 rows) through smem -> registers
    {
        const __half* Qh = g_Qhi + bhoff + (size_t)qb * DK_;
        const __half* Ql = g_Qlo + bhoff + (size_t)qb * DK_;
        #pragma unroll
        for (int i = 0; i < 4; i++) {
            int idx = i * 128 + tid;          // 0..511
            int row = idx >> 3, ch = idx & 7;
            cp_async16(sb + row * ROWB + ch * 16, Qh + row * 64 + ch * 8);
            cp_async16(sb + 64 * ROWB + row * ROWB + ch * 16, Ql + row * 64 + ch * 8);
        }
        asm volatile("cp.async.commit_group;" ::: "memory");
        asm volatile("cp.async.wait_group 0;" ::: "memory");
        __syncthreads();
    }
    uint32_t qhi[4][4], qlo[4][4];
    {
        const uint32_t ar = wid * 16 + (lane & 15);          // 0..63
        const uint32_t ac = (lane >> 4) * 16;
        #pragma unroll
        for (int j = 0; j < 4; j++) {
            ldsm_x4(qhi[j][0], qhi[j][1], qhi[j][2], qhi[j][3],
                    sb + ar * ROWB + j * 32 + ac);
            ldsm_x4(qlo[j][0], qlo[j][1], qlo[j][2], qlo[j][3],
                    sb + 64 * ROWB + ar * ROWB + j * 32 + ac);
        }
    }
    __syncthreads();

    auto issue_tile = [&](int kt, int st) {
        const size_t goff = (size_t)kt * 64 * 64;
        const uint32_t s0 = sb + st * ATT_STAGE;
        #pragma unroll
        for (int i = 0; i < 4; i++) {
            int idx = i * 128 + tid;           // 0..511
            int row = idx >> 3, ch = idx & 7;
            cp_async16(s0 + row * ROWB + ch * 16, Kg + goff + row * 64 + ch * 8);
            cp_async16(s0 + ATT_ARR + row * ROWB + ch * 16,
                       Vg + goff + row * 64 + ch * 8);
        }
        asm volatile("cp.async.commit_group;" ::: "memory");
    };

    float O[8][4];
    #pragma unroll
    for (int f = 0; f < 8; f++)
        #pragma unroll
        for (int j = 0; j < 4; j++)
            O[f][j] = 0.f;
    float Ol[4] = { 0.f, 0.f, 0.f, 0.f };     // row-sum accumulator (l)
    float m0v = -1e30f, m1v = -1e30f;

    issue_tile(0, 0);
    if (ntiles > 1) issue_tile(1, 1);

    const uint32_t b_lrow = (lane & 7) | ((lane >> 1) & 8);
    const uint32_t b_lk   = ((lane >> 3) & 1) * 16;
    const uint32_t v_row  = lane & 15;
    const uint32_t v_cb   = (lane >> 4) * 16;
    const int q0 = qb + wid * 16 + (lane >> 2);
    const int q1 = q0 + 8;

    for (int kt = 0; kt < ntiles; kt++) {
        if (kt + 1 < ntiles)
            asm volatile("cp.async.wait_group 1;" ::: "memory");
        else
            asm volatile("cp.async.wait_group 0;" ::: "memory");
        __syncthreads();
        if (kt + 2 < ntiles) issue_tile(kt + 2, (kt + 2) % 3);

        const uint32_t sK = sb + (kt % 3) * ATT_STAGE;
        const uint32_t sV = sK + ATT_ARR;

        float c[8][4];
        #pragma unroll
        for (int f = 0; f < 8; f++)
            #pragma unroll
            for (int j = 0; j < 4; j++)
                c[f][j] = 0.f;

        // S = Qhi*K + Qlo*K   (log2-domain scores)
        #pragma unroll
        for (int j = 0; j < 4; j++) {
            #pragma unroll
            for (int nb = 0; nb < 4; nb++) {
                uint32_t b0, b1, b2, b3;
                ldsm_x4(b0, b1, b2, b3,
                        sK + (nb * 16 + b_lrow) * ROWB + j * 32 + b_lk);
                mma_f16(c[2 * nb],     qhi[j], b0, b1);
                mma_f16(c[2 * nb + 1], qhi[j], b2, b3);
                mma_f16(c[2 * nb],     qlo[j], b0, b1);
                mma_f16(c[2 * nb + 1], qlo[j], b2, b3);
            }
        }

        // diagonal mask: only the last tile (kt == qt) crosses the diagonal
        if (kt == qt) {
            const int kb = kt * 64;
            #pragma unroll
            for (int f = 0; f < 8; f++) {
                const int kc = kb + f * 8 + (lane & 3) * 2;
                if (kc     > q0) c[f][0] = -1e30f;
                if (kc + 1 > q0) c[f][1] = -1e30f;
                if (kc     > q1) c[f][2] = -1e30f;
                if (kc + 1 > q1) c[f][3] = -1e30f;
            }
        }

        // running max (log2 domain)
        float tm0 = -1e30f, tm1 = -1e30f;
        #pragma unroll
        for (int f = 0; f < 8; f++) {
            tm0 = fmaxf(tm0, fmaxf(c[f][0], c[f][1]));
            tm1 = fmaxf(tm1, fmaxf(c[f][2], c[f][3]));
        }
        tm0 = fmaxf(tm0, __shfl_xor_sync(0xffffffffu, tm0, 1));
        tm0 = fmaxf(tm0, __shfl_xor_sync(0xffffffffu, tm0, 2));
        tm1 = fmaxf(tm1, __shfl_xor_sync(0xffffffffu, tm1, 1));
        tm1 = fmaxf(tm1, __shfl_xor_sync(0xffffffffu, tm1, 2));
        const float mn0 = fmaxf(m0v, tm0), mn1 = fmaxf(m1v, tm1);
        const float cor0 = ex2_f32(m0v - mn0), cor1 = ex2_f32(m1v - mn1);
        m0v = mn0; m1v = mn1;

        #pragma unroll
        for (int f = 0; f < 8; f++) {
            O[f][0] *= cor0; O[f][1] *= cor0;
            O[f][2] *= cor1; O[f][3] *= cor1;
        }
        Ol[0] *= cor0; Ol[1] *= cor0;
        Ol[2] *= cor1; Ol[3] *= cor1;

        // P = exp2(S - m) computed directly as fp16x2 A-frags
        uint32_t ph[4][4];
        #pragma unroll
        for (int j = 0; j < 4; j++) {
            ph[j][0] = ex2_f16x2(c[2 * j][0]     - mn0, c[2 * j][1]     - mn0);
            ph[j][1] = ex2_f16x2(c[2 * j][2]     - mn1, c[2 * j][3]     - mn1);
            ph[j][2] = ex2_f16x2(c[2 * j + 1][0] - mn0, c[2 * j + 1][1] - mn0);
            ph[j][3] = ex2_f16x2(c[2 * j + 1][2] - mn1, c[2 * j + 1][3] - mn1);
        }

        // O += P*V ; l += P*ones (constant B-frag, no shfl reduction)
        #pragma unroll
        for (int j = 0; j < 4; j++) {
            mma_f16(Ol, ph[j], ONES2, ONES2);
            #pragma unroll
            for (int db = 0; db < 4; db++) {
                uint32_t b0, b1, b2, b3;
                ldsm_x4t(b0, b1, b2, b3,
                         sV + (j * 16 + v_row) * ROWB + db * 32 + v_cb);
                mma_f16(O[2 * db],     ph[j], b0, b1);
                mma_f16(O[2 * db + 1], ph[j], b2, b3);
            }
        }
    }

    // epilogue: normalize, split fp16 hi/lo, write [b*T+t][h*64+d]
    const float inv0 = 1.f / Ol[0], inv1 = 1.f / Ol[2];
    const int b = bh >> 4, h = bh & 15;
    const int t0 = qb + wid * 16 + (lane >> 2);
    const size_t r0 = ((size_t)b * T_ + t0) * C_ + h * 64;
    const size_t r1 = r0 + (size_t)8 * C_;
    #pragma unroll
    for (int f = 0; f < 8; f++) {
        const int d = f * 8 + (lane & 3) * 2;
        uint32_t hi, lo;
        split_pack(O[f][0] * inv0, O[f][1] * inv0, hi, lo);
        *(uint32_t*)(g_Ahi + r0 + d) = hi;
        *(uint32_t*)(g_Alo + r0 + d) = lo;
        split_pack(O[f][2] * inv1, O[f][3] * inv1, hi, lo);
        *(uint32_t*)(g_Ahi + r1 + d) = hi;
        *(uint32_t*)(g_Alo + r1 + d) = lo;
    }
}

// ---------------------------------------------------------------------------
extern "C" void kernel_launch(void* const* d_in, const int* in_sizes, int n_in,
                              void* d_out, int out_size)
{
    const float* x      = (const float*)d_in[0];
    const float* W_qkv  = (const float*)d_in[1];
    const float* b_qkv  = (const float*)d_in[2];
    const float* W_proj = (const float*)d_in[3];
    const float* b_proj = (const float*)d_in[4];
    float* out = (float*)d_out;

    static int inited = 0;
    if (!inited) {
        cudaFuncSetAttribute(gemm_f16_kernel,
                             cudaFuncAttributeMaxDynamicSharedMemorySize, GEMM_SMEM);
        cudaFuncSetAttribute(attn_mma_kernel,
                             cudaFuncAttributeMaxDynamicSharedMemorySize, ATT_SMEM);
        inited = 1;
    }

    __half* Wh_d;
    cudaGetSymbolAddress((void**)&Wh_d, g_Wh);

    dim3 tb(32, 8);
    split_w_kernel<<<dim3(N_QKV / 32, C_ / 32), tb>>>(W_qkv, N_QKV, 0);
    split_w_kernel<<<dim3(C_ / 32, C_ / 32), tb>>>(W_proj, C_, N_QKV);
    split_act_kernel<<<(M_ * C_) / (256 * 4), 256>>>(x);

    gemm_f16_kernel<<<dim3(N_QKV / GN, M_ / GM), 128, GEMM_SMEM>>>(
        Wh_d, b_qkv, nullptr, 0, N_QKV);

    attn_mma_kernel<<<dim3(T_ / 64, B_ * H_), 128, ATT_SMEM>>>();

    gemm_f16_kernel<<<dim3((C_ + GN - 1) / GN, M_ / GM), 128, GEMM_SMEM>>>(
        Wh_d + (size_t)N_QKV * C_, b_proj, out, 1, C_);
}